// round 10
// baseline (speedup 1.0000x reference)
#include <cuda_runtime.h>
#include <cuda_bf16.h>
#include <math.h>
#include <stdint.h>

#define B   8
#define D   384
#define FD  256
#define NP  4096
#define NH  8
#define NC  4
#define HD  48
#define GS  1024
#define T   (B*NP)     /* 32768 tokens */
#define D4  1536
#define D2  768
#define QS  1152       /* packed qkv row stride */

typedef __nv_bfloat16 bf16;
typedef __nv_bfloat162 bf162;

// ---------------- scratch (device globals) ----------------------------------
static __device__ float g_gb1[B*D2];
static __device__ float g_gb2[B*D2];
static __device__ float g_gx[B*D];
static __device__ float g_gm[B];
static __device__ float g_A2[B*D];
static __device__ float g_C2[B*D];
static __device__ float g_gx2sq[B*D];
static __device__ int   g_invp[NP];
static __device__ float g_imtok[(size_t)T*D];
static __device__ float g_wi[(size_t)T*D];
static __device__ float g_wif[(size_t)T*D];
static __device__ float g_kv[B*NC*NH*HD*HD];
static __device__ float g_ks[B*NC*NH*HD];
static __device__ float g_bqkv[QS];
// bf16 activations
static __device__ bf16  g_qkv16[(size_t)T*QS];
static __device__ bf16  g_xg16[(size_t)T*D];
static __device__ bf16  g_att16[(size_t)T*D];
static __device__ bf16  g_x216[(size_t)T*D];
static __device__ bf16  g_h116[(size_t)T*D4];
// bf16 weights
static __device__ bf16  g_wqkv16[QS*D];
static __device__ bf16  g_wo16[D*D];
static __device__ bf16  g_c1w16[D4*D];
static __device__ bf16  g_c2w16[D*D4];

// ---------------- helpers ----------------------------------------------------
__device__ __forceinline__ uint32_t sptr(const void* p) {
    return (uint32_t)__cvta_generic_to_shared(p);
}
__device__ __forceinline__ void cp16(uint32_t s, const void* g) {
    asm volatile("cp.async.cg.shared.global [%0], [%1], 16;\n" :: "r"(s), "l"(g));
}
__device__ __forceinline__ void cp_commit() {
    asm volatile("cp.async.commit_group;\n");
}
template<int N>
__device__ __forceinline__ void cp_wait() {
    asm volatile("cp.async.wait_group %0;\n" :: "n"(N));
}
__device__ __forceinline__ void mma16816(float* c, const uint32_t* a, const uint32_t* b) {
    asm volatile(
        "mma.sync.aligned.m16n8k16.row.col.f32.bf16.bf16.f32 "
        "{%0,%1,%2,%3}, {%4,%5,%6,%7}, {%8,%9}, {%0,%1,%2,%3};\n"
        : "+f"(c[0]), "+f"(c[1]), "+f"(c[2]), "+f"(c[3])
        : "r"(a[0]), "r"(a[1]), "r"(a[2]), "r"(a[3]), "r"(b[0]), "r"(b[1]));
}
__device__ __forceinline__ void ldsm4(uint32_t* r, uint32_t a) {
    asm volatile("ldmatrix.sync.aligned.m8n8.x4.shared.b16 {%0,%1,%2,%3}, [%4];"
        : "=r"(r[0]), "=r"(r[1]), "=r"(r[2]), "=r"(r[3]) : "r"(a));
}

__device__ __forceinline__ float blockReduce384(float v, float* sdata) {
    int tid = threadIdx.x;
    sdata[tid] = v;
    if (tid < 128) sdata[384 + tid] = 0.f;
    __syncthreads();
    #pragma unroll
    for (int s = 256; s >= 1; s >>= 1) {
        if (tid < s) sdata[tid] += sdata[tid + s];
        __syncthreads();
    }
    float r = sdata[0];
    __syncthreads();
    return r;
}

// ---------------- launch 0: prep (weights/bias/zero/invperm) + film ----------
#define NWQKV (3*D*D)
#define NWO   (D*D)
#define NC1   (D4*D)
#define NC2   (D*D4)
#define NFILM (2*B*D2)
#define PREP_TOT (NWQKV + NWO + NC1 + NC2 + QS + B*D + B + NP + NFILM)
__global__ void k_prep(const float* __restrict__ Wq, const float* __restrict__ Wk,
                       const float* __restrict__ Wv, const float* __restrict__ Wo,
                       const float* __restrict__ c1, const float* __restrict__ c2,
                       const float* __restrict__ bq, const float* __restrict__ bk,
                       const float* __restrict__ bv,
                       const int* __restrict__ perm,
                       const float* __restrict__ film,
                       const float* __restrict__ W1, const float* __restrict__ b1,
                       const float* __restrict__ W2, const float* __restrict__ b2,
                       bf16* __restrict__ wqkv, bf16* __restrict__ wo,
                       bf16* __restrict__ c1o, bf16* __restrict__ c2o,
                       float* __restrict__ bqkv, float* __restrict__ gx2sq,
                       float* __restrict__ gm, int* __restrict__ invp,
                       float* __restrict__ gb1, float* __restrict__ gb2) {
    int i = blockIdx.x * blockDim.x + threadIdx.x;
    if (i < NWQKV) {
        int seg = i / (D*D), r = i % (D*D);
        const float* W = (seg == 0) ? Wq : (seg == 1) ? Wk : Wv;
        wqkv[i] = __float2bfloat16(W[r]);
        return;
    }
    i -= NWQKV;
    if (i < NWO) { wo[i] = __float2bfloat16(Wo[i]); return; }
    i -= NWO;
    if (i < NC1) { c1o[i] = __float2bfloat16(c1[i]); return; }
    i -= NC1;
    if (i < NC2) { c2o[i] = __float2bfloat16(c2[i]); return; }
    i -= NC2;
    if (i < QS) {
        bqkv[i] = (i < D) ? bq[i] : (i < 2*D) ? bk[i - D] : bv[i - 2*D];
        return;
    }
    i -= QS;
    if (i < B*D) { gx2sq[i] = 0.f; return; }
    i -= B*D;
    if (i < B) { gm[i] = 0.f; return; }
    i -= B;
    if (i < NP) { invp[perm[i]] = i; return; }
    i -= NP;
    if (i < NFILM) {
        int which = i / (B * D2);
        int r = i % (B * D2);
        int b = r / D2, j = r % D2;
        const float* W = which ? W2 : W1;
        const float* bb = which ? b2 : b1;
        const float* f = film + b * FD;
        const float* w = W + (size_t)j * FD;
        float s = 0.f;
        #pragma unroll 8
        for (int q = 0; q < FD; q++) s += f[q] * w[q];
        s += bb[j];
        if (which) gb2[r] = s; else gb1[r] = s;
    }
}

// ---------------- launch 1: per-(b,d) L2 norm + atomic batch-mean ------------
__global__ void k_gx_img(const float* __restrict__ img, float* __restrict__ gx,
                         float* __restrict__ gm) {
    __shared__ float sdata[256];
    int bd = blockIdx.x;
    const float* p = img + (size_t)bd * NP;
    float s = 0.f;
    for (int i = threadIdx.x; i < NP; i += 256) { float v = p[i]; s += v * v; }
    sdata[threadIdx.x] = s; __syncthreads();
    for (int st = 128; st >= 1; st >>= 1) {
        if (threadIdx.x < st) sdata[threadIdx.x] += sdata[threadIdx.x + st];
        __syncthreads();
    }
    if (threadIdx.x == 0) {
        float g = sqrtf(sdata[0]);
        gx[bd] = g;
        atomicAdd(&gm[bd / D], g * (1.f / (float)D));
    }
}

// gmean+coef for GRN2 (input gx2sq needs sqrt)
__global__ void k_gmean_coef(const float* __restrict__ gxsq,
                             const float* __restrict__ gg, const float* __restrict__ gb_,
                             const float* __restrict__ gbmat,
                             float* __restrict__ A, float* __restrict__ C) {
    __shared__ float sdata[512];
    int b = blockIdx.x, d = threadIdx.x;
    float gv = sqrtf(gxsq[b * D + d]);
    float s = blockReduce384(gv, sdata);
    float gm = s / (float)D;
    float nx = gv / (gm + 1e-6f);
    float gamma = gbmat[b * D2 + d];
    float beta  = gbmat[b * D2 + D + d];
    A[b * D + d] = ((1.f + gg[d]) * nx + 1.f) * (1.f + gamma);
    C[b * D + d] = gb_[d] * (1.f + gamma) + beta;
}

// ---------------- launch 2: transpose-gather with inline adaLN1 coef ---------
__global__ void __launch_bounds__(256) k_gather_t(
        const float* __restrict__ img, const int* __restrict__ invp,
        const float* __restrict__ gx, const float* __restrict__ gm,
        const float* __restrict__ gg, const float* __restrict__ gb_,
        const float* __restrict__ gb1,
        float* __restrict__ imtok, bf16* __restrict__ xg) {
    __shared__ float tile[64][65];
    __shared__ float sA[64], sC[64];
    __shared__ int sinv[64];
    int p0 = blockIdx.x * 64, d0 = blockIdx.y * 64, b = blockIdx.z;
    int tid = threadIdx.x;
    if (tid < 64) sinv[tid] = invp[p0 + tid];
    else if (tid >= 64 && tid < 128) {
        int dl = tid - 64, d = d0 + dl;
        float nx = gx[b * D + d] / (gm[b] + 1e-6f);
        float gamma = gb1[b * D2 + d];
        float beta  = gb1[b * D2 + D + d];
        sA[dl] = ((1.f + gg[d]) * nx + 1.f) * (1.f + gamma);
        sC[dl] = gb_[d] * (1.f + gamma) + beta;
    }
    #pragma unroll
    for (int l = 0; l < 4; l++) {
        int j = tid + l * 256;
        int i = j >> 4, q = (j & 15) * 4;
        float4 v = *(const float4*)(img + ((size_t)(b * D + d0 + i)) * NP + p0 + q);
        tile[i][q + 0] = v.x; tile[i][q + 1] = v.y;
        tile[i][q + 2] = v.z; tile[i][q + 3] = v.w;
    }
    __syncthreads();
    #pragma unroll
    for (int l = 0; l < 4; l++) {
        int j = tid + l * 256;
        int jp = j >> 4, i4 = (j & 15) * 4;
        int t = sinv[jp];
        size_t o = ((size_t)(b * NP + t)) * D + d0 + i4;
        float vv[4], xv[4];
        #pragma unroll
        for (int r = 0; r < 4; r++) {
            vv[r] = tile[i4 + r][jp];
            xv[r] = sA[i4 + r] * vv[r] + sC[i4 + r];
        }
        *(float4*)&imtok[o] = make_float4(vv[0], vv[1], vv[2], vv[3]);
        *(bf162*)&xg[o] = __floats2bfloat162_rn(xv[0], xv[1]);
        *(bf162*)&xg[o + 2] = __floats2bfloat162_rn(xv[2], xv[3]);
    }
}

// ---------------- bf16 tensor-core GEMM (ldmatrix, BK=96, 2-stage) -----------
#define LDT 104
#define STG 2
#define STAGE_E (128 * LDT)
#define GEMM_SMEM (STG * 2 * STAGE_E * 2)
template<typename OutT, bool SILU, bool RES, bool GX2>
__global__ void __launch_bounds__(256, 2) gemm_mma(
        const bf16* __restrict__ A, const bf16* __restrict__ W,
        const float* __restrict__ bias, const float* __restrict__ res,
        const float* __restrict__ scale, OutT* __restrict__ C,
        float* __restrict__ gx2sq, int M, int N, int K) {
    extern __shared__ bf16 smem[];
    bf16* sA = smem;
    bf16* sW = smem + STG * STAGE_E;
    uint32_t sbA = sptr(sA), sbW = sptr(sW);
    int tid = threadIdx.x;
    int m0 = blockIdx.y * 128, n0 = blockIdx.x * 128;
    int lane = tid & 31, warp = tid >> 5;
    int g = lane >> 2, tg = lane & 3;
    int wm = warp >> 2, wn = warp & 3;
    int lane8 = lane & 7, laneg = lane >> 3;

    uint32_t aOff[4], bOff[2];
    #pragma unroll
    for (int im = 0; im < 4; im++) {
        int row = wm * 64 + im * 16 + lane8 + (laneg & 1) * 8;
        int col = (laneg >> 1) * 8;
        aOff[im] = (uint32_t)(row * LDT + col) * 2;
    }
    #pragma unroll
    for (int p = 0; p < 2; p++) {
        int row = wn * 32 + p * 16 + lane8 + (laneg >> 1) * 8;
        int col = (laneg & 1) * 8;
        bOff[p] = (uint32_t)(row * LDT + col) * 2;
    }

    float acc[4][4][4];
    #pragma unroll
    for (int i = 0; i < 4; i++)
        #pragma unroll
        for (int j = 0; j < 4; j++)
            #pragma unroll
            for (int p = 0; p < 4; p++) acc[i][j][p] = 0.f;

    int nt = K / 96;
    auto issue = [&](int t) {
        if (t < nt) {
            int s = t & 1;
            int k0 = t * 96;
            #pragma unroll
            for (int l = 0; l < 6; l++) {
                int j = tid + l * 256;                 // 0..1535
                int row = j / 12, q = (j % 12) * 8;    // 128 rows x 12 chunks
                cp16(sbA + (s * STAGE_E + row * LDT + q) * 2, A + (size_t)(m0 + row) * K + k0 + q);
                cp16(sbW + (s * STAGE_E + row * LDT + q) * 2, W + (size_t)(n0 + row) * K + k0 + q);
            }
        }
        cp_commit();
    };

    issue(0);
    for (int t = 0; t < nt; t++) {
        issue(t + 1);
        cp_wait<1>();
        __syncthreads();
        int s = t & 1;
        uint32_t aBase = sbA + s * STAGE_E * 2;
        uint32_t wBase = sbW + s * STAGE_E * 2;
        #pragma unroll
        for (int kk = 0; kk < 96; kk += 16) {
            uint32_t af[4][4], bf[2][4];
            #pragma unroll
            for (int im = 0; im < 4; im++) ldsm4(af[im], aBase + aOff[im] + kk * 2);
            #pragma unroll
            for (int p = 0; p < 2; p++)    ldsm4(bf[p], wBase + bOff[p] + kk * 2);
            #pragma unroll
            for (int im = 0; im < 4; im++)
                #pragma unroll
                for (int in = 0; in < 4; in++)
                    mma16816(acc[im][in], af[im], &bf[in >> 1][(in & 1) * 2]);
        }
        __syncthreads();
    }

    // epilogue
    float sums[4][2];
    if (GX2) {
        #pragma unroll
        for (int in = 0; in < 4; in++) { sums[in][0] = 0.f; sums[in][1] = 0.f; }
    }
    #pragma unroll
    for (int im = 0; im < 4; im++) {
        int r0 = m0 + wm * 64 + im * 16 + g;
        #pragma unroll
        for (int in = 0; in < 4; in++) {
            int c = n0 + wn * 32 + in * 8 + tg * 2;
            float b0 = bias[c], b1 = bias[c + 1];
            float v00 = acc[im][in][0] + b0, v01 = acc[im][in][1] + b1;
            float v10 = acc[im][in][2] + b0, v11 = acc[im][in][3] + b1;
            if (SILU) {
                v00 = v00 / (1.f + expf(-v00)); v01 = v01 / (1.f + expf(-v01));
                v10 = v10 / (1.f + expf(-v10)); v11 = v11 / (1.f + expf(-v11));
            }
            if (RES) {
                float s0 = scale[c], s1 = scale[c + 1];
                float2 ra = *(const float2*)&res[(size_t)r0 * N + c];
                float2 rb = *(const float2*)&res[(size_t)(r0 + 8) * N + c];
                v00 = ra.x + v00 * s0; v01 = ra.y + v01 * s1;
                v10 = rb.x + v10 * s0; v11 = rb.y + v11 * s1;
            }
            if (GX2) {
                sums[in][0] += v00 * v00 + v10 * v10;
                sums[in][1] += v01 * v01 + v11 * v11;
            }
            if (sizeof(OutT) == 4) {
                *(float2*)((float*)C + (size_t)r0 * N + c) = make_float2(v00, v01);
                *(float2*)((float*)C + (size_t)(r0 + 8) * N + c) = make_float2(v10, v11);
            } else {
                *(bf162*)((bf16*)C + (size_t)r0 * N + c) = __floats2bfloat162_rn(v00, v01);
                *(bf162*)((bf16*)C + (size_t)(r0 + 8) * N + c) = __floats2bfloat162_rn(v10, v11);
            }
        }
    }
    if (GX2) {
        #pragma unroll
        for (int off = 4; off <= 16; off <<= 1) {
            #pragma unroll
            for (int in = 0; in < 4; in++) {
                sums[in][0] += __shfl_xor_sync(0xffffffff, sums[in][0], off);
                sums[in][1] += __shfl_xor_sync(0xffffffff, sums[in][1], off);
            }
        }
        if (lane < 4) {
            int b = m0 >> 12;
            #pragma unroll
            for (int in = 0; in < 4; in++) {
                int c = n0 + wn * 32 + in * 8 + tg * 2;
                atomicAdd(&gx2sq[b * D + c], sums[in][0]);
                atomicAdd(&gx2sq[b * D + c + 1], sums[in][1]);
            }
        }
    }
}

// per-token LayerNorm over D then elu+1, bf16 in/out, warp per token; y: 0=q, 1=k
__global__ void __launch_bounds__(256) k_lnelu(bf16* __restrict__ X,
        const float* __restrict__ gq, const float* __restrict__ bq_,
        const float* __restrict__ gk, const float* __restrict__ bk_) {
    int warp = threadIdx.x >> 5, lane = threadIdx.x & 31;
    int t = blockIdx.x * 8 + warp;
    int seg = blockIdx.y;
    const float* gam = seg ? gk : gq;
    const float* bet = seg ? bk_ : bq_;
    size_t base = (size_t)t * QS + seg * D;
    float v[12];
    float s = 0.f, s2 = 0.f;
    #pragma unroll
    for (int j = 0; j < 12; j++) {
        v[j] = __bfloat162float(X[base + j * 32 + lane]);
        s += v[j]; s2 += v[j] * v[j];
    }
    #pragma unroll
    for (int o = 16; o >= 1; o >>= 1) {
        s  += __shfl_xor_sync(0xffffffff, s, o);
        s2 += __shfl_xor_sync(0xffffffff, s2, o);
    }
    float mean = s / (float)D;
    float var = s2 / (float)D - mean * mean;
    float rstd = rsqrtf(var + 1e-5f);
    #pragma unroll
    for (int j = 0; j < 12; j++) {
        int d = j * 32 + lane;
        float y = (v[j] - mean) * rstd * gam[d] + bet[d];
        X[base + d] = __float2bfloat16((y > 0.f) ? (y + 1.f) : expf(y));
    }
}

// kv[bh] = sum_i k_i outer v_i ; ksum[bh] = sum_i k_i
__global__ void __launch_bounds__(256) k_attn_kv(const bf16* __restrict__ qkv,
                                                 float* __restrict__ kv,
                                                 float* __restrict__ ksum) {
    int bh = blockIdx.x;
    int h = bh & (NH - 1), bc = bh >> 3;
    __shared__ float sk[16][HD];
    __shared__ float sv[16][HD];
    int tid = threadIdx.x;
    float acc[9];
    #pragma unroll
    for (int p = 0; p < 9; p++) acc[p] = 0.f;
    float ks = 0.f;
    int base = tid * 9;
    int dp[9], ep[9];
    #pragma unroll
    for (int p = 0; p < 9; p++) { dp[p] = (base + p) / HD; ep[p] = (base + p) % HD; }

    for (int c = 0; c < GS / 16; c++) {
        int tt0 = bc * GS + c * 16;
        #pragma unroll
        for (int r = 0; r < 3; r++) {
            int j = r * 256 + tid;
            int ti = j / HD, d = j % HD;
            size_t row = (size_t)(tt0 + ti) * QS + h * HD + d;
            sk[ti][d] = __bfloat162float(qkv[row + D]);
            sv[ti][d] = __bfloat162float(qkv[row + 2 * D]);
        }
        __syncthreads();
        #pragma unroll 4
        for (int ti = 0; ti < 16; ti++) {
            #pragma unroll
            for (int p = 0; p < 9; p++) acc[p] += sk[ti][dp[p]] * sv[ti][ep[p]];
        }
        if (tid < HD) {
            #pragma unroll 4
            for (int ti = 0; ti < 16; ti++) ks += sk[ti][tid];
        }
        __syncthreads();
    }
    #pragma unroll
    for (int p = 0; p < 9; p++) kv[(size_t)bh * HD * HD + base + p] = acc[p];
    if (tid < HD) ksum[bh * HD + tid] = ks;
}

// out[t,h,e] = (q . kv[:,e]) / (q . ksum + 1e-8), bf16 output
__global__ void __launch_bounds__(256) k_attn_apply(const bf16* __restrict__ qkv,
                                                    const float* __restrict__ kv,
                                                    const float* __restrict__ ksum,
                                                    bf16* __restrict__ out) {
    int bh = blockIdx.x;
    int tile = blockIdx.y;
    int h = bh & (NH - 1), bc = bh >> 3;
    __shared__ float skv[HD * HD];
    __shared__ float sks[HD];
    __shared__ float sq[16][HD];
    int tid = threadIdx.x;
    for (int i = tid; i < HD * HD; i += 256) skv[i] = kv[(size_t)bh * HD * HD + i];
    if (tid < HD) sks[tid] = ksum[bh * HD + tid];
    __syncthreads();
    int t0 = bc * GS + tile * 64;
    for (int sub = 0; sub < 4; sub++) {
        int tt0 = t0 + sub * 16;
        #pragma unroll
        for (int r = 0; r < 3; r++) {
            int j = r * 256 + tid;
            int ti = j / HD, d = j % HD;
            sq[ti][d] = __bfloat162float(qkv[(size_t)(tt0 + ti) * QS + h * HD + d]);
        }
        __syncthreads();
        #pragma unroll
        for (int r = 0; r < 3; r++) {
            int j = r * 256 + tid;
            int ti = j / HD, e = j % HD;
            float num = 0.f, den = 0.f;
            #pragma unroll
            for (int d = 0; d < HD; d++) {
                float qq = sq[ti][d];
                num += qq * skv[d * HD + e];
                den += qq * sks[d];
            }
            out[(size_t)(tt0 + ti) * D + h * HD + e] = __float2bfloat16(num / (den + 1e-8f));
        }
        __syncthreads();
    }
}

// x2 = A2[b,d]*wi + C2[b,d], bf16 output
__global__ void k_x2(const float* __restrict__ wi, const float* __restrict__ A,
                     const float* __restrict__ C, bf16* __restrict__ x2) {
    size_t idx = (size_t)blockIdx.x * 256 + threadIdx.x;
    int t = (int)(idx / D), d = (int)(idx % D);
    int b = t >> 12;
    x2[idx] = __float2bfloat16(A[b * D + d] * wi[idx] + C[b * D + d]);
}

// out[b,d,pix] = image[b,d,pix] + wif[token(pix), d] * final_scalar[d]
__global__ void __launch_bounds__(256) k_final_t(
        const float* __restrict__ img, const float* __restrict__ wif,
        const int* __restrict__ invp, const float* __restrict__ fs,
        float* __restrict__ out) {
    __shared__ float tile[64][65];
    __shared__ int sinv[64];
    int p0 = blockIdx.x * 64, d0 = blockIdx.y * 64, b = blockIdx.z;
    int tid = threadIdx.x;
    if (tid < 64) sinv[tid] = invp[p0 + tid];
    __syncthreads();
    #pragma unroll
    for (int l = 0; l < 4; l++) {
        int j = tid + l * 256;
        int jp = j >> 4, i4 = (j & 15) * 4;
        int t = sinv[jp];
        float4 v = *(const float4*)(wif + ((size_t)(b * NP + t)) * D + d0 + i4);
        tile[i4 + 0][jp] = v.x; tile[i4 + 1][jp] = v.y;
        tile[i4 + 2][jp] = v.z; tile[i4 + 3][jp] = v.w;
    }
    __syncthreads();
    #pragma unroll
    for (int l = 0; l < 4; l++) {
        int j = tid + l * 256;
        int i = j >> 4, q = (j & 15) * 4;
        size_t o = ((size_t)(b * D + d0 + i)) * NP + p0 + q;
        float4 im4 = *(const float4*)(img + o);
        float f = fs[d0 + i];
        float4 r;
        r.x = im4.x + tile[i][q + 0] * f;
        r.y = im4.y + tile[i][q + 1] * f;
        r.z = im4.z + tile[i][q + 2] * f;
        r.w = im4.w + tile[i][q + 3] * f;
        *(float4*)(out + o) = r;
    }
}

// ---------------- driver ----------------------------------------------------
extern "C" void kernel_launch(void* const* d_in, const int* in_sizes, int n_in,
                              void* d_out, int out_size) {
    const float* image  = (const float*)d_in[0];
    const float* film   = (const float*)d_in[1];
    const int*   perm   = (const int*)d_in[2];
    const float* Wq = (const float*)d_in[3];  const float* bq = (const float*)d_in[4];
    const float* Wk = (const float*)d_in[5];  const float* bk = (const float*)d_in[6];
    const float* Wv = (const float*)d_in[7];  const float* bv = (const float*)d_in[8];
    const float* Wo = (const float*)d_in[9];  const float* bo = (const float*)d_in[10];
    const float* lnq_g = (const float*)d_in[11]; const float* lnq_b = (const float*)d_in[12];
    const float* lnk_g = (const float*)d_in[13]; const float* lnk_b = (const float*)d_in[14];
    const float* ada1_W = (const float*)d_in[15]; const float* ada1_b = (const float*)d_in[16];
    const float* grn1_g = (const float*)d_in[17]; const float* grn1_b = (const float*)d_in[18];
    const float* ada2_W = (const float*)d_in[19]; const float* ada2_b = (const float*)d_in[20];
    const float* grn2_g = (const float*)d_in[21]; const float* grn2_b = (const float*)d_in[22];
    const float* conv1_W = (const float*)d_in[23]; const float* conv1_b = (const float*)d_in[24];
    const float* conv2_W = (const float*)d_in[25]; const float* conv2_b = (const float*)d_in[26];
    const float* cs  = (const float*)d_in[27];
    const float* ffs = (const float*)d_in[28];
    const float* fs  = (const float*)d_in[29];
    float* out = (float*)d_out;

    float *p_gb1, *p_gb2, *p_gx, *p_gm, *p_A2, *p_C2, *p_gx2sq;
    int* p_invp;
    float *p_imtok, *p_wi, *p_wif, *p_kv, *p_ks, *p_bqkv;
    bf16 *p_qkv16, *p_xg16, *p_att16, *p_x216, *p_h116;
    bf16 *p_wqkv16, *p_wo16, *p_c1w16, *p_c2w16;
    cudaGetSymbolAddress((void**)&p_gb1, g_gb1);
    cudaGetSymbolAddress((void**)&p_gb2, g_gb2);
    cudaGetSymbolAddress((void**)&p_gx, g_gx);
    cudaGetSymbolAddress((void**)&p_gm, g_gm);
    cudaGetSymbolAddress((void**)&p_A2, g_A2);
    cudaGetSymbolAddress((void**)&p_C2, g_C2);
    cudaGetSymbolAddress((void**)&p_gx2sq, g_gx2sq);
    cudaGetSymbolAddress((void**)&p_invp, g_invp);
    cudaGetSymbolAddress((void**)&p_imtok, g_imtok);
    cudaGetSymbolAddress((void**)&p_wi, g_wi);
    cudaGetSymbolAddress((void**)&p_wif, g_wif);
    cudaGetSymbolAddress((void**)&p_kv, g_kv);
    cudaGetSymbolAddress((void**)&p_ks, g_ks);
    cudaGetSymbolAddress((void**)&p_bqkv, g_bqkv);
    cudaGetSymbolAddress((void**)&p_qkv16, g_qkv16);
    cudaGetSymbolAddress((void**)&p_xg16, g_xg16);
    cudaGetSymbolAddress((void**)&p_att16, g_att16);
    cudaGetSymbolAddress((void**)&p_x216, g_x216);
    cudaGetSymbolAddress((void**)&p_h116, g_h116);
    cudaGetSymbolAddress((void**)&p_wqkv16, g_wqkv16);
    cudaGetSymbolAddress((void**)&p_wo16, g_wo16);
    cudaGetSymbolAddress((void**)&p_c1w16, g_c1w16);
    cudaGetSymbolAddress((void**)&p_c2w16, g_c2w16);

    cudaFuncSetAttribute((const void*)gemm_mma<bf16,false,false,false>,
                         cudaFuncAttributeMaxDynamicSharedMemorySize, GEMM_SMEM);
    cudaFuncSetAttribute((const void*)gemm_mma<float,false,true,true>,
                         cudaFuncAttributeMaxDynamicSharedMemorySize, GEMM_SMEM);
    cudaFuncSetAttribute((const void*)gemm_mma<bf16,true,false,false>,
                         cudaFuncAttributeMaxDynamicSharedMemorySize, GEMM_SMEM);
    cudaFuncSetAttribute((const void*)gemm_mma<float,false,true,false>,
                         cudaFuncAttributeMaxDynamicSharedMemorySize, GEMM_SMEM);

    // launch 0: all prep + film
    k_prep<<<(PREP_TOT + 255) / 256, 256>>>(Wq, Wk, Wv, Wo, conv1_W, conv2_W,
        bq, bk, bv, perm, film, ada1_W, ada1_b, ada2_W, ada2_b,
        p_wqkv16, p_wo16, p_c1w16, p_c2w16,
        p_bqkv, p_gx2sq, p_gm, p_invp, p_gb1, p_gb2);
    // launch 1: gx + batch mean
    k_gx_img<<<B * D, 256>>>(image, p_gx, p_gm);
    // launch 2: gather with inline adaLN1 coefficients
    k_gather_t<<<dim3(NP/64, D/64, B), 256>>>(image, p_invp, p_gx, p_gm,
        grn1_g, grn1_b, p_gb1, p_imtok, p_xg16);
    // launch 3: packed QKV GEMM  <-- profiled launch
    gemm_mma<bf16,false,false,false><<<dim3(QS/128, T/128), 256, GEMM_SMEM>>>(
        p_xg16, p_wqkv16, p_bqkv, nullptr, nullptr, p_qkv16, nullptr, T, QS, D);

    k_lnelu<<<dim3(T/8, 2), 256>>>(p_qkv16, lnq_g, lnq_b, lnk_g, lnk_b);

    k_attn_kv<<<B * NC * NH, 256>>>(p_qkv16, p_kv, p_ks);
    k_attn_apply<<<dim3(B * NC * NH, 16), 256>>>(p_qkv16, p_kv, p_ks, p_att16);

    // wi = imtok + (attn@Wo^T + bo) * cs ; also gx2sq += wi^2
    gemm_mma<float,false,true,true><<<dim3(3, T/128), 256, GEMM_SMEM>>>(
        p_att16, p_wo16, bo, p_imtok, cs, p_wi, p_gx2sq, T, D, D);

    k_gmean_coef<<<B, 384>>>(p_gx2sq, grn2_g, grn2_b, p_gb2, p_A2, p_C2);
    k_x2<<<(int)(((size_t)T*D) / 256), 256>>>(p_wi, p_A2, p_C2, p_x216);

    // h1 = silu(x2 @ conv1^T + b1)
    gemm_mma<bf16,true,false,false><<<dim3(12, T/128), 256, GEMM_SMEM>>>(
        p_x216, p_c1w16, conv1_b, nullptr, nullptr, p_h116, nullptr, T, D4, D);
    // wif = wi + (h1 @ conv2^T + b2) * ffs
    gemm_mma<float,false,true,false><<<dim3(3, T/128), 256, GEMM_SMEM>>>(
        p_h116, p_c2w16, conv2_b, p_wi, ffs, p_wif, nullptr, T, D, D4);

    k_final_t<<<dim3(NP/64, D/64, B), 256>>>(image, p_wif, p_invp, fs, out);
}

// round 11
// speedup vs baseline: 1.0436x; 1.0436x over previous
#include <cuda_runtime.h>
#include <cuda_bf16.h>
#include <math.h>
#include <stdint.h>

#define B   8
#define D   384
#define FD  256
#define NP  4096
#define NH  8
#define NC  4
#define HD  48
#define GS  1024
#define T   (B*NP)     /* 32768 tokens */
#define D4  1536
#define D2  768
#define QS  1152       /* packed qkv row stride */

typedef __nv_bfloat16 bf16;
typedef __nv_bfloat162 bf162;

// ---------------- scratch (device globals) ----------------------------------
static __device__ float g_gb1[B*D2];
static __device__ float g_gb2[B*D2];
static __device__ float g_gx[B*D];
static __device__ float g_gm[B];
static __device__ float g_A2[B*D];
static __device__ float g_C2[B*D];
static __device__ float g_gx2sq[B*D];
static __device__ int   g_invp[NP];
static __device__ float g_kv[B*NC*NH*HD*HD];
static __device__ float g_ks[B*NC*NH*HD];
static __device__ float g_bqkv[QS];
// bf16 activations
static __device__ bf16  g_imtok16[(size_t)T*D];
static __device__ bf16  g_wi16[(size_t)T*D];
static __device__ bf16  g_wif16[(size_t)T*D];
static __device__ bf16  g_qkv16[(size_t)T*QS];
static __device__ bf16  g_xg16[(size_t)T*D];
static __device__ bf16  g_att16[(size_t)T*D];
static __device__ bf16  g_x216[(size_t)T*D];
static __device__ bf16  g_h116[(size_t)T*D4];
// bf16 weights
static __device__ bf16  g_wqkv16[QS*D];
static __device__ bf16  g_wo16[D*D];
static __device__ bf16  g_c1w16[D4*D];
static __device__ bf16  g_c2w16[D*D4];

// ---------------- helpers ----------------------------------------------------
__device__ __forceinline__ uint32_t sptr(const void* p) {
    return (uint32_t)__cvta_generic_to_shared(p);
}
__device__ __forceinline__ void cp16(uint32_t s, const void* g) {
    asm volatile("cp.async.cg.shared.global [%0], [%1], 16;\n" :: "r"(s), "l"(g));
}
__device__ __forceinline__ void cp_commit() {
    asm volatile("cp.async.commit_group;\n");
}
template<int N>
__device__ __forceinline__ void cp_wait() {
    asm volatile("cp.async.wait_group %0;\n" :: "n"(N));
}
__device__ __forceinline__ void mma16816(float* c, const uint32_t* a, const uint32_t* b) {
    asm volatile(
        "mma.sync.aligned.m16n8k16.row.col.f32.bf16.bf16.f32 "
        "{%0,%1,%2,%3}, {%4,%5,%6,%7}, {%8,%9}, {%0,%1,%2,%3};\n"
        : "+f"(c[0]), "+f"(c[1]), "+f"(c[2]), "+f"(c[3])
        : "r"(a[0]), "r"(a[1]), "r"(a[2]), "r"(a[3]), "r"(b[0]), "r"(b[1]));
}
__device__ __forceinline__ void ldsm4(uint32_t* r, uint32_t a) {
    asm volatile("ldmatrix.sync.aligned.m8n8.x4.shared.b16 {%0,%1,%2,%3}, [%4];"
        : "=r"(r[0]), "=r"(r[1]), "=r"(r[2]), "=r"(r[3]) : "r"(a));
}

__device__ __forceinline__ float blockReduce384(float v, float* sdata) {
    int tid = threadIdx.x;
    sdata[tid] = v;
    if (tid < 128) sdata[384 + tid] = 0.f;
    __syncthreads();
    #pragma unroll
    for (int s = 256; s >= 1; s >>= 1) {
        if (tid < s) sdata[tid] += sdata[tid + s];
        __syncthreads();
    }
    float r = sdata[0];
    __syncthreads();
    return r;
}

// ---------------- launch 0: prep (weights/bias/zero/invperm) + film ----------
#define NWQKV (3*D*D)
#define NWO   (D*D)
#define NC1   (D4*D)
#define NC2   (D*D4)
#define NFILM (2*B*D2)
#define PREP_TOT (NWQKV + NWO + NC1 + NC2 + QS + B*D + B + NP + NFILM)
__global__ void k_prep(const float* __restrict__ Wq, const float* __restrict__ Wk,
                       const float* __restrict__ Wv, const float* __restrict__ Wo,
                       const float* __restrict__ c1, const float* __restrict__ c2,
                       const float* __restrict__ bq, const float* __restrict__ bk,
                       const float* __restrict__ bv,
                       const int* __restrict__ perm,
                       const float* __restrict__ film,
                       const float* __restrict__ W1, const float* __restrict__ b1,
                       const float* __restrict__ W2, const float* __restrict__ b2,
                       bf16* __restrict__ wqkv, bf16* __restrict__ wo,
                       bf16* __restrict__ c1o, bf16* __restrict__ c2o,
                       float* __restrict__ bqkv, float* __restrict__ gx2sq,
                       float* __restrict__ gm, int* __restrict__ invp,
                       float* __restrict__ gb1, float* __restrict__ gb2) {
    int i = blockIdx.x * blockDim.x + threadIdx.x;
    if (i < NWQKV) {
        int seg = i / (D*D), r = i % (D*D);
        const float* W = (seg == 0) ? Wq : (seg == 1) ? Wk : Wv;
        wqkv[i] = __float2bfloat16(W[r]);
        return;
    }
    i -= NWQKV;
    if (i < NWO) { wo[i] = __float2bfloat16(Wo[i]); return; }
    i -= NWO;
    if (i < NC1) { c1o[i] = __float2bfloat16(c1[i]); return; }
    i -= NC1;
    if (i < NC2) { c2o[i] = __float2bfloat16(c2[i]); return; }
    i -= NC2;
    if (i < QS) {
        bqkv[i] = (i < D) ? bq[i] : (i < 2*D) ? bk[i - D] : bv[i - 2*D];
        return;
    }
    i -= QS;
    if (i < B*D) { gx2sq[i] = 0.f; return; }
    i -= B*D;
    if (i < B) { gm[i] = 0.f; return; }
    i -= B;
    if (i < NP) { invp[perm[i]] = i; return; }
    i -= NP;
    if (i < NFILM) {
        int which = i / (B * D2);
        int r = i % (B * D2);
        int b = r / D2, j = r % D2;
        const float* W = which ? W2 : W1;
        const float* bb = which ? b2 : b1;
        const float* f = film + b * FD;
        const float* w = W + (size_t)j * FD;
        float s = 0.f;
        #pragma unroll 8
        for (int q = 0; q < FD; q++) s += f[q] * w[q];
        s += bb[j];
        if (which) gb2[r] = s; else gb1[r] = s;
    }
}

// ---------------- launch 1: per-(b,d) L2 norm + atomic batch-mean ------------
__global__ void k_gx_img(const float* __restrict__ img, float* __restrict__ gx,
                         float* __restrict__ gm) {
    __shared__ float sdata[256];
    int bd = blockIdx.x;
    const float* p = img + (size_t)bd * NP;
    float s = 0.f;
    for (int i = threadIdx.x; i < NP; i += 256) { float v = p[i]; s += v * v; }
    sdata[threadIdx.x] = s; __syncthreads();
    for (int st = 128; st >= 1; st >>= 1) {
        if (threadIdx.x < st) sdata[threadIdx.x] += sdata[threadIdx.x + st];
        __syncthreads();
    }
    if (threadIdx.x == 0) {
        float g = sqrtf(sdata[0]);
        gx[bd] = g;
        atomicAdd(&gm[bd / D], g * (1.f / (float)D));
    }
}

// gmean+coef for GRN2 (input gx2sq needs sqrt)
__global__ void k_gmean_coef(const float* __restrict__ gxsq,
                             const float* __restrict__ gg, const float* __restrict__ gb_,
                             const float* __restrict__ gbmat,
                             float* __restrict__ A, float* __restrict__ C) {
    __shared__ float sdata[512];
    int b = blockIdx.x, d = threadIdx.x;
    float gv = sqrtf(gxsq[b * D + d]);
    float s = blockReduce384(gv, sdata);
    float gm = s / (float)D;
    float nx = gv / (gm + 1e-6f);
    float gamma = gbmat[b * D2 + d];
    float beta  = gbmat[b * D2 + D + d];
    A[b * D + d] = ((1.f + gg[d]) * nx + 1.f) * (1.f + gamma);
    C[b * D + d] = gb_[d] * (1.f + gamma) + beta;
}

// ---------------- launch 2: transpose-gather with inline adaLN1 coef ---------
__global__ void __launch_bounds__(256) k_gather_t(
        const float* __restrict__ img, const int* __restrict__ invp,
        const float* __restrict__ gx, const float* __restrict__ gm,
        const float* __restrict__ gg, const float* __restrict__ gb_,
        const float* __restrict__ gb1,
        bf16* __restrict__ imtok, bf16* __restrict__ xg) {
    __shared__ float tile[64][65];
    __shared__ float sA[64], sC[64];
    __shared__ int sinv[64];
    int p0 = blockIdx.x * 64, d0 = blockIdx.y * 64, b = blockIdx.z;
    int tid = threadIdx.x;
    if (tid < 64) sinv[tid] = invp[p0 + tid];
    else if (tid >= 64 && tid < 128) {
        int dl = tid - 64, d = d0 + dl;
        float nx = gx[b * D + d] / (gm[b] + 1e-6f);
        float gamma = gb1[b * D2 + d];
        float beta  = gb1[b * D2 + D + d];
        sA[dl] = ((1.f + gg[d]) * nx + 1.f) * (1.f + gamma);
        sC[dl] = gb_[d] * (1.f + gamma) + beta;
    }
    #pragma unroll
    for (int l = 0; l < 4; l++) {
        int j = tid + l * 256;
        int i = j >> 4, q = (j & 15) * 4;
        float4 v = *(const float4*)(img + ((size_t)(b * D + d0 + i)) * NP + p0 + q);
        tile[i][q + 0] = v.x; tile[i][q + 1] = v.y;
        tile[i][q + 2] = v.z; tile[i][q + 3] = v.w;
    }
    __syncthreads();
    #pragma unroll
    for (int l = 0; l < 4; l++) {
        int j = tid + l * 256;
        int jp = j >> 4, i4 = (j & 15) * 4;
        int t = sinv[jp];
        size_t o = ((size_t)(b * NP + t)) * D + d0 + i4;
        float vv[4], xv[4];
        #pragma unroll
        for (int r = 0; r < 4; r++) {
            vv[r] = tile[i4 + r][jp];
            xv[r] = sA[i4 + r] * vv[r] + sC[i4 + r];
        }
        *(bf162*)&imtok[o] = __floats2bfloat162_rn(vv[0], vv[1]);
        *(bf162*)&imtok[o + 2] = __floats2bfloat162_rn(vv[2], vv[3]);
        *(bf162*)&xg[o] = __floats2bfloat162_rn(xv[0], xv[1]);
        *(bf162*)&xg[o + 2] = __floats2bfloat162_rn(xv[2], xv[3]);
    }
}

// ---------------- bf16 tensor-core GEMM (ldmatrix, BK=64, 2-stage) -----------
// C = act(A @ W^T + bias)[*scale + res]; res/out are bf16.
#define LDT 72
#define STG 2
#define STAGE_E (128 * LDT)
#define GEMM_SMEM (STG * 2 * STAGE_E * 2)
template<bool SILU, bool RES, bool GX2>
__global__ void __launch_bounds__(256, 2) gemm_mma(
        const bf16* __restrict__ A, const bf16* __restrict__ W,
        const float* __restrict__ bias, const bf16* __restrict__ res,
        const float* __restrict__ scale, bf16* __restrict__ C,
        float* __restrict__ gx2sq, int M, int N, int K) {
    extern __shared__ bf16 smem[];
    bf16* sA = smem;
    bf16* sW = smem + STG * STAGE_E;
    uint32_t sbA = sptr(sA), sbW = sptr(sW);
    int tid = threadIdx.x;
    int m0 = blockIdx.y * 128, n0 = blockIdx.x * 128;
    int lane = tid & 31, warp = tid >> 5;
    int g = lane >> 2, tg = lane & 3;
    int wm = warp >> 2, wn = warp & 3;
    int lane8 = lane & 7, laneg = lane >> 3;

    uint32_t aOff[4], bOff[2];
    #pragma unroll
    for (int im = 0; im < 4; im++) {
        int row = wm * 64 + im * 16 + lane8 + (laneg & 1) * 8;
        int col = (laneg >> 1) * 8;
        aOff[im] = (uint32_t)(row * LDT + col) * 2;
    }
    #pragma unroll
    for (int p = 0; p < 2; p++) {
        int row = wn * 32 + p * 16 + lane8 + (laneg >> 1) * 8;
        int col = (laneg & 1) * 8;
        bOff[p] = (uint32_t)(row * LDT + col) * 2;
    }

    float acc[4][4][4];
    #pragma unroll
    for (int i = 0; i < 4; i++)
        #pragma unroll
        for (int j = 0; j < 4; j++)
            #pragma unroll
            for (int p = 0; p < 4; p++) acc[i][j][p] = 0.f;

    int nt = K / 64;
    auto issue = [&](int t) {
        if (t < nt) {
            int s = t & 1;
            int k0 = t * 64;
            #pragma unroll
            for (int l = 0; l < 4; l++) {
                int j = tid + l * 256;                 // 0..1023
                int row = j >> 3, q = (j & 7) * 8;     // 128 rows x 8 chunks
                cp16(sbA + (s * STAGE_E + row * LDT + q) * 2, A + (size_t)(m0 + row) * K + k0 + q);
                cp16(sbW + (s * STAGE_E + row * LDT + q) * 2, W + (size_t)(n0 + row) * K + k0 + q);
            }
        }
        cp_commit();
    };

    issue(0);
    for (int t = 0; t < nt; t++) {
        issue(t + 1);
        cp_wait<1>();
        __syncthreads();
        int s = t & 1;
        uint32_t aBase = sbA + s * STAGE_E * 2;
        uint32_t wBase = sbW + s * STAGE_E * 2;
        #pragma unroll
        for (int kk = 0; kk < 64; kk += 16) {
            uint32_t af[4][4], bf[2][4];
            #pragma unroll
            for (int im = 0; im < 4; im++) ldsm4(af[im], aBase + aOff[im] + kk * 2);
            #pragma unroll
            for (int p = 0; p < 2; p++)    ldsm4(bf[p], wBase + bOff[p] + kk * 2);
            #pragma unroll
            for (int im = 0; im < 4; im++)
                #pragma unroll
                for (int in = 0; in < 4; in++)
                    mma16816(acc[im][in], af[im], &bf[in >> 1][(in & 1) * 2]);
        }
        __syncthreads();
    }

    // epilogue
    float sums[4][2];
    if (GX2) {
        #pragma unroll
        for (int in = 0; in < 4; in++) { sums[in][0] = 0.f; sums[in][1] = 0.f; }
    }
    #pragma unroll
    for (int im = 0; im < 4; im++) {
        int r0 = m0 + wm * 64 + im * 16 + g;
        #pragma unroll
        for (int in = 0; in < 4; in++) {
            int c = n0 + wn * 32 + in * 8 + tg * 2;
            float b0 = bias[c], b1 = bias[c + 1];
            float v00 = acc[im][in][0] + b0, v01 = acc[im][in][1] + b1;
            float v10 = acc[im][in][2] + b0, v11 = acc[im][in][3] + b1;
            if (SILU) {
                v00 = v00 / (1.f + expf(-v00)); v01 = v01 / (1.f + expf(-v01));
                v10 = v10 / (1.f + expf(-v10)); v11 = v11 / (1.f + expf(-v11));
            }
            if (RES) {
                float s0 = scale[c], s1 = scale[c + 1];
                bf162 ra = *(const bf162*)&res[(size_t)r0 * N + c];
                bf162 rb = *(const bf162*)&res[(size_t)(r0 + 8) * N + c];
                v00 = __bfloat162float(ra.x) + v00 * s0;
                v01 = __bfloat162float(ra.y) + v01 * s1;
                v10 = __bfloat162float(rb.x) + v10 * s0;
                v11 = __bfloat162float(rb.y) + v11 * s1;
            }
            if (GX2) {
                sums[in][0] += v00 * v00 + v10 * v10;
                sums[in][1] += v01 * v01 + v11 * v11;
            }
            *(bf162*)&C[(size_t)r0 * N + c] = __floats2bfloat162_rn(v00, v01);
            *(bf162*)&C[(size_t)(r0 + 8) * N + c] = __floats2bfloat162_rn(v10, v11);
        }
    }
    if (GX2) {
        #pragma unroll
        for (int off = 4; off <= 16; off <<= 1) {
            #pragma unroll
            for (int in = 0; in < 4; in++) {
                sums[in][0] += __shfl_xor_sync(0xffffffff, sums[in][0], off);
                sums[in][1] += __shfl_xor_sync(0xffffffff, sums[in][1], off);
            }
        }
        if (lane < 4) {
            int b = m0 >> 12;
            #pragma unroll
            for (int in = 0; in < 4; in++) {
                int c = n0 + wn * 32 + in * 8 + tg * 2;
                atomicAdd(&gx2sq[b * D + c], sums[in][0]);
                atomicAdd(&gx2sq[b * D + c + 1], sums[in][1]);
            }
        }
    }
}

// per-token LayerNorm over D then elu+1, bf16 in/out, warp per token; y: 0=q, 1=k
__global__ void __launch_bounds__(256) k_lnelu(bf16* __restrict__ X,
        const float* __restrict__ gq, const float* __restrict__ bq_,
        const float* __restrict__ gk, const float* __restrict__ bk_) {
    int warp = threadIdx.x >> 5, lane = threadIdx.x & 31;
    int t = blockIdx.x * 8 + warp;
    int seg = blockIdx.y;
    const float* gam = seg ? gk : gq;
    const float* bet = seg ? bk_ : bq_;
    size_t base = (size_t)t * QS + seg * D;
    float v[12];
    float s = 0.f, s2 = 0.f;
    #pragma unroll
    for (int j = 0; j < 12; j++) {
        v[j] = __bfloat162float(X[base + j * 32 + lane]);
        s += v[j]; s2 += v[j] * v[j];
    }
    #pragma unroll
    for (int o = 16; o >= 1; o >>= 1) {
        s  += __shfl_xor_sync(0xffffffff, s, o);
        s2 += __shfl_xor_sync(0xffffffff, s2, o);
    }
    float mean = s / (float)D;
    float var = s2 / (float)D - mean * mean;
    float rstd = rsqrtf(var + 1e-5f);
    #pragma unroll
    for (int j = 0; j < 12; j++) {
        int d = j * 32 + lane;
        float y = (v[j] - mean) * rstd * gam[d] + bet[d];
        X[base + d] = __float2bfloat16((y > 0.f) ? (y + 1.f) : expf(y));
    }
}

// kv[bh] = sum_i k_i outer v_i ; ksum[bh] = sum_i k_i
__global__ void __launch_bounds__(256) k_attn_kv(const bf16* __restrict__ qkv,
                                                 float* __restrict__ kv,
                                                 float* __restrict__ ksum) {
    int bh = blockIdx.x;
    int h = bh & (NH - 1), bc = bh >> 3;
    __shared__ float sk[16][HD];
    __shared__ float sv[16][HD];
    int tid = threadIdx.x;
    float acc[9];
    #pragma unroll
    for (int p = 0; p < 9; p++) acc[p] = 0.f;
    float ks = 0.f;
    int base = tid * 9;
    int dp[9], ep[9];
    #pragma unroll
    for (int p = 0; p < 9; p++) { dp[p] = (base + p) / HD; ep[p] = (base + p) % HD; }

    for (int c = 0; c < GS / 16; c++) {
        int tt0 = bc * GS + c * 16;
        #pragma unroll
        for (int r = 0; r < 3; r++) {
            int j = r * 256 + tid;
            int ti = j / HD, d = j % HD;
            size_t row = (size_t)(tt0 + ti) * QS + h * HD + d;
            sk[ti][d] = __bfloat162float(qkv[row + D]);
            sv[ti][d] = __bfloat162float(qkv[row + 2 * D]);
        }
        __syncthreads();
        #pragma unroll 4
        for (int ti = 0; ti < 16; ti++) {
            #pragma unroll
            for (int p = 0; p < 9; p++) acc[p] += sk[ti][dp[p]] * sv[ti][ep[p]];
        }
        if (tid < HD) {
            #pragma unroll 4
            for (int ti = 0; ti < 16; ti++) ks += sk[ti][tid];
        }
        __syncthreads();
    }
    #pragma unroll
    for (int p = 0; p < 9; p++) kv[(size_t)bh * HD * HD + base + p] = acc[p];
    if (tid < HD) ksum[bh * HD + tid] = ks;
}

// out[t,h,e] = (q . kv[:,e]) / (q . ksum + 1e-8), bf16 output
__global__ void __launch_bounds__(256) k_attn_apply(const bf16* __restrict__ qkv,
                                                    const float* __restrict__ kv,
                                                    const float* __restrict__ ksum,
                                                    bf16* __restrict__ out) {
    int bh = blockIdx.x;
    int tile = blockIdx.y;
    int h = bh & (NH - 1), bc = bh >> 3;
    __shared__ float skv[HD * HD];
    __shared__ float sks[HD];
    __shared__ float sq[16][HD];
    int tid = threadIdx.x;
    for (int i = tid; i < HD * HD; i += 256) skv[i] = kv[(size_t)bh * HD * HD + i];
    if (tid < HD) sks[tid] = ksum[bh * HD + tid];
    __syncthreads();
    int t0 = bc * GS + tile * 64;
    for (int sub = 0; sub < 4; sub++) {
        int tt0 = t0 + sub * 16;
        #pragma unroll
        for (int r = 0; r < 3; r++) {
            int j = r * 256 + tid;
            int ti = j / HD, d = j % HD;
            sq[ti][d] = __bfloat162float(qkv[(size_t)(tt0 + ti) * QS + h * HD + d]);
        }
        __syncthreads();
        #pragma unroll
        for (int r = 0; r < 3; r++) {
            int j = r * 256 + tid;
            int ti = j / HD, e = j % HD;
            float num = 0.f, den = 0.f;
            #pragma unroll
            for (int d = 0; d < HD; d++) {
                float qq = sq[ti][d];
                num += qq * skv[d * HD + e];
                den += qq * sks[d];
            }
            out[(size_t)(tt0 + ti) * D + h * HD + e] = __float2bfloat16(num / (den + 1e-8f));
        }
        __syncthreads();
    }
}

// x2 = A2[b,d]*wi + C2[b,d], bf16 in/out
__global__ void k_x2(const bf16* __restrict__ wi, const float* __restrict__ A,
                     const float* __restrict__ C, bf16* __restrict__ x2) {
    size_t idx = (size_t)blockIdx.x * 256 + threadIdx.x;
    int t = (int)(idx / D), d = (int)(idx % D);
    int b = t >> 12;
    x2[idx] = __float2bfloat16(A[b * D + d] * __bfloat162float(wi[idx]) + C[b * D + d]);
}

// out[b,d,pix] = image[b,d,pix] + wif[token(pix), d] * final_scalar[d]
__global__ void __launch_bounds__(256) k_final_t(
        const float* __restrict__ img, const bf16* __restrict__ wif,
        const int* __restrict__ invp, const float* __restrict__ fs,
        float* __restrict__ out) {
    __shared__ float tile[64][65];
    __shared__ int sinv[64];
    int p0 = blockIdx.x * 64, d0 = blockIdx.y * 64, b = blockIdx.z;
    int tid = threadIdx.x;
    if (tid < 64) sinv[tid] = invp[p0 + tid];
    __syncthreads();
    #pragma unroll
    for (int l = 0; l < 4; l++) {
        int j = tid + l * 256;
        int jp = j >> 4, i4 = (j & 15) * 4;
        int t = sinv[jp];
        const bf16* src = wif + ((size_t)(b * NP + t)) * D + d0 + i4;
        bf162 v01 = *(const bf162*)src;
        bf162 v23 = *(const bf162*)(src + 2);
        tile[i4 + 0][jp] = __bfloat162float(v01.x);
        tile[i4 + 1][jp] = __bfloat162float(v01.y);
        tile[i4 + 2][jp] = __bfloat162float(v23.x);
        tile[i4 + 3][jp] = __bfloat162float(v23.y);
    }
    __syncthreads();
    #pragma unroll
    for (int l = 0; l < 4; l++) {
        int j = tid + l * 256;
        int i = j >> 4, q = (j & 15) * 4;
        size_t o = ((size_t)(b * D + d0 + i)) * NP + p0 + q;
        float4 im4 = *(const float4*)(img + o);
        float f = fs[d0 + i];
        float4 r;
        r.x = im4.x + tile[i][q + 0] * f;
        r.y = im4.y + tile[i][q + 1] * f;
        r.z = im4.z + tile[i][q + 2] * f;
        r.w = im4.w + tile[i][q + 3] * f;
        *(float4*)(out + o) = r;
    }
}

// ---------------- driver ----------------------------------------------------
extern "C" void kernel_launch(void* const* d_in, const int* in_sizes, int n_in,
                              void* d_out, int out_size) {
    const float* image  = (const float*)d_in[0];
    const float* film   = (const float*)d_in[1];
    const int*   perm   = (const int*)d_in[2];
    const float* Wq = (const float*)d_in[3];  const float* bq = (const float*)d_in[4];
    const float* Wk = (const float*)d_in[5];  const float* bk = (const float*)d_in[6];
    const float* Wv = (const float*)d_in[7];  const float* bv = (const float*)d_in[8];
    const float* Wo = (const float*)d_in[9];  const float* bo = (const float*)d_in[10];
    const float* lnq_g = (const float*)d_in[11]; const float* lnq_b = (const float*)d_in[12];
    const float* lnk_g = (const float*)d_in[13]; const float* lnk_b = (const float*)d_in[14];
    const float* ada1_W = (const float*)d_in[15]; const float* ada1_b = (const float*)d_in[16];
    const float* grn1_g = (const float*)d_in[17]; const float* grn1_b = (const float*)d_in[18];
    const float* ada2_W = (const float*)d_in[19]; const float* ada2_b = (const float*)d_in[20];
    const float* grn2_g = (const float*)d_in[21]; const float* grn2_b = (const float*)d_in[22];
    const float* conv1_W = (const float*)d_in[23]; const float* conv1_b = (const float*)d_in[24];
    const float* conv2_W = (const float*)d_in[25]; const float* conv2_b = (const float*)d_in[26];
    const float* cs  = (const float*)d_in[27];
    const float* ffs = (const float*)d_in[28];
    const float* fs  = (const float*)d_in[29];
    float* out = (float*)d_out;

    float *p_gb1, *p_gb2, *p_gx, *p_gm, *p_A2, *p_C2, *p_gx2sq;
    int* p_invp;
    float *p_kv, *p_ks, *p_bqkv;
    bf16 *p_imtok16, *p_wi16, *p_wif16;
    bf16 *p_qkv16, *p_xg16, *p_att16, *p_x216, *p_h116;
    bf16 *p_wqkv16, *p_wo16, *p_c1w16, *p_c2w16;
    cudaGetSymbolAddress((void**)&p_gb1, g_gb1);
    cudaGetSymbolAddress((void**)&p_gb2, g_gb2);
    cudaGetSymbolAddress((void**)&p_gx, g_gx);
    cudaGetSymbolAddress((void**)&p_gm, g_gm);
    cudaGetSymbolAddress((void**)&p_A2, g_A2);
    cudaGetSymbolAddress((void**)&p_C2, g_C2);
    cudaGetSymbolAddress((void**)&p_gx2sq, g_gx2sq);
    cudaGetSymbolAddress((void**)&p_invp, g_invp);
    cudaGetSymbolAddress((void**)&p_kv, g_kv);
    cudaGetSymbolAddress((void**)&p_ks, g_ks);
    cudaGetSymbolAddress((void**)&p_bqkv, g_bqkv);
    cudaGetSymbolAddress((void**)&p_imtok16, g_imtok16);
    cudaGetSymbolAddress((void**)&p_wi16, g_wi16);
    cudaGetSymbolAddress((void**)&p_wif16, g_wif16);
    cudaGetSymbolAddress((void**)&p_qkv16, g_qkv16);
    cudaGetSymbolAddress((void**)&p_xg16, g_xg16);
    cudaGetSymbolAddress((void**)&p_att16, g_att16);
    cudaGetSymbolAddress((void**)&p_x216, g_x216);
    cudaGetSymbolAddress((void**)&p_h116, g_h116);
    cudaGetSymbolAddress((void**)&p_wqkv16, g_wqkv16);
    cudaGetSymbolAddress((void**)&p_wo16, g_wo16);
    cudaGetSymbolAddress((void**)&p_c1w16, g_c1w16);
    cudaGetSymbolAddress((void**)&p_c2w16, g_c2w16);

    cudaFuncSetAttribute((const void*)gemm_mma<false,false,false>,
                         cudaFuncAttributeMaxDynamicSharedMemorySize, GEMM_SMEM);
    cudaFuncSetAttribute((const void*)gemm_mma<false,true,true>,
                         cudaFuncAttributeMaxDynamicSharedMemorySize, GEMM_SMEM);
    cudaFuncSetAttribute((const void*)gemm_mma<true,false,false>,
                         cudaFuncAttributeMaxDynamicSharedMemorySize, GEMM_SMEM);
    cudaFuncSetAttribute((const void*)gemm_mma<false,true,false>,
                         cudaFuncAttributeMaxDynamicSharedMemorySize, GEMM_SMEM);

    // launch 0: all prep + film
    k_prep<<<(PREP_TOT + 255) / 256, 256>>>(Wq, Wk, Wv, Wo, conv1_W, conv2_W,
        bq, bk, bv, perm, film, ada1_W, ada1_b, ada2_W, ada2_b,
        p_wqkv16, p_wo16, p_c1w16, p_c2w16,
        p_bqkv, p_gx2sq, p_gm, p_invp, p_gb1, p_gb2);
    // launch 1: gx + batch mean
    k_gx_img<<<B * D, 256>>>(image, p_gx, p_gm);
    // launch 2: gather with inline adaLN1 coefficients
    k_gather_t<<<dim3(NP/64, D/64, B), 256>>>(image, p_invp, p_gx, p_gm,
        grn1_g, grn1_b, p_gb1, p_imtok16, p_xg16);
    // launch 3: packed QKV GEMM  <-- profiled launch
    gemm_mma<false,false,false><<<dim3(QS/128, T/128), 256, GEMM_SMEM>>>(
        p_xg16, p_wqkv16, p_bqkv, nullptr, nullptr, p_qkv16, nullptr, T, QS, D);

    k_lnelu<<<dim3(T/8, 2), 256>>>(p_qkv16, lnq_g, lnq_b, lnk_g, lnk_b);

    k_attn_kv<<<B * NC * NH, 256>>>(p_qkv16, p_kv, p_ks);
    k_attn_apply<<<dim3(B * NC * NH, 16), 256>>>(p_qkv16, p_kv, p_ks, p_att16);

    // wi = imtok + (attn@Wo^T + bo) * cs ; also gx2sq += wi^2
    gemm_mma<false,true,true><<<dim3(3, T/128), 256, GEMM_SMEM>>>(
        p_att16, p_wo16, bo, p_imtok16, cs, p_wi16, p_gx2sq, T, D, D);

    k_gmean_coef<<<B, 384>>>(p_gx2sq, grn2_g, grn2_b, p_gb2, p_A2, p_C2);
    k_x2<<<(int)(((size_t)T*D) / 256), 256>>>(p_wi16, p_A2, p_C2, p_x216);

    // h1 = silu(x2 @ conv1^T + b1)
    gemm_mma<true,false,false><<<dim3(12, T/128), 256, GEMM_SMEM>>>(
        p_x216, p_c1w16, conv1_b, nullptr, nullptr, p_h116, nullptr, T, D4, D);
    // wif = wi + (h1 @ conv2^T + b2) * ffs
    gemm_mma<false,true,false><<<dim3(3, T/128), 256, GEMM_SMEM>>>(
        p_h116, p_c2w16, conv2_b, p_wi16, ffs, p_wif16, nullptr, T, D, D4);

    k_final_t<<<dim3(NP/64, D/64, B), 256>>>(image, p_wif16, p_invp, fs, out);
}

// round 12
// speedup vs baseline: 1.2149x; 1.1641x over previous
#include <cuda_runtime.h>
#include <cuda_bf16.h>
#include <math.h>
#include <stdint.h>

#define B   8
#define D   384
#define FD  256
#define NP  4096
#define NH  8
#define NC  4
#define HD  48
#define GS  1024
#define T   (B*NP)     /* 32768 tokens */
#define D4  1536
#define D2  768
#define QS  1152       /* packed qkv row stride */
#define KVSPLIT 2

typedef __nv_bfloat16 bf16;
typedef __nv_bfloat162 bf162;

// ---------------- scratch (device globals) ----------------------------------
static __device__ float g_gb1[B*D2];
static __device__ float g_gb2[B*D2];
static __device__ float g_gx[B*D];
static __device__ float g_gm[B];
static __device__ float g_A2[B*D];
static __device__ float g_C2[B*D];
static __device__ float g_gx2sq[B*D];
static __device__ int   g_invp[NP];
static __device__ float g_kv[KVSPLIT*B*NC*NH*HD*HD];
static __device__ float g_ks[KVSPLIT*B*NC*NH*HD];
static __device__ float g_bqkv[QS];
// bf16 activations
static __device__ bf16  g_imtok16[(size_t)T*D];
static __device__ bf16  g_wi16[(size_t)T*D];
static __device__ bf16  g_wif16[(size_t)T*D];
static __device__ bf16  g_qkv16[(size_t)T*QS];
static __device__ bf16  g_xg16[(size_t)T*D];
static __device__ bf16  g_att16[(size_t)T*D];
static __device__ bf16  g_x216[(size_t)T*D];
static __device__ bf16  g_h116[(size_t)T*D4];
// bf16 weights
static __device__ bf16  g_wqkv16[QS*D];
static __device__ bf16  g_wo16[D*D];
static __device__ bf16  g_c1w16[D4*D];
static __device__ bf16  g_c2w16[D*D4];

// ---------------- helpers ----------------------------------------------------
__device__ __forceinline__ uint32_t sptr(const void* p) {
    return (uint32_t)__cvta_generic_to_shared(p);
}
__device__ __forceinline__ void cp16(uint32_t s, const void* g) {
    asm volatile("cp.async.cg.shared.global [%0], [%1], 16;\n" :: "r"(s), "l"(g));
}
__device__ __forceinline__ void cp_commit() {
    asm volatile("cp.async.commit_group;\n");
}
template<int N>
__device__ __forceinline__ void cp_wait() {
    asm volatile("cp.async.wait_group %0;\n" :: "n"(N));
}
__device__ __forceinline__ void mma16816(float* c, const uint32_t* a, const uint32_t* b) {
    asm volatile(
        "mma.sync.aligned.m16n8k16.row.col.f32.bf16.bf16.f32 "
        "{%0,%1,%2,%3}, {%4,%5,%6,%7}, {%8,%9}, {%0,%1,%2,%3};\n"
        : "+f"(c[0]), "+f"(c[1]), "+f"(c[2]), "+f"(c[3])
        : "r"(a[0]), "r"(a[1]), "r"(a[2]), "r"(a[3]), "r"(b[0]), "r"(b[1]));
}
__device__ __forceinline__ void ldsm4(uint32_t* r, uint32_t a) {
    asm volatile("ldmatrix.sync.aligned.m8n8.x4.shared.b16 {%0,%1,%2,%3}, [%4];"
        : "=r"(r[0]), "=r"(r[1]), "=r"(r[2]), "=r"(r[3]) : "r"(a));
}

__device__ __forceinline__ float blockReduce384(float v, float* sdata) {
    int tid = threadIdx.x;
    sdata[tid] = v;
    if (tid < 128) sdata[384 + tid] = 0.f;
    __syncthreads();
    #pragma unroll
    for (int s = 256; s >= 1; s >>= 1) {
        if (tid < s) sdata[tid] += sdata[tid + s];
        __syncthreads();
    }
    float r = sdata[0];
    __syncthreads();
    return r;
}

// ---------------- launch 0: prep (weights/bias/zero/invperm) + film ----------
#define NWQKV (3*D*D)
#define NWO   (D*D)
#define NC1   (D4*D)
#define NC2   (D*D4)
#define NFILM (2*B*D2)
#define PREP_TOT (NWQKV + NWO + NC1 + NC2 + QS + B*D + B + NP + NFILM)
__global__ void k_prep(const float* __restrict__ Wq, const float* __restrict__ Wk,
                       const float* __restrict__ Wv, const float* __restrict__ Wo,
                       const float* __restrict__ c1, const float* __restrict__ c2,
                       const float* __restrict__ bq, const float* __restrict__ bk,
                       const float* __restrict__ bv,
                       const int* __restrict__ perm,
                       const float* __restrict__ film,
                       const float* __restrict__ W1, const float* __restrict__ b1,
                       const float* __restrict__ W2, const float* __restrict__ b2,
                       bf16* __restrict__ wqkv, bf16* __restrict__ wo,
                       bf16* __restrict__ c1o, bf16* __restrict__ c2o,
                       float* __restrict__ bqkv, float* __restrict__ gx2sq,
                       float* __restrict__ gm, int* __restrict__ invp,
                       float* __restrict__ gb1, float* __restrict__ gb2) {
    int i = blockIdx.x * blockDim.x + threadIdx.x;
    if (i < NWQKV) {
        int seg = i / (D*D), r = i % (D*D);
        const float* W = (seg == 0) ? Wq : (seg == 1) ? Wk : Wv;
        wqkv[i] = __float2bfloat16(W[r]);
        return;
    }
    i -= NWQKV;
    if (i < NWO) { wo[i] = __float2bfloat16(Wo[i]); return; }
    i -= NWO;
    if (i < NC1) { c1o[i] = __float2bfloat16(c1[i]); return; }
    i -= NC1;
    if (i < NC2) { c2o[i] = __float2bfloat16(c2[i]); return; }
    i -= NC2;
    if (i < QS) {
        bqkv[i] = (i < D) ? bq[i] : (i < 2*D) ? bk[i - D] : bv[i - 2*D];
        return;
    }
    i -= QS;
    if (i < B*D) { gx2sq[i] = 0.f; return; }
    i -= B*D;
    if (i < B) { gm[i] = 0.f; return; }
    i -= B;
    if (i < NP) { invp[perm[i]] = i; return; }
    i -= NP;
    if (i < NFILM) {
        int which = i / (B * D2);
        int r = i % (B * D2);
        int b = r / D2, j = r % D2;
        const float* W = which ? W2 : W1;
        const float* bb = which ? b2 : b1;
        const float* f = film + b * FD;
        const float* w = W + (size_t)j * FD;
        float s = 0.f;
        #pragma unroll 8
        for (int q = 0; q < FD; q++) s += f[q] * w[q];
        s += bb[j];
        if (which) gb2[r] = s; else gb1[r] = s;
    }
}

// ---------------- launch 1: per-(b,d) L2 norm + atomic batch-mean ------------
__global__ void k_gx_img(const float* __restrict__ img, float* __restrict__ gx,
                         float* __restrict__ gm) {
    __shared__ float sdata[256];
    int bd = blockIdx.x;
    const float* p = img + (size_t)bd * NP;
    float s = 0.f;
    for (int i = threadIdx.x; i < NP; i += 256) { float v = p[i]; s += v * v; }
    sdata[threadIdx.x] = s; __syncthreads();
    for (int st = 128; st >= 1; st >>= 1) {
        if (threadIdx.x < st) sdata[threadIdx.x] += sdata[threadIdx.x + st];
        __syncthreads();
    }
    if (threadIdx.x == 0) {
        float g = sqrtf(sdata[0]);
        gx[bd] = g;
        atomicAdd(&gm[bd / D], g * (1.f / (float)D));
    }
}

// gmean+coef for GRN2 (input gx2sq needs sqrt)
__global__ void k_gmean_coef(const float* __restrict__ gxsq,
                             const float* __restrict__ gg, const float* __restrict__ gb_,
                             const float* __restrict__ gbmat,
                             float* __restrict__ A, float* __restrict__ C) {
    __shared__ float sdata[512];
    int b = blockIdx.x, d = threadIdx.x;
    float gv = sqrtf(gxsq[b * D + d]);
    float s = blockReduce384(gv, sdata);
    float gm = s / (float)D;
    float nx = gv / (gm + 1e-6f);
    float gamma = gbmat[b * D2 + d];
    float beta  = gbmat[b * D2 + D + d];
    A[b * D + d] = ((1.f + gg[d]) * nx + 1.f) * (1.f + gamma);
    C[b * D + d] = gb_[d] * (1.f + gamma) + beta;
}

// ---------------- launch 2: transpose-gather with inline adaLN1 coef ---------
__global__ void __launch_bounds__(256) k_gather_t(
        const float* __restrict__ img, const int* __restrict__ invp,
        const float* __restrict__ gx, const float* __restrict__ gm,
        const float* __restrict__ gg, const float* __restrict__ gb_,
        const float* __restrict__ gb1,
        bf16* __restrict__ imtok, bf16* __restrict__ xg) {
    __shared__ float tile[64][65];
    __shared__ float sA[64], sC[64];
    __shared__ int sinv[64];
    int p0 = blockIdx.x * 64, d0 = blockIdx.y * 64, b = blockIdx.z;
    int tid = threadIdx.x;
    if (tid < 64) sinv[tid] = invp[p0 + tid];
    else if (tid >= 64 && tid < 128) {
        int dl = tid - 64, d = d0 + dl;
        float nx = gx[b * D + d] / (gm[b] + 1e-6f);
        float gamma = gb1[b * D2 + d];
        float beta  = gb1[b * D2 + D + d];
        sA[dl] = ((1.f + gg[d]) * nx + 1.f) * (1.f + gamma);
        sC[dl] = gb_[d] * (1.f + gamma) + beta;
    }
    #pragma unroll
    for (int l = 0; l < 4; l++) {
        int j = tid + l * 256;
        int i = j >> 4, q = (j & 15) * 4;
        float4 v = *(const float4*)(img + ((size_t)(b * D + d0 + i)) * NP + p0 + q);
        tile[i][q + 0] = v.x; tile[i][q + 1] = v.y;
        tile[i][q + 2] = v.z; tile[i][q + 3] = v.w;
    }
    __syncthreads();
    #pragma unroll
    for (int l = 0; l < 4; l++) {
        int j = tid + l * 256;
        int jp = j >> 4, i4 = (j & 15) * 4;
        int t = sinv[jp];
        size_t o = ((size_t)(b * NP + t)) * D + d0 + i4;
        float vv[4], xv[4];
        #pragma unroll
        for (int r = 0; r < 4; r++) {
            vv[r] = tile[i4 + r][jp];
            xv[r] = sA[i4 + r] * vv[r] + sC[i4 + r];
        }
        *(bf162*)&imtok[o] = __floats2bfloat162_rn(vv[0], vv[1]);
        *(bf162*)&imtok[o + 2] = __floats2bfloat162_rn(vv[2], vv[3]);
        *(bf162*)&xg[o] = __floats2bfloat162_rn(xv[0], xv[1]);
        *(bf162*)&xg[o + 2] = __floats2bfloat162_rn(xv[2], xv[3]);
    }
}

// ---------------- bf16 tensor-core GEMM (ldmatrix, BK=64, 2-stage) -----------
#define LDT 72
#define STG 2
#define STAGE_E (128 * LDT)
#define GEMM_SMEM (STG * 2 * STAGE_E * 2)
template<bool SILU, bool RES, bool GX2>
__global__ void __launch_bounds__(256, 2) gemm_mma(
        const bf16* __restrict__ A, const bf16* __restrict__ W,
        const float* __restrict__ bias, const bf16* __restrict__ res,
        const float* __restrict__ scale, bf16* __restrict__ C,
        float* __restrict__ gx2sq, int M, int N, int K) {
    extern __shared__ bf16 smem[];
    bf16* sA = smem;
    bf16* sW = smem + STG * STAGE_E;
    uint32_t sbA = sptr(sA), sbW = sptr(sW);
    int tid = threadIdx.x;
    int m0 = blockIdx.y * 128, n0 = blockIdx.x * 128;
    int lane = tid & 31, warp = tid >> 5;
    int g = lane >> 2, tg = lane & 3;
    int wm = warp >> 2, wn = warp & 3;
    int lane8 = lane & 7, laneg = lane >> 3;

    uint32_t aOff[4], bOff[2];
    #pragma unroll
    for (int im = 0; im < 4; im++) {
        int row = wm * 64 + im * 16 + lane8 + (laneg & 1) * 8;
        int col = (laneg >> 1) * 8;
        aOff[im] = (uint32_t)(row * LDT + col) * 2;
    }
    #pragma unroll
    for (int p = 0; p < 2; p++) {
        int row = wn * 32 + p * 16 + lane8 + (laneg >> 1) * 8;
        int col = (laneg & 1) * 8;
        bOff[p] = (uint32_t)(row * LDT + col) * 2;
    }

    float acc[4][4][4];
    #pragma unroll
    for (int i = 0; i < 4; i++)
        #pragma unroll
        for (int j = 0; j < 4; j++)
            #pragma unroll
            for (int p = 0; p < 4; p++) acc[i][j][p] = 0.f;

    int nt = K / 64;
    auto issue = [&](int t) {
        if (t < nt) {
            int s = t & 1;
            int k0 = t * 64;
            #pragma unroll
            for (int l = 0; l < 4; l++) {
                int j = tid + l * 256;
                int row = j >> 3, q = (j & 7) * 8;
                cp16(sbA + (s * STAGE_E + row * LDT + q) * 2, A + (size_t)(m0 + row) * K + k0 + q);
                cp16(sbW + (s * STAGE_E + row * LDT + q) * 2, W + (size_t)(n0 + row) * K + k0 + q);
            }
        }
        cp_commit();
    };

    issue(0);
    for (int t = 0; t < nt; t++) {
        issue(t + 1);
        cp_wait<1>();
        __syncthreads();
        int s = t & 1;
        uint32_t aBase = sbA + s * STAGE_E * 2;
        uint32_t wBase = sbW + s * STAGE_E * 2;
        #pragma unroll
        for (int kk = 0; kk < 64; kk += 16) {
            uint32_t af[4][4], bf[2][4];
            #pragma unroll
            for (int im = 0; im < 4; im++) ldsm4(af[im], aBase + aOff[im] + kk * 2);
            #pragma unroll
            for (int p = 0; p < 2; p++)    ldsm4(bf[p], wBase + bOff[p] + kk * 2);
            #pragma unroll
            for (int im = 0; im < 4; im++)
                #pragma unroll
                for (int in = 0; in < 4; in++)
                    mma16816(acc[im][in], af[im], &bf[in >> 1][(in & 1) * 2]);
        }
        __syncthreads();
    }

    // epilogue
    float sums[4][2];
    if (GX2) {
        #pragma unroll
        for (int in = 0; in < 4; in++) { sums[in][0] = 0.f; sums[in][1] = 0.f; }
    }
    #pragma unroll
    for (int im = 0; im < 4; im++) {
        int r0 = m0 + wm * 64 + im * 16 + g;
        #pragma unroll
        for (int in = 0; in < 4; in++) {
            int c = n0 + wn * 32 + in * 8 + tg * 2;
            float b0 = bias[c], b1 = bias[c + 1];
            float v00 = acc[im][in][0] + b0, v01 = acc[im][in][1] + b1;
            float v10 = acc[im][in][2] + b0, v11 = acc[im][in][3] + b1;
            if (SILU) {
                v00 = v00 / (1.f + expf(-v00)); v01 = v01 / (1.f + expf(-v01));
                v10 = v10 / (1.f + expf(-v10)); v11 = v11 / (1.f + expf(-v11));
            }
            if (RES) {
                float s0 = scale[c], s1 = scale[c + 1];
                bf162 ra = *(const bf162*)&res[(size_t)r0 * N + c];
                bf162 rb = *(const bf162*)&res[(size_t)(r0 + 8) * N + c];
                v00 = __bfloat162float(ra.x) + v00 * s0;
                v01 = __bfloat162float(ra.y) + v01 * s1;
                v10 = __bfloat162float(rb.x) + v10 * s0;
                v11 = __bfloat162float(rb.y) + v11 * s1;
            }
            if (GX2) {
                sums[in][0] += v00 * v00 + v10 * v10;
                sums[in][1] += v01 * v01 + v11 * v11;
            }
            *(bf162*)&C[(size_t)r0 * N + c] = __floats2bfloat162_rn(v00, v01);
            *(bf162*)&C[(size_t)(r0 + 8) * N + c] = __floats2bfloat162_rn(v10, v11);
        }
    }
    if (GX2) {
        #pragma unroll
        for (int off = 4; off <= 16; off <<= 1) {
            #pragma unroll
            for (int in = 0; in < 4; in++) {
                sums[in][0] += __shfl_xor_sync(0xffffffff, sums[in][0], off);
                sums[in][1] += __shfl_xor_sync(0xffffffff, sums[in][1], off);
            }
        }
        if (lane < 4) {
            int b = m0 >> 12;
            #pragma unroll
            for (int in = 0; in < 4; in++) {
                int c = n0 + wn * 32 + in * 8 + tg * 2;
                atomicAdd(&gx2sq[b * D + c], sums[in][0]);
                atomicAdd(&gx2sq[b * D + c + 1], sums[in][1]);
            }
        }
    }
}

// per-token LayerNorm over D then elu+1, bf16 in/out, warp per token; y: 0=q, 1=k
__global__ void __launch_bounds__(256) k_lnelu(bf16* __restrict__ X,
        const float* __restrict__ gq, const float* __restrict__ bq_,
        const float* __restrict__ gk, const float* __restrict__ bk_) {
    int warp = threadIdx.x >> 5, lane = threadIdx.x & 31;
    int t = blockIdx.x * 8 + warp;
    int seg = blockIdx.y;
    const float* gam = seg ? gk : gq;
    const float* bet = seg ? bk_ : bq_;
    size_t base = (size_t)t * QS + seg * D;
    float v[12];
    float s = 0.f, s2 = 0.f;
    #pragma unroll
    for (int j = 0; j < 12; j++) {
        v[j] = __bfloat162float(X[base + j * 32 + lane]);
        s += v[j]; s2 += v[j] * v[j];
    }
    #pragma unroll
    for (int o = 16; o >= 1; o >>= 1) {
        s  += __shfl_xor_sync(0xffffffff, s, o);
        s2 += __shfl_xor_sync(0xffffffff, s2, o);
    }
    float mean = s / (float)D;
    float var = s2 / (float)D - mean * mean;
    float rstd = rsqrtf(var + 1e-5f);
    #pragma unroll
    for (int j = 0; j < 12; j++) {
        int d = j * 32 + lane;
        float y = (v[j] - mean) * rstd * gam[d] + bet[d];
        X[base + d] = __float2bfloat16((y > 0.f) ? (y + 1.f) : expf(y));
    }
}

// kv partial: kvp[sp][bh][d*48+e] = sum over 512 tokens of k[t,d]*v[t,e]
// 288 threads = 48 d-lanes x 6 e-groups; k held in register, v via broadcast float4
__global__ void __launch_bounds__(288) k_attn_kv(const bf16* __restrict__ qkv,
                                                 float* __restrict__ kvp,
                                                 float* __restrict__ ksp) {
    int bh = blockIdx.x, sp = blockIdx.y;
    int h = bh & (NH - 1), bc = bh >> 3;
    int tid = threadIdx.x;
    int d = tid % 48, eg = tid / 48;   // eg in 0..5
    __shared__ float sk[16][48];
    __shared__ float sv[16][48];
    float acc[8];
    #pragma unroll
    for (int p = 0; p < 8; p++) acc[p] = 0.f;
    float ks = 0.f;

    for (int c = 0; c < (GS / KVSPLIT) / 16; c++) {
        int tt0 = bc * GS + sp * (GS / KVSPLIT) + c * 16;
        #pragma unroll
        for (int r = 0; r < 3; r++) {
            int ti = eg + r * 6;
            if (ti < 16) {
                size_t row = (size_t)(tt0 + ti) * QS + h * HD + d;
                sk[ti][d] = __bfloat162float(qkv[row + D]);
                sv[ti][d] = __bfloat162float(qkv[row + 2 * D]);
            }
        }
        __syncthreads();
        #pragma unroll
        for (int ti = 0; ti < 16; ti++) {
            float kval = sk[ti][d];
            const float* vp = &sv[ti][eg * 8];
            float4 v0 = *(const float4*)vp;
            float4 v1 = *(const float4*)(vp + 4);
            acc[0] += kval * v0.x; acc[1] += kval * v0.y;
            acc[2] += kval * v0.z; acc[3] += kval * v0.w;
            acc[4] += kval * v1.x; acc[5] += kval * v1.y;
            acc[6] += kval * v1.z; acc[7] += kval * v1.w;
            if (tid < 48) ks += kval;
        }
        __syncthreads();
    }
    float* out = kvp + ((size_t)(sp * (B*NC*NH) + bh)) * HD * HD + d * HD + eg * 8;
    *(float4*)out = make_float4(acc[0], acc[1], acc[2], acc[3]);
    *(float4*)(out + 4) = make_float4(acc[4], acc[5], acc[6], acc[7]);
    if (tid < 48) ksp[(sp * (B*NC*NH) + bh) * HD + tid] = ks;
}

// apply: out[t,h,e] = (q.kv[:,e]) / (q.ksum + 1e-8); 384 threads = 64 tok x 6 eg
__global__ void __launch_bounds__(384) k_attn_apply(const bf16* __restrict__ qkv,
                                                    const float* __restrict__ kvp,
                                                    const float* __restrict__ ksp,
                                                    bf16* __restrict__ out) {
    int bh = blockIdx.x, tile = blockIdx.y;
    int h = bh & (NH - 1), bc = bh >> 3;
    int tid = threadIdx.x;
    __shared__ float skv[48 * 48];
    __shared__ float sks[48];
    __shared__ float sq[64][49];

    const float* kv0 = kvp + (size_t)bh * HD * HD;
    const float* kv1 = kvp + (size_t)(B*NC*NH + bh) * HD * HD;
    for (int i = tid; i < HD * HD; i += 384) skv[i] = kv0[i] + kv1[i];
    if (tid < 48) sks[tid] = ksp[bh * HD + tid] + ksp[(B*NC*NH + bh) * HD + tid];

    int t0 = bc * GS + tile * 64;
    int dd = tid % 48, tq = tid / 48;   // tq 0..7
    #pragma unroll
    for (int r = 0; r < 8; r++) {
        int lt = tq + r * 8;
        sq[lt][dd] = __bfloat162float(qkv[(size_t)(t0 + lt) * QS + h * HD + dd]);
    }
    __syncthreads();

    int g = tid % 6, lt = tid / 6;      // lt 0..63
    float acc[8];
    #pragma unroll
    for (int p = 0; p < 8; p++) acc[p] = 0.f;
    float den = 0.f;
    #pragma unroll 8
    for (int dl = 0; dl < 48; dl++) {
        float qq = sq[lt][dl];
        const float* kp = &skv[dl * 48 + g * 8];
        float4 a = *(const float4*)kp;
        float4 b = *(const float4*)(kp + 4);
        acc[0] += qq * a.x; acc[1] += qq * a.y;
        acc[2] += qq * a.z; acc[3] += qq * a.w;
        acc[4] += qq * b.x; acc[5] += qq * b.y;
        acc[6] += qq * b.z; acc[7] += qq * b.w;
        den += qq * sks[dl];
    }
    float rden = 1.f / (den + 1e-8f);
    bf16* op = out + (size_t)(t0 + lt) * D + h * HD + g * 8;
    *(bf162*)(op + 0) = __floats2bfloat162_rn(acc[0] * rden, acc[1] * rden);
    *(bf162*)(op + 2) = __floats2bfloat162_rn(acc[2] * rden, acc[3] * rden);
    *(bf162*)(op + 4) = __floats2bfloat162_rn(acc[4] * rden, acc[5] * rden);
    *(bf162*)(op + 6) = __floats2bfloat162_rn(acc[6] * rden, acc[7] * rden);
}

// x2 = A2[b,d]*wi + C2[b,d], bf16 in/out
__global__ void k_x2(const bf16* __restrict__ wi, const float* __restrict__ A,
                     const float* __restrict__ C, bf16* __restrict__ x2) {
    size_t idx = (size_t)blockIdx.x * 256 + threadIdx.x;
    int t = (int)(idx / D), d = (int)(idx % D);
    int b = t >> 12;
    x2[idx] = __float2bfloat16(A[b * D + d] * __bfloat162float(wi[idx]) + C[b * D + d]);
}

// out[b,d,pix] = image[b,d,pix] + wif[token(pix), d] * final_scalar[d]
__global__ void __launch_bounds__(256) k_final_t(
        const float* __restrict__ img, const bf16* __restrict__ wif,
        const int* __restrict__ invp, const float* __restrict__ fs,
        float* __restrict__ out) {
    __shared__ float tile[64][65];
    __shared__ int sinv[64];
    int p0 = blockIdx.x * 64, d0 = blockIdx.y * 64, b = blockIdx.z;
    int tid = threadIdx.x;
    if (tid < 64) sinv[tid] = invp[p0 + tid];
    __syncthreads();
    #pragma unroll
    for (int l = 0; l < 4; l++) {
        int j = tid + l * 256;
        int jp = j >> 4, i4 = (j & 15) * 4;
        int t = sinv[jp];
        const bf16* src = wif + ((size_t)(b * NP + t)) * D + d0 + i4;
        bf162 v01 = *(const bf162*)src;
        bf162 v23 = *(const bf162*)(src + 2);
        tile[i4 + 0][jp] = __bfloat162float(v01.x);
        tile[i4 + 1][jp] = __bfloat162float(v01.y);
        tile[i4 + 2][jp] = __bfloat162float(v23.x);
        tile[i4 + 3][jp] = __bfloat162float(v23.y);
    }
    __syncthreads();
    #pragma unroll
    for (int l = 0; l < 4; l++) {
        int j = tid + l * 256;
        int i = j >> 4, q = (j & 15) * 4;
        size_t o = ((size_t)(b * D + d0 + i)) * NP + p0 + q;
        float4 im4 = *(const float4*)(img + o);
        float f = fs[d0 + i];
        float4 r;
        r.x = im4.x + tile[i][q + 0] * f;
        r.y = im4.y + tile[i][q + 1] * f;
        r.z = im4.z + tile[i][q + 2] * f;
        r.w = im4.w + tile[i][q + 3] * f;
        *(float4*)(out + o) = r;
    }
}

// ---------------- driver ----------------------------------------------------
extern "C" void kernel_launch(void* const* d_in, const int* in_sizes, int n_in,
                              void* d_out, int out_size) {
    const float* image  = (const float*)d_in[0];
    const float* film   = (const float*)d_in[1];
    const int*   perm   = (const int*)d_in[2];
    const float* Wq = (const float*)d_in[3];  const float* bq = (const float*)d_in[4];
    const float* Wk = (const float*)d_in[5];  const float* bk = (const float*)d_in[6];
    const float* Wv = (const float*)d_in[7];  const float* bv = (const float*)d_in[8];
    const float* Wo = (const float*)d_in[9];  const float* bo = (const float*)d_in[10];
    const float* lnq_g = (const float*)d_in[11]; const float* lnq_b = (const float*)d_in[12];
    const float* lnk_g = (const float*)d_in[13]; const float* lnk_b = (const float*)d_in[14];
    const float* ada1_W = (const float*)d_in[15]; const float* ada1_b = (const float*)d_in[16];
    const float* grn1_g = (const float*)d_in[17]; const float* grn1_b = (const float*)d_in[18];
    const float* ada2_W = (const float*)d_in[19]; const float* ada2_b = (const float*)d_in[20];
    const float* grn2_g = (const float*)d_in[21]; const float* grn2_b = (const float*)d_in[22];
    const float* conv1_W = (const float*)d_in[23]; const float* conv1_b = (const float*)d_in[24];
    const float* conv2_W = (const float*)d_in[25]; const float* conv2_b = (const float*)d_in[26];
    const float* cs  = (const float*)d_in[27];
    const float* ffs = (const float*)d_in[28];
    const float* fs  = (const float*)d_in[29];
    float* out = (float*)d_out;

    float *p_gb1, *p_gb2, *p_gx, *p_gm, *p_A2, *p_C2, *p_gx2sq;
    int* p_invp;
    float *p_kv, *p_ks, *p_bqkv;
    bf16 *p_imtok16, *p_wi16, *p_wif16;
    bf16 *p_qkv16, *p_xg16, *p_att16, *p_x216, *p_h116;
    bf16 *p_wqkv16, *p_wo16, *p_c1w16, *p_c2w16;
    cudaGetSymbolAddress((void**)&p_gb1, g_gb1);
    cudaGetSymbolAddress((void**)&p_gb2, g_gb2);
    cudaGetSymbolAddress((void**)&p_gx, g_gx);
    cudaGetSymbolAddress((void**)&p_gm, g_gm);
    cudaGetSymbolAddress((void**)&p_A2, g_A2);
    cudaGetSymbolAddress((void**)&p_C2, g_C2);
    cudaGetSymbolAddress((void**)&p_gx2sq, g_gx2sq);
    cudaGetSymbolAddress((void**)&p_invp, g_invp);
    cudaGetSymbolAddress((void**)&p_kv, g_kv);
    cudaGetSymbolAddress((void**)&p_ks, g_ks);
    cudaGetSymbolAddress((void**)&p_bqkv, g_bqkv);
    cudaGetSymbolAddress((void**)&p_imtok16, g_imtok16);
    cudaGetSymbolAddress((void**)&p_wi16, g_wi16);
    cudaGetSymbolAddress((void**)&p_wif16, g_wif16);
    cudaGetSymbolAddress((void**)&p_qkv16, g_qkv16);
    cudaGetSymbolAddress((void**)&p_xg16, g_xg16);
    cudaGetSymbolAddress((void**)&p_att16, g_att16);
    cudaGetSymbolAddress((void**)&p_x216, g_x216);
    cudaGetSymbolAddress((void**)&p_h116, g_h116);
    cudaGetSymbolAddress((void**)&p_wqkv16, g_wqkv16);
    cudaGetSymbolAddress((void**)&p_wo16, g_wo16);
    cudaGetSymbolAddress((void**)&p_c1w16, g_c1w16);
    cudaGetSymbolAddress((void**)&p_c2w16, g_c2w16);

    cudaFuncSetAttribute((const void*)gemm_mma<false,false,false>,
                         cudaFuncAttributeMaxDynamicSharedMemorySize, GEMM_SMEM);
    cudaFuncSetAttribute((const void*)gemm_mma<false,true,true>,
                         cudaFuncAttributeMaxDynamicSharedMemorySize, GEMM_SMEM);
    cudaFuncSetAttribute((const void*)gemm_mma<true,false,false>,
                         cudaFuncAttributeMaxDynamicSharedMemorySize, GEMM_SMEM);
    cudaFuncSetAttribute((const void*)gemm_mma<false,true,false>,
                         cudaFuncAttributeMaxDynamicSharedMemorySize, GEMM_SMEM);

    // launch 0: all prep + film
    k_prep<<<(PREP_TOT + 255) / 256, 256>>>(Wq, Wk, Wv, Wo, conv1_W, conv2_W,
        bq, bk, bv, perm, film, ada1_W, ada1_b, ada2_W, ada2_b,
        p_wqkv16, p_wo16, p_c1w16, p_c2w16,
        p_bqkv, p_gx2sq, p_gm, p_invp, p_gb1, p_gb2);
    // launch 1: gx + batch mean
    k_gx_img<<<B * D, 256>>>(image, p_gx, p_gm);
    // launch 2: gather with inline adaLN1 coefficients
    k_gather_t<<<dim3(NP/64, D/64, B), 256>>>(image, p_invp, p_gx, p_gm,
        grn1_g, grn1_b, p_gb1, p_imtok16, p_xg16);
    // launch 3: packed QKV GEMM  <-- profiled launch
    gemm_mma<false,false,false><<<dim3(QS/128, T/128), 256, GEMM_SMEM>>>(
        p_xg16, p_wqkv16, p_bqkv, nullptr, nullptr, p_qkv16, nullptr, T, QS, D);

    k_lnelu<<<dim3(T/8, 2), 256>>>(p_qkv16, lnq_g, lnq_b, lnk_g, lnk_b);

    k_attn_kv<<<dim3(B * NC * NH, KVSPLIT), 288>>>(p_qkv16, p_kv, p_ks);
    k_attn_apply<<<dim3(B * NC * NH, 16), 384>>>(p_qkv16, p_kv, p_ks, p_att16);

    // wi = imtok + (attn@Wo^T + bo) * cs ; also gx2sq += wi^2
    gemm_mma<false,true,true><<<dim3(3, T/128), 256, GEMM_SMEM>>>(
        p_att16, p_wo16, bo, p_imtok16, cs, p_wi16, p_gx2sq, T, D, D);

    k_gmean_coef<<<B, 384>>>(p_gx2sq, grn2_g, grn2_b, p_gb2, p_A2, p_C2);
    k_x2<<<(int)(((size_t)T*D) / 256), 256>>>(p_wi16, p_A2, p_C2, p_x216);

    // h1 = silu(x2 @ conv1^T + b1)
    gemm_mma<true,false,false><<<dim3(12, T/128), 256, GEMM_SMEM>>>(
        p_x216, p_c1w16, conv1_b, nullptr, nullptr, p_h116, nullptr, T, D4, D);
    // wif = wi + (h1 @ conv2^T + b2) * ffs
    gemm_mma<false,true,false><<<dim3(3, T/128), 256, GEMM_SMEM>>>(
        p_h116, p_c2w16, conv2_b, p_wi16, ffs, p_wif16, nullptr, T, D, D4);

    k_final_t<<<dim3(NP/64, D/64, B), 256>>>(image, p_wif16, p_invp, fs, out);
}

// round 13
// speedup vs baseline: 1.2782x; 1.0521x over previous
#include <cuda_runtime.h>
#include <cuda_bf16.h>
#include <math.h>
#include <stdint.h>

#define B   8
#define D   384
#define FD  256
#define NP  4096
#define NH  8
#define NC  4
#define HD  48
#define GS  1024
#define T   (B*NP)     /* 32768 tokens */
#define D4  1536
#define D2  768
#define QS  1152       /* packed qkv row stride */
#define KVSPLIT 2

typedef __nv_bfloat16 bf16;
typedef __nv_bfloat162 bf162;

// ---------------- scratch (device globals) ----------------------------------
static __device__ float g_gb1[B*D2];
static __device__ float g_gb2[B*D2];
static __device__ float g_gx[B*D];
static __device__ float g_gm[B];
static __device__ float g_A2[B*D];
static __device__ float g_C2[B*D];
static __device__ float g_gx2sq[B*D];
static __device__ int   g_invp[NP];
static __device__ float g_kv[KVSPLIT*B*NC*NH*HD*HD];
static __device__ float g_ks[KVSPLIT*B*NC*NH*HD];
static __device__ float g_bqkv[QS];
// bf16 activations
static __device__ bf16  g_imtok16[(size_t)T*D];
static __device__ bf16  g_wi16[(size_t)T*D];
static __device__ bf16  g_wif16[(size_t)T*D];
static __device__ bf16  g_qkv16[(size_t)T*QS];
static __device__ bf16  g_xg16[(size_t)T*D];
static __device__ bf16  g_att16[(size_t)T*D];
static __device__ bf16  g_x216[(size_t)T*D];
static __device__ bf16  g_h116[(size_t)T*D4];
// bf16 weights
static __device__ bf16  g_wqkv16[QS*D];
static __device__ bf16  g_wo16[D*D];
static __device__ bf16  g_c1w16[D4*D];
static __device__ bf16  g_c2w16[D*D4];

// ---------------- helpers ----------------------------------------------------
__device__ __forceinline__ uint32_t sptr(const void* p) {
    return (uint32_t)__cvta_generic_to_shared(p);
}
__device__ __forceinline__ void cp16(uint32_t s, const void* g) {
    asm volatile("cp.async.cg.shared.global [%0], [%1], 16;\n" :: "r"(s), "l"(g));
}
__device__ __forceinline__ void cp_commit() {
    asm volatile("cp.async.commit_group;\n");
}
template<int N>
__device__ __forceinline__ void cp_wait() {
    asm volatile("cp.async.wait_group %0;\n" :: "n"(N));
}
__device__ __forceinline__ void mma16816(float* c, const uint32_t* a, const uint32_t* b) {
    asm volatile(
        "mma.sync.aligned.m16n8k16.row.col.f32.bf16.bf16.f32 "
        "{%0,%1,%2,%3}, {%4,%5,%6,%7}, {%8,%9}, {%0,%1,%2,%3};\n"
        : "+f"(c[0]), "+f"(c[1]), "+f"(c[2]), "+f"(c[3])
        : "r"(a[0]), "r"(a[1]), "r"(a[2]), "r"(a[3]), "r"(b[0]), "r"(b[1]));
}
__device__ __forceinline__ void ldsm4(uint32_t* r, uint32_t a) {
    asm volatile("ldmatrix.sync.aligned.m8n8.x4.shared.b16 {%0,%1,%2,%3}, [%4];"
        : "=r"(r[0]), "=r"(r[1]), "=r"(r[2]), "=r"(r[3]) : "r"(a));
}

__device__ __forceinline__ float blockReduce384(float v, float* sdata) {
    int tid = threadIdx.x;
    sdata[tid] = v;
    if (tid < 128) sdata[384 + tid] = 0.f;
    __syncthreads();
    #pragma unroll
    for (int s = 256; s >= 1; s >>= 1) {
        if (tid < s) sdata[tid] += sdata[tid + s];
        __syncthreads();
    }
    float r = sdata[0];
    __syncthreads();
    return r;
}

// ---------------- launch 0: prep (weights/bias/zero/invperm) + film ----------
#define NWQKV (3*D*D)
#define NWO   (D*D)
#define NC1   (D4*D)
#define NC2   (D*D4)
#define NFILM (2*B*D2)
#define PREP_TOT (NWQKV + NWO + NC1 + NC2 + QS + B*D + B + NP + NFILM)
__global__ void k_prep(const float* __restrict__ Wq, const float* __restrict__ Wk,
                       const float* __restrict__ Wv, const float* __restrict__ Wo,
                       const float* __restrict__ c1, const float* __restrict__ c2,
                       const float* __restrict__ bq, const float* __restrict__ bk,
                       const float* __restrict__ bv,
                       const int* __restrict__ perm,
                       const float* __restrict__ film,
                       const float* __restrict__ W1, const float* __restrict__ b1,
                       const float* __restrict__ W2, const float* __restrict__ b2,
                       bf16* __restrict__ wqkv, bf16* __restrict__ wo,
                       bf16* __restrict__ c1o, bf16* __restrict__ c2o,
                       float* __restrict__ bqkv, float* __restrict__ gx2sq,
                       float* __restrict__ gm, int* __restrict__ invp,
                       float* __restrict__ gb1, float* __restrict__ gb2) {
    int i = blockIdx.x * blockDim.x + threadIdx.x;
    if (i < NWQKV) {
        int seg = i / (D*D), r = i % (D*D);
        const float* W = (seg == 0) ? Wq : (seg == 1) ? Wk : Wv;
        wqkv[i] = __float2bfloat16(W[r]);
        return;
    }
    i -= NWQKV;
    if (i < NWO) { wo[i] = __float2bfloat16(Wo[i]); return; }
    i -= NWO;
    if (i < NC1) { c1o[i] = __float2bfloat16(c1[i]); return; }
    i -= NC1;
    if (i < NC2) { c2o[i] = __float2bfloat16(c2[i]); return; }
    i -= NC2;
    if (i < QS) {
        bqkv[i] = (i < D) ? bq[i] : (i < 2*D) ? bk[i - D] : bv[i - 2*D];
        return;
    }
    i -= QS;
    if (i < B*D) { gx2sq[i] = 0.f; return; }
    i -= B*D;
    if (i < B) { gm[i] = 0.f; return; }
    i -= B;
    if (i < NP) { invp[perm[i]] = i; return; }
    i -= NP;
    if (i < NFILM) {
        int which = i / (B * D2);
        int r = i % (B * D2);
        int b = r / D2, j = r % D2;
        const float* W = which ? W2 : W1;
        const float* bb = which ? b2 : b1;
        const float* f = film + b * FD;
        const float* w = W + (size_t)j * FD;
        float s = 0.f;
        #pragma unroll 8
        for (int q = 0; q < FD; q++) s += f[q] * w[q];
        s += bb[j];
        if (which) gb2[r] = s; else gb1[r] = s;
    }
}

// ---------------- launch 1: per-(b,d) L2 norm + atomic batch-mean ------------
__global__ void k_gx_img(const float* __restrict__ img, float* __restrict__ gx,
                         float* __restrict__ gm) {
    __shared__ float sdata[256];
    int bd = blockIdx.x;
    const float* p = img + (size_t)bd * NP;
    float s = 0.f;
    for (int i = threadIdx.x; i < NP; i += 256) { float v = p[i]; s += v * v; }
    sdata[threadIdx.x] = s; __syncthreads();
    for (int st = 128; st >= 1; st >>= 1) {
        if (threadIdx.x < st) sdata[threadIdx.x] += sdata[threadIdx.x + st];
        __syncthreads();
    }
    if (threadIdx.x == 0) {
        float g = sqrtf(sdata[0]);
        gx[bd] = g;
        atomicAdd(&gm[bd / D], g * (1.f / (float)D));
    }
}

// gmean+coef for GRN2 (input gx2sq needs sqrt)
__global__ void k_gmean_coef(const float* __restrict__ gxsq,
                             const float* __restrict__ gg, const float* __restrict__ gb_,
                             const float* __restrict__ gbmat,
                             float* __restrict__ A, float* __restrict__ C) {
    __shared__ float sdata[512];
    int b = blockIdx.x, d = threadIdx.x;
    float gv = sqrtf(gxsq[b * D + d]);
    float s = blockReduce384(gv, sdata);
    float gm = s / (float)D;
    float nx = gv / (gm + 1e-6f);
    float gamma = gbmat[b * D2 + d];
    float beta  = gbmat[b * D2 + D + d];
    A[b * D + d] = ((1.f + gg[d]) * nx + 1.f) * (1.f + gamma);
    C[b * D + d] = gb_[d] * (1.f + gamma) + beta;
}

// ---------------- launch 2: transpose-gather with inline adaLN1 coef ---------
__global__ void __launch_bounds__(256) k_gather_t(
        const float* __restrict__ img, const int* __restrict__ invp,
        const float* __restrict__ gx, const float* __restrict__ gm,
        const float* __restrict__ gg, const float* __restrict__ gb_,
        const float* __restrict__ gb1,
        bf16* __restrict__ imtok, bf16* __restrict__ xg) {
    __shared__ float tile[64][65];
    __shared__ float sA[64], sC[64];
    __shared__ int sinv[64];
    int p0 = blockIdx.x * 64, d0 = blockIdx.y * 64, b = blockIdx.z;
    int tid = threadIdx.x;
    if (tid < 64) sinv[tid] = invp[p0 + tid];
    else if (tid >= 64 && tid < 128) {
        int dl = tid - 64, d = d0 + dl;
        float nx = gx[b * D + d] / (gm[b] + 1e-6f);
        float gamma = gb1[b * D2 + d];
        float beta  = gb1[b * D2 + D + d];
        sA[dl] = ((1.f + gg[d]) * nx + 1.f) * (1.f + gamma);
        sC[dl] = gb_[d] * (1.f + gamma) + beta;
    }
    #pragma unroll
    for (int l = 0; l < 4; l++) {
        int j = tid + l * 256;
        int i = j >> 4, q = (j & 15) * 4;
        float4 v = *(const float4*)(img + ((size_t)(b * D + d0 + i)) * NP + p0 + q);
        tile[i][q + 0] = v.x; tile[i][q + 1] = v.y;
        tile[i][q + 2] = v.z; tile[i][q + 3] = v.w;
    }
    __syncthreads();
    #pragma unroll
    for (int l = 0; l < 4; l++) {
        int j = tid + l * 256;
        int jp = j >> 4, i4 = (j & 15) * 4;
        int t = sinv[jp];
        size_t o = ((size_t)(b * NP + t)) * D + d0 + i4;
        float vv[4], xv[4];
        #pragma unroll
        for (int r = 0; r < 4; r++) {
            vv[r] = tile[i4 + r][jp];
            xv[r] = sA[i4 + r] * vv[r] + sC[i4 + r];
        }
        *(bf162*)&imtok[o] = __floats2bfloat162_rn(vv[0], vv[1]);
        *(bf162*)&imtok[o + 2] = __floats2bfloat162_rn(vv[2], vv[3]);
        *(bf162*)&xg[o] = __floats2bfloat162_rn(xv[0], xv[1]);
        *(bf162*)&xg[o + 2] = __floats2bfloat162_rn(xv[2], xv[3]);
    }
}

// ---------------- bf16 tensor-core GEMM (BK=64, 3-stage, XOR swizzle) --------
// Stage = 128 rows x 128B per operand (no padding). chunk' = chunk ^ (row & 7).
#define STG 3
#define STAGE_B 16384                    /* bytes per operand per stage */
#define GEMM_SMEM (STG * 2 * STAGE_B)    /* 98304 */
template<bool SILU, bool RES, bool GX2>
__global__ void __launch_bounds__(256, 2) gemm_mma(
        const bf16* __restrict__ A, const bf16* __restrict__ W,
        const float* __restrict__ bias, const bf16* __restrict__ res,
        const float* __restrict__ scale, bf16* __restrict__ C,
        float* __restrict__ gx2sq, int M, int N, int K) {
    extern __shared__ char smem[];
    uint32_t sbA = sptr(smem);
    uint32_t sbW = sbA + STG * STAGE_B;
    int tid = threadIdx.x;
    int m0 = blockIdx.y * 128, n0 = blockIdx.x * 128;
    int lane = tid & 31, warp = tid >> 5;
    int g = lane >> 2, tg = lane & 3;
    int wm = warp >> 2, wn = warp & 3;
    int lane8 = lane & 7, laneg = lane >> 3;

    // fragment row bases + swizzle masks
    uint32_t aByte[4], aMask[4];
    #pragma unroll
    for (int im = 0; im < 4; im++) {
        int row = wm * 64 + im * 16 + lane8 + (laneg & 1) * 8;
        aByte[im] = (uint32_t)row * 128;
        aMask[im] = (uint32_t)(row & 7);
    }
    uint32_t bByte[2], bMask[2];
    #pragma unroll
    for (int p = 0; p < 2; p++) {
        int row = wn * 32 + p * 16 + lane8 + (laneg >> 1) * 8;
        bByte[p] = (uint32_t)row * 128;
        bMask[p] = (uint32_t)(row & 7);
    }
    uint32_t cA = (uint32_t)(laneg >> 1);   // chunk base for A frag
    uint32_t cB = (uint32_t)(laneg & 1);    // chunk base for B frag

    float acc[4][4][4];
    #pragma unroll
    for (int i = 0; i < 4; i++)
        #pragma unroll
        for (int j = 0; j < 4; j++)
            #pragma unroll
            for (int p = 0; p < 4; p++) acc[i][j][p] = 0.f;

    int nt = K / 64;
    auto issue = [&](int t) {
        if (t < nt) {
            int s = t % STG;
            int k0 = t * 64;
            uint32_t ab = sbA + s * STAGE_B;
            uint32_t wb = sbW + s * STAGE_B;
            #pragma unroll
            for (int l = 0; l < 4; l++) {
                int j = tid + l * 256;                 // 0..1023
                uint32_t row = (uint32_t)(j >> 3), q8 = (uint32_t)(j & 7);
                uint32_t sw = (q8 ^ (row & 7)) << 4;
                cp16(ab + row * 128 + sw, A + (size_t)(m0 + (int)row) * K + k0 + (int)q8 * 8);
                cp16(wb + row * 128 + sw, W + (size_t)(n0 + (int)row) * K + k0 + (int)q8 * 8);
            }
        }
        cp_commit();
    };

    issue(0);
    issue(1);
    for (int t = 0; t < nt; t++) {
        issue(t + 2);
        cp_wait<2>();
        __syncthreads();
        int s = t % STG;
        uint32_t aBase = sbA + s * STAGE_B;
        uint32_t wBase = sbW + s * STAGE_B;
        #pragma unroll
        for (int kk = 0; kk < 64; kk += 16) {
            uint32_t kc = (uint32_t)(kk >> 3);       // chunk offset {0,2,4,6}
            uint32_t af[4][4], bf[2][4];
            #pragma unroll
            for (int im = 0; im < 4; im++)
                ldsm4(af[im], aBase + aByte[im] + (((kc + cA) ^ aMask[im]) << 4));
            #pragma unroll
            for (int p = 0; p < 2; p++)
                ldsm4(bf[p], wBase + bByte[p] + (((kc + cB) ^ bMask[p]) << 4));
            #pragma unroll
            for (int im = 0; im < 4; im++)
                #pragma unroll
                for (int in = 0; in < 4; in++)
                    mma16816(acc[im][in], af[im], &bf[in >> 1][(in & 1) * 2]);
        }
        __syncthreads();
    }

    // epilogue
    float sums[4][2];
    if (GX2) {
        #pragma unroll
        for (int in = 0; in < 4; in++) { sums[in][0] = 0.f; sums[in][1] = 0.f; }
    }
    #pragma unroll
    for (int im = 0; im < 4; im++) {
        int r0 = m0 + wm * 64 + im * 16 + g;
        #pragma unroll
        for (int in = 0; in < 4; in++) {
            int c = n0 + wn * 32 + in * 8 + tg * 2;
            float b0 = bias[c], b1 = bias[c + 1];
            float v00 = acc[im][in][0] + b0, v01 = acc[im][in][1] + b1;
            float v10 = acc[im][in][2] + b0, v11 = acc[im][in][3] + b1;
            if (SILU) {
                v00 = v00 / (1.f + expf(-v00)); v01 = v01 / (1.f + expf(-v01));
                v10 = v10 / (1.f + expf(-v10)); v11 = v11 / (1.f + expf(-v11));
            }
            if (RES) {
                float s0 = scale[c], s1 = scale[c + 1];
                bf162 ra = *(const bf162*)&res[(size_t)r0 * N + c];
                bf162 rb = *(const bf162*)&res[(size_t)(r0 + 8) * N + c];
                v00 = __bfloat162float(ra.x) + v00 * s0;
                v01 = __bfloat162float(ra.y) + v01 * s1;
                v10 = __bfloat162float(rb.x) + v10 * s0;
                v11 = __bfloat162float(rb.y) + v11 * s1;
            }
            if (GX2) {
                sums[in][0] += v00 * v00 + v10 * v10;
                sums[in][1] += v01 * v01 + v11 * v11;
            }
            *(bf162*)&C[(size_t)r0 * N + c] = __floats2bfloat162_rn(v00, v01);
            *(bf162*)&C[(size_t)(r0 + 8) * N + c] = __floats2bfloat162_rn(v10, v11);
        }
    }
    if (GX2) {
        #pragma unroll
        for (int off = 4; off <= 16; off <<= 1) {
            #pragma unroll
            for (int in = 0; in < 4; in++) {
                sums[in][0] += __shfl_xor_sync(0xffffffff, sums[in][0], off);
                sums[in][1] += __shfl_xor_sync(0xffffffff, sums[in][1], off);
            }
        }
        if (lane < 4) {
            int b = m0 >> 12;
            #pragma unroll
            for (int in = 0; in < 4; in++) {
                int c = n0 + wn * 32 + in * 8 + tg * 2;
                atomicAdd(&gx2sq[b * D + c], sums[in][0]);
                atomicAdd(&gx2sq[b * D + c + 1], sums[in][1]);
            }
        }
    }
}

// per-token LayerNorm over D then elu+1, bf16 in/out, warp per token; y: 0=q, 1=k
__global__ void __launch_bounds__(256) k_lnelu(bf16* __restrict__ X,
        const float* __restrict__ gq, const float* __restrict__ bq_,
        const float* __restrict__ gk, const float* __restrict__ bk_) {
    int warp = threadIdx.x >> 5, lane = threadIdx.x & 31;
    int t = blockIdx.x * 8 + warp;
    int seg = blockIdx.y;
    const float* gam = seg ? gk : gq;
    const float* bet = seg ? bk_ : bq_;
    size_t base = (size_t)t * QS + seg * D;
    float v[12];
    float s = 0.f, s2 = 0.f;
    #pragma unroll
    for (int j = 0; j < 12; j++) {
        v[j] = __bfloat162float(X[base + j * 32 + lane]);
        s += v[j]; s2 += v[j] * v[j];
    }
    #pragma unroll
    for (int o = 16; o >= 1; o >>= 1) {
        s  += __shfl_xor_sync(0xffffffff, s, o);
        s2 += __shfl_xor_sync(0xffffffff, s2, o);
    }
    float mean = s / (float)D;
    float var = s2 / (float)D - mean * mean;
    float rstd = rsqrtf(var + 1e-5f);
    #pragma unroll
    for (int j = 0; j < 12; j++) {
        int d = j * 32 + lane;
        float y = (v[j] - mean) * rstd * gam[d] + bet[d];
        X[base + d] = __float2bfloat16((y > 0.f) ? (y + 1.f) : expf(y));
    }
}

// kv partial: kvp[sp][bh][d*48+e] = sum over 512 tokens of k[t,d]*v[t,e]
__global__ void __launch_bounds__(288) k_attn_kv(const bf16* __restrict__ qkv,
                                                 float* __restrict__ kvp,
                                                 float* __restrict__ ksp) {
    int bh = blockIdx.x, sp = blockIdx.y;
    int h = bh & (NH - 1), bc = bh >> 3;
    int tid = threadIdx.x;
    int d = tid % 48, eg = tid / 48;
    __shared__ float sk[16][48];
    __shared__ float sv[16][48];
    float acc[8];
    #pragma unroll
    for (int p = 0; p < 8; p++) acc[p] = 0.f;
    float ks = 0.f;

    for (int c = 0; c < (GS / KVSPLIT) / 16; c++) {
        int tt0 = bc * GS + sp * (GS / KVSPLIT) + c * 16;
        #pragma unroll
        for (int r = 0; r < 3; r++) {
            int ti = eg + r * 6;
            if (ti < 16) {
                size_t row = (size_t)(tt0 + ti) * QS + h * HD + d;
                sk[ti][d] = __bfloat162float(qkv[row + D]);
                sv[ti][d] = __bfloat162float(qkv[row + 2 * D]);
            }
        }
        __syncthreads();
        #pragma unroll
        for (int ti = 0; ti < 16; ti++) {
            float kval = sk[ti][d];
            const float* vp = &sv[ti][eg * 8];
            float4 v0 = *(const float4*)vp;
            float4 v1 = *(const float4*)(vp + 4);
            acc[0] += kval * v0.x; acc[1] += kval * v0.y;
            acc[2] += kval * v0.z; acc[3] += kval * v0.w;
            acc[4] += kval * v1.x; acc[5] += kval * v1.y;
            acc[6] += kval * v1.z; acc[7] += kval * v1.w;
            if (tid < 48) ks += kval;
        }
        __syncthreads();
    }
    float* out = kvp + ((size_t)(sp * (B*NC*NH) + bh)) * HD * HD + d * HD + eg * 8;
    *(float4*)out = make_float4(acc[0], acc[1], acc[2], acc[3]);
    *(float4*)(out + 4) = make_float4(acc[4], acc[5], acc[6], acc[7]);
    if (tid < 48) ksp[(sp * (B*NC*NH) + bh) * HD + tid] = ks;
}

// apply: out[t,h,e] = (q.kv[:,e]) / (q.ksum + 1e-8); 384 threads = 64 tok x 6 eg
__global__ void __launch_bounds__(384) k_attn_apply(const bf16* __restrict__ qkv,
                                                    const float* __restrict__ kvp,
                                                    const float* __restrict__ ksp,
                                                    bf16* __restrict__ out) {
    int bh = blockIdx.x, tile = blockIdx.y;
    int h = bh & (NH - 1), bc = bh >> 3;
    int tid = threadIdx.x;
    __shared__ float skv[48 * 48];
    __shared__ float sks[48];
    __shared__ float sq[64][49];

    const float* kv0 = kvp + (size_t)bh * HD * HD;
    const float* kv1 = kvp + (size_t)(B*NC*NH + bh) * HD * HD;
    for (int i = tid; i < HD * HD; i += 384) skv[i] = kv0[i] + kv1[i];
    if (tid < 48) sks[tid] = ksp[bh * HD + tid] + ksp[(B*NC*NH + bh) * HD + tid];

    int t0 = bc * GS + tile * 64;
    int dd = tid % 48, tq = tid / 48;
    #pragma unroll
    for (int r = 0; r < 8; r++) {
        int lt = tq + r * 8;
        sq[lt][dd] = __bfloat162float(qkv[(size_t)(t0 + lt) * QS + h * HD + dd]);
    }
    __syncthreads();

    int g = tid % 6, lt = tid / 6;
    float acc[8];
    #pragma unroll
    for (int p = 0; p < 8; p++) acc[p] = 0.f;
    float den = 0.f;
    #pragma unroll 8
    for (int dl = 0; dl < 48; dl++) {
        float qq = sq[lt][dl];
        const float* kp = &skv[dl * 48 + g * 8];
        float4 a = *(const float4*)kp;
        float4 b = *(const float4*)(kp + 4);
        acc[0] += qq * a.x; acc[1] += qq * a.y;
        acc[2] += qq * a.z; acc[3] += qq * a.w;
        acc[4] += qq * b.x; acc[5] += qq * b.y;
        acc[6] += qq * b.z; acc[7] += qq * b.w;
        den += qq * sks[dl];
    }
    float rden = 1.f / (den + 1e-8f);
    bf16* op = out + (size_t)(t0 + lt) * D + h * HD + g * 8;
    *(bf162*)(op + 0) = __floats2bfloat162_rn(acc[0] * rden, acc[1] * rden);
    *(bf162*)(op + 2) = __floats2bfloat162_rn(acc[2] * rden, acc[3] * rden);
    *(bf162*)(op + 4) = __floats2bfloat162_rn(acc[4] * rden, acc[5] * rden);
    *(bf162*)(op + 6) = __floats2bfloat162_rn(acc[6] * rden, acc[7] * rden);
}

// x2 = A2[b,d]*wi + C2[b,d], bf16 in/out
__global__ void k_x2(const bf16* __restrict__ wi, const float* __restrict__ A,
                     const float* __restrict__ C, bf16* __restrict__ x2) {
    size_t idx = (size_t)blockIdx.x * 256 + threadIdx.x;
    int t = (int)(idx / D), d = (int)(idx % D);
    int b = t >> 12;
    x2[idx] = __float2bfloat16(A[b * D + d] * __bfloat162float(wi[idx]) + C[b * D + d]);
}

// out[b,d,pix] = image[b,d,pix] + wif[token(pix), d] * final_scalar[d]
__global__ void __launch_bounds__(256) k_final_t(
        const float* __restrict__ img, const bf16* __restrict__ wif,
        const int* __restrict__ invp, const float* __restrict__ fs,
        float* __restrict__ out) {
    __shared__ float tile[64][65];
    __shared__ int sinv[64];
    int p0 = blockIdx.x * 64, d0 = blockIdx.y * 64, b = blockIdx.z;
    int tid = threadIdx.x;
    if (tid < 64) sinv[tid] = invp[p0 + tid];
    __syncthreads();
    #pragma unroll
    for (int l = 0; l < 4; l++) {
        int j = tid + l * 256;
        int jp = j >> 4, i4 = (j & 15) * 4;
        int t = sinv[jp];
        const bf16* src = wif + ((size_t)(b * NP + t)) * D + d0 + i4;
        bf162 v01 = *(const bf162*)src;
        bf162 v23 = *(const bf162*)(src + 2);
        tile[i4 + 0][jp] = __bfloat162float(v01.x);
        tile[i4 + 1][jp] = __bfloat162float(v01.y);
        tile[i4 + 2][jp] = __bfloat162float(v23.x);
        tile[i4 + 3][jp] = __bfloat162float(v23.y);
    }
    __syncthreads();
    #pragma unroll
    for (int l = 0; l < 4; l++) {
        int j = tid + l * 256;
        int i = j >> 4, q = (j & 15) * 4;
        size_t o = ((size_t)(b * D + d0 + i)) * NP + p0 + q;
        float4 im4 = *(const float4*)(img + o);
        float f = fs[d0 + i];
        float4 r;
        r.x = im4.x + tile[i][q + 0] * f;
        r.y = im4.y + tile[i][q + 1] * f;
        r.z = im4.z + tile[i][q + 2] * f;
        r.w = im4.w + tile[i][q + 3] * f;
        *(float4*)(out + o) = r;
    }
}

// ---------------- driver ----------------------------------------------------
extern "C" void kernel_launch(void* const* d_in, const int* in_sizes, int n_in,
                              void* d_out, int out_size) {
    const float* image  = (const float*)d_in[0];
    const float* film   = (const float*)d_in[1];
    const int*   perm   = (const int*)d_in[2];
    const float* Wq = (const float*)d_in[3];  const float* bq = (const float*)d_in[4];
    const float* Wk = (const float*)d_in[5];  const float* bk = (const float*)d_in[6];
    const float* Wv = (const float*)d_in[7];  const float* bv = (const float*)d_in[8];
    const float* Wo = (const float*)d_in[9];  const float* bo = (const float*)d_in[10];
    const float* lnq_g = (const float*)d_in[11]; const float* lnq_b = (const float*)d_in[12];
    const float* lnk_g = (const float*)d_in[13]; const float* lnk_b = (const float*)d_in[14];
    const float* ada1_W = (const float*)d_in[15]; const float* ada1_b = (const float*)d_in[16];
    const float* grn1_g = (const float*)d_in[17]; const float* grn1_b = (const float*)d_in[18];
    const float* ada2_W = (const float*)d_in[19]; const float* ada2_b = (const float*)d_in[20];
    const float* grn2_g = (const float*)d_in[21]; const float* grn2_b = (const float*)d_in[22];
    const float* conv1_W = (const float*)d_in[23]; const float* conv1_b = (const float*)d_in[24];
    const float* conv2_W = (const float*)d_in[25]; const float* conv2_b = (const float*)d_in[26];
    const float* cs  = (const float*)d_in[27];
    const float* ffs = (const float*)d_in[28];
    const float* fs  = (const float*)d_in[29];
    float* out = (float*)d_out;

    float *p_gb1, *p_gb2, *p_gx, *p_gm, *p_A2, *p_C2, *p_gx2sq;
    int* p_invp;
    float *p_kv, *p_ks, *p_bqkv;
    bf16 *p_imtok16, *p_wi16, *p_wif16;
    bf16 *p_qkv16, *p_xg16, *p_att16, *p_x216, *p_h116;
    bf16 *p_wqkv16, *p_wo16, *p_c1w16, *p_c2w16;
    cudaGetSymbolAddress((void**)&p_gb1, g_gb1);
    cudaGetSymbolAddress((void**)&p_gb2, g_gb2);
    cudaGetSymbolAddress((void**)&p_gx, g_gx);
    cudaGetSymbolAddress((void**)&p_gm, g_gm);
    cudaGetSymbolAddress((void**)&p_A2, g_A2);
    cudaGetSymbolAddress((void**)&p_C2, g_C2);
    cudaGetSymbolAddress((void**)&p_gx2sq, g_gx2sq);
    cudaGetSymbolAddress((void**)&p_invp, g_invp);
    cudaGetSymbolAddress((void**)&p_kv, g_kv);
    cudaGetSymbolAddress((void**)&p_ks, g_ks);
    cudaGetSymbolAddress((void**)&p_bqkv, g_bqkv);
    cudaGetSymbolAddress((void**)&p_imtok16, g_imtok16);
    cudaGetSymbolAddress((void**)&p_wi16, g_wi16);
    cudaGetSymbolAddress((void**)&p_wif16, g_wif16);
    cudaGetSymbolAddress((void**)&p_qkv16, g_qkv16);
    cudaGetSymbolAddress((void**)&p_xg16, g_xg16);
    cudaGetSymbolAddress((void**)&p_att16, g_att16);
    cudaGetSymbolAddress((void**)&p_x216, g_x216);
    cudaGetSymbolAddress((void**)&p_h116, g_h116);
    cudaGetSymbolAddress((void**)&p_wqkv16, g_wqkv16);
    cudaGetSymbolAddress((void**)&p_wo16, g_wo16);
    cudaGetSymbolAddress((void**)&p_c1w16, g_c1w16);
    cudaGetSymbolAddress((void**)&p_c2w16, g_c2w16);

    cudaFuncSetAttribute((const void*)gemm_mma<false,false,false>,
                         cudaFuncAttributeMaxDynamicSharedMemorySize, GEMM_SMEM);
    cudaFuncSetAttribute((const void*)gemm_mma<false,true,true>,
                         cudaFuncAttributeMaxDynamicSharedMemorySize, GEMM_SMEM);
    cudaFuncSetAttribute((const void*)gemm_mma<true,false,false>,
                         cudaFuncAttributeMaxDynamicSharedMemorySize, GEMM_SMEM);
    cudaFuncSetAttribute((const void*)gemm_mma<false,true,false>,
                         cudaFuncAttributeMaxDynamicSharedMemorySize, GEMM_SMEM);

    // launch 0: all prep + film
    k_prep<<<(PREP_TOT + 255) / 256, 256>>>(Wq, Wk, Wv, Wo, conv1_W, conv2_W,
        bq, bk, bv, perm, film, ada1_W, ada1_b, ada2_W, ada2_b,
        p_wqkv16, p_wo16, p_c1w16, p_c2w16,
        p_bqkv, p_gx2sq, p_gm, p_invp, p_gb1, p_gb2);
    // launch 1: gx + batch mean
    k_gx_img<<<B * D, 256>>>(image, p_gx, p_gm);
    // launch 2: gather with inline adaLN1 coefficients
    k_gather_t<<<dim3(NP/64, D/64, B), 256>>>(image, p_invp, p_gx, p_gm,
        grn1_g, grn1_b, p_gb1, p_imtok16, p_xg16);
    // launch 3: packed QKV GEMM  <-- profiled launch
    gemm_mma<false,false,false><<<dim3(QS/128, T/128), 256, GEMM_SMEM>>>(
        p_xg16, p_wqkv16, p_bqkv, nullptr, nullptr, p_qkv16, nullptr, T, QS, D);

    k_lnelu<<<dim3(T/8, 2), 256>>>(p_qkv16, lnq_g, lnq_b, lnk_g, lnk_b);

    k_attn_kv<<<dim3(B * NC * NH, KVSPLIT), 288>>>(p_qkv16, p_kv, p_ks);
    k_attn_apply<<<dim3(B * NC * NH, 16), 384>>>(p_qkv16, p_kv, p_ks, p_att16);

    // wi = imtok + (attn@Wo^T + bo) * cs ; also gx2sq += wi^2
    gemm_mma<false,true,true><<<dim3(3, T/128), 256, GEMM_SMEM>>>(
        p_att16, p_wo16, bo, p_imtok16, cs, p_wi16, p_gx2sq, T, D, D);

    k_gmean_coef<<<B, 384>>>(p_gx2sq, grn2_g, grn2_b, p_gb2, p_A2, p_C2);
    k_x2<<<(int)(((size_t)T*D) / 256), 256>>>(p_wi16, p_A2, p_C2, p_x216);

    // h1 = silu(x2 @ conv1^T + b1)
    gemm_mma<true,false,false><<<dim3(12, T/128), 256, GEMM_SMEM>>>(
        p_x216, p_c1w16, conv1_b, nullptr, nullptr, p_h116, nullptr, T, D4, D);
    // wif = wi + (h1 @ conv2^T + b2) * ffs
    gemm_mma<false,true,false><<<dim3(3, T/128), 256, GEMM_SMEM>>>(
        p_h116, p_c2w16, conv2_b, p_wi16, ffs, p_wif16, nullptr, T, D, D4);

    k_final_t<<<dim3(NP/64, D/64, B), 256>>>(image, p_wif16, p_invp, fs, out);
}

// round 14
// speedup vs baseline: 1.3294x; 1.0401x over previous
#include <cuda_runtime.h>
#include <cuda_bf16.h>
#include <math.h>
#include <stdint.h>

#define B   8
#define D   384
#define FD  256
#define NP  4096
#define NH  8
#define NC  4
#define HD  48
#define GS  1024
#define T   (B*NP)     /* 32768 tokens */
#define D4  1536
#define D2  768
#define QS  1152       /* packed qkv row stride */
#define KVSPLIT 2

typedef __nv_bfloat16 bf16;
typedef __nv_bfloat162 bf162;

// ---------------- scratch (device globals) ----------------------------------
static __device__ float g_gb1[B*D2];
static __device__ float g_gb2[B*D2];
static __device__ float g_gx[B*D];
static __device__ float g_A2[B*D];
static __device__ float g_C2[B*D];
static __device__ float g_gx2sq[B*D];
static __device__ int   g_invp[NP];
static __device__ float g_kv[KVSPLIT*B*NC*NH*HD*HD];
static __device__ float g_ks[KVSPLIT*B*NC*NH*HD];
static __device__ float g_bqkv[QS];
// bf16 activations
static __device__ bf16  g_imtok16[(size_t)T*D];
static __device__ bf16  g_wi16[(size_t)T*D];
static __device__ bf16  g_wif16[(size_t)T*D];
static __device__ bf16  g_qkv16[(size_t)T*QS];
static __device__ bf16  g_xg16[(size_t)T*D];
static __device__ bf16  g_att16[(size_t)T*D];
static __device__ bf16  g_x216[(size_t)T*D];
static __device__ bf16  g_h116[(size_t)T*D4];
// bf16 weights
static __device__ bf16  g_wqkv16[QS*D];
static __device__ bf16  g_wo16[D*D];
static __device__ bf16  g_c1w16[D4*D];
static __device__ bf16  g_c2w16[D*D4];

// ---------------- helpers ----------------------------------------------------
__device__ __forceinline__ uint32_t sptr(const void* p) {
    return (uint32_t)__cvta_generic_to_shared(p);
}
__device__ __forceinline__ void cp16(uint32_t s, const void* g) {
    asm volatile("cp.async.cg.shared.global [%0], [%1], 16;\n" :: "r"(s), "l"(g));
}
__device__ __forceinline__ void cp_commit() {
    asm volatile("cp.async.commit_group;\n");
}
template<int N>
__device__ __forceinline__ void cp_wait() {
    asm volatile("cp.async.wait_group %0;\n" :: "n"(N));
}
__device__ __forceinline__ void mma16816(float* c, const uint32_t* a, const uint32_t* b) {
    asm volatile(
        "mma.sync.aligned.m16n8k16.row.col.f32.bf16.bf16.f32 "
        "{%0,%1,%2,%3}, {%4,%5,%6,%7}, {%8,%9}, {%0,%1,%2,%3};\n"
        : "+f"(c[0]), "+f"(c[1]), "+f"(c[2]), "+f"(c[3])
        : "r"(a[0]), "r"(a[1]), "r"(a[2]), "r"(a[3]), "r"(b[0]), "r"(b[1]));
}
__device__ __forceinline__ void ldsm4(uint32_t* r, uint32_t a) {
    asm volatile("ldmatrix.sync.aligned.m8n8.x4.shared.b16 {%0,%1,%2,%3}, [%4];"
        : "=r"(r[0]), "=r"(r[1]), "=r"(r[2]), "=r"(r[3]) : "r"(a));
}

__device__ __forceinline__ float blockReduce384(float v, float* sdata) {
    int tid = threadIdx.x;
    sdata[tid] = v;
    if (tid < 128) sdata[384 + tid] = 0.f;
    __syncthreads();
    #pragma unroll
    for (int s = 256; s >= 1; s >>= 1) {
        if (tid < s) sdata[tid] += sdata[tid + s];
        __syncthreads();
    }
    float r = sdata[0];
    __syncthreads();
    return r;
}

// ---------------- launch 0: prep + film + per-(b,d) image L2 norm ------------
#define NWQKV (3*D*D)
#define NWO   (D*D)
#define NC1   (D4*D)
#define NC2   (D*D4)
#define NFILM (2*B*D2)
#define PREP_ELEMS (NWQKV + NWO + NC1 + NC2 + QS + B*D + NP + NFILM)
#define PREP_BLOCKS ((PREP_ELEMS + 255) / 256)
__global__ void k_prep(const float* __restrict__ Wq, const float* __restrict__ Wk,
                       const float* __restrict__ Wv, const float* __restrict__ Wo,
                       const float* __restrict__ c1, const float* __restrict__ c2,
                       const float* __restrict__ bq, const float* __restrict__ bk,
                       const float* __restrict__ bv,
                       const int* __restrict__ perm,
                       const float* __restrict__ film,
                       const float* __restrict__ W1, const float* __restrict__ b1,
                       const float* __restrict__ W2, const float* __restrict__ b2,
                       const float* __restrict__ img,
                       bf16* __restrict__ wqkv, bf16* __restrict__ wo,
                       bf16* __restrict__ c1o, bf16* __restrict__ c2o,
                       float* __restrict__ bqkv, float* __restrict__ gx2sq,
                       int* __restrict__ invp,
                       float* __restrict__ gb1, float* __restrict__ gb2,
                       float* __restrict__ gx) {
    __shared__ float sdata[256];
    if (blockIdx.x >= PREP_BLOCKS) {
        // gx part: per-(b,d) L2 norm over NP pixels
        int bd = blockIdx.x - PREP_BLOCKS;
        const float* p = img + (size_t)bd * NP;
        float s = 0.f;
        for (int i = threadIdx.x; i < NP; i += 256) { float v = p[i]; s += v * v; }
        sdata[threadIdx.x] = s; __syncthreads();
        for (int st = 128; st >= 1; st >>= 1) {
            if (threadIdx.x < st) sdata[threadIdx.x] += sdata[threadIdx.x + st];
            __syncthreads();
        }
        if (threadIdx.x == 0) gx[bd] = sqrtf(sdata[0]);
        return;
    }
    int i = blockIdx.x * blockDim.x + threadIdx.x;
    if (i < NWQKV) {
        int seg = i / (D*D), r = i % (D*D);
        const float* W = (seg == 0) ? Wq : (seg == 1) ? Wk : Wv;
        wqkv[i] = __float2bfloat16(W[r]);
        return;
    }
    i -= NWQKV;
    if (i < NWO) { wo[i] = __float2bfloat16(Wo[i]); return; }
    i -= NWO;
    if (i < NC1) { c1o[i] = __float2bfloat16(c1[i]); return; }
    i -= NC1;
    if (i < NC2) { c2o[i] = __float2bfloat16(c2[i]); return; }
    i -= NC2;
    if (i < QS) {
        bqkv[i] = (i < D) ? bq[i] : (i < 2*D) ? bk[i - D] : bv[i - 2*D];
        return;
    }
    i -= QS;
    if (i < B*D) { gx2sq[i] = 0.f; return; }
    i -= B*D;
    if (i < NP) { invp[perm[i]] = i; return; }
    i -= NP;
    if (i < NFILM) {
        int which = i / (B * D2);
        int r = i % (B * D2);
        int b = r / D2, j = r % D2;
        const float* W = which ? W2 : W1;
        const float* bb = which ? b2 : b1;
        const float* f = film + b * FD;
        const float* w = W + (size_t)j * FD;
        float s = 0.f;
        #pragma unroll 8
        for (int q = 0; q < FD; q++) s += f[q] * w[q];
        s += bb[j];
        if (which) gb2[r] = s; else gb1[r] = s;
    }
}

// gmean+coef for GRN2 (input gx2sq needs sqrt)
__global__ void k_gmean_coef(const float* __restrict__ gxsq,
                             const float* __restrict__ gg, const float* __restrict__ gb_,
                             const float* __restrict__ gbmat,
                             float* __restrict__ A, float* __restrict__ C) {
    __shared__ float sdata[512];
    int b = blockIdx.x, d = threadIdx.x;
    float gv = sqrtf(gxsq[b * D + d]);
    float s = blockReduce384(gv, sdata);
    float gm = s / (float)D;
    float nx = gv / (gm + 1e-6f);
    float gamma = gbmat[b * D2 + d];
    float beta  = gbmat[b * D2 + D + d];
    A[b * D + d] = ((1.f + gg[d]) * nx + 1.f) * (1.f + gamma);
    C[b * D + d] = gb_[d] * (1.f + gamma) + beta;
}

// ---------------- launch 1: transpose-gather w/ inline adaLN1 + local gmean --
__global__ void __launch_bounds__(256) k_gather_t(
        const float* __restrict__ img, const int* __restrict__ invp,
        const float* __restrict__ gx,
        const float* __restrict__ gg, const float* __restrict__ gb_,
        const float* __restrict__ gb1,
        bf16* __restrict__ imtok, bf16* __restrict__ xg) {
    __shared__ float tile[64][65];
    __shared__ float sA[64], sC[64];
    __shared__ float sred[256];
    __shared__ int sinv[64];
    int p0 = blockIdx.x * 64, d0 = blockIdx.y * 64, b = blockIdx.z;
    int tid = threadIdx.x;
    // local batch-mean of gx over D dims
    float s = 0.f;
    for (int t = tid; t < D; t += 256) s += gx[b * D + t];
    sred[tid] = s; __syncthreads();
    for (int st = 128; st >= 1; st >>= 1) {
        if (tid < st) sred[tid] += sred[tid + st];
        __syncthreads();
    }
    float gmv = sred[0] * (1.f / (float)D);

    if (tid < 64) sinv[tid] = invp[p0 + tid];
    else if (tid >= 64 && tid < 128) {
        int dl = tid - 64, d = d0 + dl;
        float nx = gx[b * D + d] / (gmv + 1e-6f);
        float gamma = gb1[b * D2 + d];
        float beta  = gb1[b * D2 + D + d];
        sA[dl] = ((1.f + gg[d]) * nx + 1.f) * (1.f + gamma);
        sC[dl] = gb_[d] * (1.f + gamma) + beta;
    }
    #pragma unroll
    for (int l = 0; l < 4; l++) {
        int j = tid + l * 256;
        int i = j >> 4, q = (j & 15) * 4;
        float4 v = *(const float4*)(img + ((size_t)(b * D + d0 + i)) * NP + p0 + q);
        tile[i][q + 0] = v.x; tile[i][q + 1] = v.y;
        tile[i][q + 2] = v.z; tile[i][q + 3] = v.w;
    }
    __syncthreads();
    #pragma unroll
    for (int l = 0; l < 4; l++) {
        int j = tid + l * 256;
        int jp = j >> 4, i4 = (j & 15) * 4;
        int t = sinv[jp];
        size_t o = ((size_t)(b * NP + t)) * D + d0 + i4;
        float vv[4], xv[4];
        #pragma unroll
        for (int r = 0; r < 4; r++) {
            vv[r] = tile[i4 + r][jp];
            xv[r] = sA[i4 + r] * vv[r] + sC[i4 + r];
        }
        *(bf162*)&imtok[o] = __floats2bfloat162_rn(vv[0], vv[1]);
        *(bf162*)&imtok[o + 2] = __floats2bfloat162_rn(vv[2], vv[3]);
        *(bf162*)&xg[o] = __floats2bfloat162_rn(xv[0], xv[1]);
        *(bf162*)&xg[o + 2] = __floats2bfloat162_rn(xv[2], xv[3]);
    }
}

// ---------------- bf16 tensor-core GEMM (BK=64, 3-stage, XOR swizzle) --------
#define STG 3
#define STAGE_B 16384
#define GEMM_SMEM (STG * 2 * STAGE_B)
template<bool SILU, bool RES, bool GX2>
__global__ void __launch_bounds__(256, 2) gemm_mma(
        const bf16* __restrict__ A, const bf16* __restrict__ W,
        const float* __restrict__ bias, const bf16* __restrict__ res,
        const float* __restrict__ scale, bf16* __restrict__ C,
        float* __restrict__ gx2sq, int M, int N, int K) {
    extern __shared__ char smem[];
    uint32_t sbA = sptr(smem);
    uint32_t sbW = sbA + STG * STAGE_B;
    int tid = threadIdx.x;
    int m0 = blockIdx.y * 128, n0 = blockIdx.x * 128;
    int lane = tid & 31, warp = tid >> 5;
    int g = lane >> 2, tg = lane & 3;
    int wm = warp >> 2, wn = warp & 3;
    int lane8 = lane & 7, laneg = lane >> 3;

    uint32_t aByte[4], aMask[4];
    #pragma unroll
    for (int im = 0; im < 4; im++) {
        int row = wm * 64 + im * 16 + lane8 + (laneg & 1) * 8;
        aByte[im] = (uint32_t)row * 128;
        aMask[im] = (uint32_t)(row & 7);
    }
    uint32_t bByte[2], bMask[2];
    #pragma unroll
    for (int p = 0; p < 2; p++) {
        int row = wn * 32 + p * 16 + lane8 + (laneg >> 1) * 8;
        bByte[p] = (uint32_t)row * 128;
        bMask[p] = (uint32_t)(row & 7);
    }
    uint32_t cA = (uint32_t)(laneg >> 1);
    uint32_t cB = (uint32_t)(laneg & 1);

    float acc[4][4][4];
    #pragma unroll
    for (int i = 0; i < 4; i++)
        #pragma unroll
        for (int j = 0; j < 4; j++)
            #pragma unroll
            for (int p = 0; p < 4; p++) acc[i][j][p] = 0.f;

    int nt = K / 64;
    auto issue = [&](int t) {
        if (t < nt) {
            int s = t % STG;
            int k0 = t * 64;
            uint32_t ab = sbA + s * STAGE_B;
            uint32_t wb = sbW + s * STAGE_B;
            #pragma unroll
            for (int l = 0; l < 4; l++) {
                int j = tid + l * 256;
                uint32_t row = (uint32_t)(j >> 3), q8 = (uint32_t)(j & 7);
                uint32_t sw = (q8 ^ (row & 7)) << 4;
                cp16(ab + row * 128 + sw, A + (size_t)(m0 + (int)row) * K + k0 + (int)q8 * 8);
                cp16(wb + row * 128 + sw, W + (size_t)(n0 + (int)row) * K + k0 + (int)q8 * 8);
            }
        }
        cp_commit();
    };

    issue(0);
    issue(1);
    for (int t = 0; t < nt; t++) {
        issue(t + 2);
        cp_wait<2>();
        __syncthreads();
        int s = t % STG;
        uint32_t aBase = sbA + s * STAGE_B;
        uint32_t wBase = sbW + s * STAGE_B;
        #pragma unroll
        for (int kk = 0; kk < 64; kk += 16) {
            uint32_t kc = (uint32_t)(kk >> 3);
            uint32_t af[4][4], bf[2][4];
            #pragma unroll
            for (int im = 0; im < 4; im++)
                ldsm4(af[im], aBase + aByte[im] + (((kc + cA) ^ aMask[im]) << 4));
            #pragma unroll
            for (int p = 0; p < 2; p++)
                ldsm4(bf[p], wBase + bByte[p] + (((kc + cB) ^ bMask[p]) << 4));
            #pragma unroll
            for (int im = 0; im < 4; im++)
                #pragma unroll
                for (int in = 0; in < 4; in++)
                    mma16816(acc[im][in], af[im], &bf[in >> 1][(in & 1) * 2]);
        }
        __syncthreads();
    }

    // epilogue
    float sums[4][2];
    if (GX2) {
        #pragma unroll
        for (int in = 0; in < 4; in++) { sums[in][0] = 0.f; sums[in][1] = 0.f; }
    }
    #pragma unroll
    for (int im = 0; im < 4; im++) {
        int r0 = m0 + wm * 64 + im * 16 + g;
        #pragma unroll
        for (int in = 0; in < 4; in++) {
            int c = n0 + wn * 32 + in * 8 + tg * 2;
            float b0 = bias[c], b1 = bias[c + 1];
            float v00 = acc[im][in][0] + b0, v01 = acc[im][in][1] + b1;
            float v10 = acc[im][in][2] + b0, v11 = acc[im][in][3] + b1;
            if (SILU) {
                v00 = v00 / (1.f + expf(-v00)); v01 = v01 / (1.f + expf(-v01));
                v10 = v10 / (1.f + expf(-v10)); v11 = v11 / (1.f + expf(-v11));
            }
            if (RES) {
                float s0 = scale[c], s1 = scale[c + 1];
                bf162 ra = *(const bf162*)&res[(size_t)r0 * N + c];
                bf162 rb = *(const bf162*)&res[(size_t)(r0 + 8) * N + c];
                v00 = __bfloat162float(ra.x) + v00 * s0;
                v01 = __bfloat162float(ra.y) + v01 * s1;
                v10 = __bfloat162float(rb.x) + v10 * s0;
                v11 = __bfloat162float(rb.y) + v11 * s1;
            }
            if (GX2) {
                sums[in][0] += v00 * v00 + v10 * v10;
                sums[in][1] += v01 * v01 + v11 * v11;
            }
            *(bf162*)&C[(size_t)r0 * N + c] = __floats2bfloat162_rn(v00, v01);
            *(bf162*)&C[(size_t)(r0 + 8) * N + c] = __floats2bfloat162_rn(v10, v11);
        }
    }
    if (GX2) {
        #pragma unroll
        for (int off = 4; off <= 16; off <<= 1) {
            #pragma unroll
            for (int in = 0; in < 4; in++) {
                sums[in][0] += __shfl_xor_sync(0xffffffff, sums[in][0], off);
                sums[in][1] += __shfl_xor_sync(0xffffffff, sums[in][1], off);
            }
        }
        if (lane < 4) {
            int b = m0 >> 12;
            #pragma unroll
            for (int in = 0; in < 4; in++) {
                int c = n0 + wn * 32 + in * 8 + tg * 2;
                atomicAdd(&gx2sq[b * D + c], sums[in][0]);
                atomicAdd(&gx2sq[b * D + c + 1], sums[in][1]);
            }
        }
    }
}

// per-token LayerNorm over D then elu+1, bf162-vectorized; y: 0=q, 1=k
__global__ void __launch_bounds__(256) k_lnelu(bf16* __restrict__ X,
        const float* __restrict__ gq, const float* __restrict__ bq_,
        const float* __restrict__ gk, const float* __restrict__ bk_) {
    int warp = threadIdx.x >> 5, lane = threadIdx.x & 31;
    int t = blockIdx.x * 8 + warp;
    int seg = blockIdx.y;
    const float* gam = seg ? gk : gq;
    const float* bet = seg ? bk_ : bq_;
    size_t base = (size_t)t * QS + seg * D;
    float2 v[6];
    float s = 0.f, s2 = 0.f;
    #pragma unroll
    for (int j = 0; j < 6; j++) {
        bf162 h = *(const bf162*)&X[base + j * 64 + lane * 2];
        v[j].x = __bfloat162float(h.x);
        v[j].y = __bfloat162float(h.y);
        s += v[j].x + v[j].y;
        s2 += v[j].x * v[j].x + v[j].y * v[j].y;
    }
    #pragma unroll
    for (int o = 16; o >= 1; o >>= 1) {
        s  += __shfl_xor_sync(0xffffffff, s, o);
        s2 += __shfl_xor_sync(0xffffffff, s2, o);
    }
    float mean = s / (float)D;
    float var = s2 / (float)D - mean * mean;
    float rstd = rsqrtf(var + 1e-5f);
    #pragma unroll
    for (int j = 0; j < 6; j++) {
        int d = j * 64 + lane * 2;
        float y0 = (v[j].x - mean) * rstd * gam[d] + bet[d];
        float y1 = (v[j].y - mean) * rstd * gam[d + 1] + bet[d + 1];
        y0 = (y0 > 0.f) ? (y0 + 1.f) : expf(y0);
        y1 = (y1 > 0.f) ? (y1 + 1.f) : expf(y1);
        *(bf162*)&X[base + d] = __floats2bfloat162_rn(y0, y1);
    }
}

// kv partial: kvp[sp][bh][d*48+e] = sum over 512 tokens of k[t,d]*v[t,e]
__global__ void __launch_bounds__(288) k_attn_kv(const bf16* __restrict__ qkv,
                                                 float* __restrict__ kvp,
                                                 float* __restrict__ ksp) {
    int bh = blockIdx.x, sp = blockIdx.y;
    int h = bh & (NH - 1), bc = bh >> 3;
    int tid = threadIdx.x;
    int d = tid % 48, eg = tid / 48;
    __shared__ float sk[16][48];
    __shared__ float sv[16][48];
    float acc[8];
    #pragma unroll
    for (int p = 0; p < 8; p++) acc[p] = 0.f;
    float ks = 0.f;

    for (int c = 0; c < (GS / KVSPLIT) / 16; c++) {
        int tt0 = bc * GS + sp * (GS / KVSPLIT) + c * 16;
        #pragma unroll
        for (int r = 0; r < 3; r++) {
            int ti = eg + r * 6;
            if (ti < 16) {
                size_t row = (size_t)(tt0 + ti) * QS + h * HD + d;
                sk[ti][d] = __bfloat162float(qkv[row + D]);
                sv[ti][d] = __bfloat162float(qkv[row + 2 * D]);
            }
        }
        __syncthreads();
        #pragma unroll
        for (int ti = 0; ti < 16; ti++) {
            float kval = sk[ti][d];
            const float* vp = &sv[ti][eg * 8];
            float4 v0 = *(const float4*)vp;
            float4 v1 = *(const float4*)(vp + 4);
            acc[0] += kval * v0.x; acc[1] += kval * v0.y;
            acc[2] += kval * v0.z; acc[3] += kval * v0.w;
            acc[4] += kval * v1.x; acc[5] += kval * v1.y;
            acc[6] += kval * v1.z; acc[7] += kval * v1.w;
            if (tid < 48) ks += kval;
        }
        __syncthreads();
    }
    float* out = kvp + ((size_t)(sp * (B*NC*NH) + bh)) * HD * HD + d * HD + eg * 8;
    *(float4*)out = make_float4(acc[0], acc[1], acc[2], acc[3]);
    *(float4*)(out + 4) = make_float4(acc[4], acc[5], acc[6], acc[7]);
    if (tid < 48) ksp[(sp * (B*NC*NH) + bh) * HD + tid] = ks;
}

// apply: out[t,h,e] = (q.kv[:,e]) / (q.ksum + 1e-8); 384 threads = 64 tok x 6 eg
__global__ void __launch_bounds__(384) k_attn_apply(const bf16* __restrict__ qkv,
                                                    const float* __restrict__ kvp,
                                                    const float* __restrict__ ksp,
                                                    bf16* __restrict__ out) {
    int bh = blockIdx.x, tile = blockIdx.y;
    int h = bh & (NH - 1), bc = bh >> 3;
    int tid = threadIdx.x;
    __shared__ float skv[48 * 48];
    __shared__ float sks[48];
    __shared__ float sq[64][49];

    const float* kv0 = kvp + (size_t)bh * HD * HD;
    const float* kv1 = kvp + (size_t)(B*NC*NH + bh) * HD * HD;
    for (int i = tid; i < HD * HD; i += 384) skv[i] = kv0[i] + kv1[i];
    if (tid < 48) sks[tid] = ksp[bh * HD + tid] + ksp[(B*NC*NH + bh) * HD + tid];

    int t0 = bc * GS + tile * 64;
    int dd = tid % 48, tq = tid / 48;
    #pragma unroll
    for (int r = 0; r < 8; r++) {
        int lt = tq + r * 8;
        sq[lt][dd] = __bfloat162float(qkv[(size_t)(t0 + lt) * QS + h * HD + dd]);
    }
    __syncthreads();

    int g = tid % 6, lt = tid / 6;
    float acc[8];
    #pragma unroll
    for (int p = 0; p < 8; p++) acc[p] = 0.f;
    float den = 0.f;
    #pragma unroll 8
    for (int dl = 0; dl < 48; dl++) {
        float qq = sq[lt][dl];
        const float* kp = &skv[dl * 48 + g * 8];
        float4 a = *(const float4*)kp;
        float4 b = *(const float4*)(kp + 4);
        acc[0] += qq * a.x; acc[1] += qq * a.y;
        acc[2] += qq * a.z; acc[3] += qq * a.w;
        acc[4] += qq * b.x; acc[5] += qq * b.y;
        acc[6] += qq * b.z; acc[7] += qq * b.w;
        den += qq * sks[dl];
    }
    float rden = 1.f / (den + 1e-8f);
    bf16* op = out + (size_t)(t0 + lt) * D + h * HD + g * 8;
    *(bf162*)(op + 0) = __floats2bfloat162_rn(acc[0] * rden, acc[1] * rden);
    *(bf162*)(op + 2) = __floats2bfloat162_rn(acc[2] * rden, acc[3] * rden);
    *(bf162*)(op + 4) = __floats2bfloat162_rn(acc[4] * rden, acc[5] * rden);
    *(bf162*)(op + 6) = __floats2bfloat162_rn(acc[6] * rden, acc[7] * rden);
}

// x2 = A2[b,d]*wi + C2[b,d]; 4 elems/thread
__global__ void k_x2(const bf16* __restrict__ wi, const float* __restrict__ A,
                     const float* __restrict__ C, bf16* __restrict__ x2) {
    size_t e = ((size_t)blockIdx.x * 256 + threadIdx.x) * 4;
    int t = (int)(e / D), d = (int)(e % D);
    int b = t >> 12;
    bf162 w01 = *(const bf162*)&wi[e];
    bf162 w23 = *(const bf162*)&wi[e + 2];
    const float* Ab = A + b * D + d;
    const float* Cb = C + b * D + d;
    float r0 = Ab[0] * __bfloat162float(w01.x) + Cb[0];
    float r1 = Ab[1] * __bfloat162float(w01.y) + Cb[1];
    float r2 = Ab[2] * __bfloat162float(w23.x) + Cb[2];
    float r3 = Ab[3] * __bfloat162float(w23.y) + Cb[3];
    bf162 o01 = __floats2bfloat162_rn(r0, r1);
    bf162 o23 = __floats2bfloat162_rn(r2, r3);
    uint2 u; u.x = *(uint32_t*)&o01; u.y = *(uint32_t*)&o23;
    *(uint2*)&x2[e] = u;
}

// out[b,d,pix] = image[b,d,pix] + wif[token(pix), d] * final_scalar[d]
__global__ void __launch_bounds__(256) k_final_t(
        const float* __restrict__ img, const bf16* __restrict__ wif,
        const int* __restrict__ invp, const float* __restrict__ fs,
        float* __restrict__ out) {
    __shared__ float tile[64][65];
    __shared__ int sinv[64];
    int p0 = blockIdx.x * 64, d0 = blockIdx.y * 64, b = blockIdx.z;
    int tid = threadIdx.x;
    if (tid < 64) sinv[tid] = invp[p0 + tid];
    __syncthreads();
    #pragma unroll
    for (int l = 0; l < 4; l++) {
        int j = tid + l * 256;
        int jp = j >> 4, i4 = (j & 15) * 4;
        int t = sinv[jp];
        const bf16* src = wif + ((size_t)(b * NP + t)) * D + d0 + i4;
        bf162 v01 = *(const bf162*)src;
        bf162 v23 = *(const bf162*)(src + 2);
        tile[i4 + 0][jp] = __bfloat162float(v01.x);
        tile[i4 + 1][jp] = __bfloat162float(v01.y);
        tile[i4 + 2][jp] = __bfloat162float(v23.x);
        tile[i4 + 3][jp] = __bfloat162float(v23.y);
    }
    __syncthreads();
    #pragma unroll
    for (int l = 0; l < 4; l++) {
        int j = tid + l * 256;
        int i = j >> 4, q = (j & 15) * 4;
        size_t o = ((size_t)(b * D + d0 + i)) * NP + p0 + q;
        float4 im4 = *(const float4*)(img + o);
        float f = fs[d0 + i];
        float4 r;
        r.x = im4.x + tile[i][q + 0] * f;
        r.y = im4.y + tile[i][q + 1] * f;
        r.z = im4.z + tile[i][q + 2] * f;
        r.w = im4.w + tile[i][q + 3] * f;
        *(float4*)(out + o) = r;
    }
}

// ---------------- driver ----------------------------------------------------
extern "C" void kernel_launch(void* const* d_in, const int* in_sizes, int n_in,
                              void* d_out, int out_size) {
    const float* image  = (const float*)d_in[0];
    const float* film   = (const float*)d_in[1];
    const int*   perm   = (const int*)d_in[2];
    const float* Wq = (const float*)d_in[3];  const float* bq = (const float*)d_in[4];
    const float* Wk = (const float*)d_in[5];  const float* bk = (const float*)d_in[6];
    const float* Wv = (const float*)d_in[7];  const float* bv = (const float*)d_in[8];
    const float* Wo = (const float*)d_in[9];  const float* bo = (const float*)d_in[10];
    const float* lnq_g = (const float*)d_in[11]; const float* lnq_b = (const float*)d_in[12];
    const float* lnk_g = (const float*)d_in[13]; const float* lnk_b = (const float*)d_in[14];
    const float* ada1_W = (const float*)d_in[15]; const float* ada1_b = (const float*)d_in[16];
    const float* grn1_g = (const float*)d_in[17]; const float* grn1_b = (const float*)d_in[18];
    const float* ada2_W = (const float*)d_in[19]; const float* ada2_b = (const float*)d_in[20];
    const float* grn2_g = (const float*)d_in[21]; const float* grn2_b = (const float*)d_in[22];
    const float* conv1_W = (const float*)d_in[23]; const float* conv1_b = (const float*)d_in[24];
    const float* conv2_W = (const float*)d_in[25]; const float* conv2_b = (const float*)d_in[26];
    const float* cs  = (const float*)d_in[27];
    const float* ffs = (const float*)d_in[28];
    const float* fs  = (const float*)d_in[29];
    float* out = (float*)d_out;

    float *p_gb1, *p_gb2, *p_gx, *p_A2, *p_C2, *p_gx2sq;
    int* p_invp;
    float *p_kv, *p_ks, *p_bqkv;
    bf16 *p_imtok16, *p_wi16, *p_wif16;
    bf16 *p_qkv16, *p_xg16, *p_att16, *p_x216, *p_h116;
    bf16 *p_wqkv16, *p_wo16, *p_c1w16, *p_c2w16;
    cudaGetSymbolAddress((void**)&p_gb1, g_gb1);
    cudaGetSymbolAddress((void**)&p_gb2, g_gb2);
    cudaGetSymbolAddress((void**)&p_gx, g_gx);
    cudaGetSymbolAddress((void**)&p_A2, g_A2);
    cudaGetSymbolAddress((void**)&p_C2, g_C2);
    cudaGetSymbolAddress((void**)&p_gx2sq, g_gx2sq);
    cudaGetSymbolAddress((void**)&p_invp, g_invp);
    cudaGetSymbolAddress((void**)&p_kv, g_kv);
    cudaGetSymbolAddress((void**)&p_ks, g_ks);
    cudaGetSymbolAddress((void**)&p_bqkv, g_bqkv);
    cudaGetSymbolAddress((void**)&p_imtok16, g_imtok16);
    cudaGetSymbolAddress((void**)&p_wi16, g_wi16);
    cudaGetSymbolAddress((void**)&p_wif16, g_wif16);
    cudaGetSymbolAddress((void**)&p_qkv16, g_qkv16);
    cudaGetSymbolAddress((void**)&p_xg16, g_xg16);
    cudaGetSymbolAddress((void**)&p_att16, g_att16);
    cudaGetSymbolAddress((void**)&p_x216, g_x216);
    cudaGetSymbolAddress((void**)&p_h116, g_h116);
    cudaGetSymbolAddress((void**)&p_wqkv16, g_wqkv16);
    cudaGetSymbolAddress((void**)&p_wo16, g_wo16);
    cudaGetSymbolAddress((void**)&p_c1w16, g_c1w16);
    cudaGetSymbolAddress((void**)&p_c2w16, g_c2w16);

    cudaFuncSetAttribute((const void*)gemm_mma<false,false,false>,
                         cudaFuncAttributeMaxDynamicSharedMemorySize, GEMM_SMEM);
    cudaFuncSetAttribute((const void*)gemm_mma<false,true,true>,
                         cudaFuncAttributeMaxDynamicSharedMemorySize, GEMM_SMEM);
    cudaFuncSetAttribute((const void*)gemm_mma<true,false,false>,
                         cudaFuncAttributeMaxDynamicSharedMemorySize, GEMM_SMEM);
    cudaFuncSetAttribute((const void*)gemm_mma<false,true,false>,
                         cudaFuncAttributeMaxDynamicSharedMemorySize, GEMM_SMEM);

    // launch 0: all prep + film + gx
    k_prep<<<PREP_BLOCKS + B * D, 256>>>(Wq, Wk, Wv, Wo, conv1_W, conv2_W,
        bq, bk, bv, perm, film, ada1_W, ada1_b, ada2_W, ada2_b, image,
        p_wqkv16, p_wo16, p_c1w16, p_c2w16,
        p_bqkv, p_gx2sq, p_invp, p_gb1, p_gb2, p_gx);
    // launch 1: gather with inline adaLN1 coefficients + local gmean
    k_gather_t<<<dim3(NP/64, D/64, B), 256>>>(image, p_invp, p_gx,
        grn1_g, grn1_b, p_gb1, p_imtok16, p_xg16);
    // launch 2: packed QKV GEMM
    gemm_mma<false,false,false><<<dim3(QS/128, T/128), 256, GEMM_SMEM>>>(
        p_xg16, p_wqkv16, p_bqkv, nullptr, nullptr, p_qkv16, nullptr, T, QS, D);

    k_lnelu<<<dim3(T/8, 2), 256>>>(p_qkv16, lnq_g, lnq_b, lnk_g, lnk_b);

    k_attn_kv<<<dim3(B * NC * NH, KVSPLIT), 288>>>(p_qkv16, p_kv, p_ks);
    k_attn_apply<<<dim3(B * NC * NH, 16), 384>>>(p_qkv16, p_kv, p_ks, p_att16);

    // wi = imtok + (attn@Wo^T + bo) * cs ; also gx2sq += wi^2
    gemm_mma<false,true,true><<<dim3(3, T/128), 256, GEMM_SMEM>>>(
        p_att16, p_wo16, bo, p_imtok16, cs, p_wi16, p_gx2sq, T, D, D);

    k_gmean_coef<<<B, 384>>>(p_gx2sq, grn2_g, grn2_b, p_gb2, p_A2, p_C2);
    k_x2<<<(int)(((size_t)T*D) / 1024), 256>>>(p_wi16, p_A2, p_C2, p_x216);

    // h1 = silu(x2 @ conv1^T + b1)
    gemm_mma<true,false,false><<<dim3(12, T/128), 256, GEMM_SMEM>>>(
        p_x216, p_c1w16, conv1_b, nullptr, nullptr, p_h116, nullptr, T, D4, D);
    // wif = wi + (h1 @ conv2^T + b2) * ffs
    gemm_mma<false,true,false><<<dim3(3, T/128), 256, GEMM_SMEM>>>(
        p_h116, p_c2w16, conv2_b, p_wi16, ffs, p_wif16, nullptr, T, D, D4);

    k_final_t<<<dim3(NP/64, D/64, B), 256>>>(image, p_wif16, p_invp, fs, out);
}

// round 15
// speedup vs baseline: 1.3431x; 1.0103x over previous
#include <cuda_runtime.h>
#include <cuda_bf16.h>
#include <math.h>
#include <stdint.h>

#define B   8
#define D   384
#define FD  256
#define NP  4096
#define NH  8
#define NC  4
#define HD  48
#define GS  1024
#define T   (B*NP)     /* 32768 tokens */
#define D4  1536
#define D2  768
#define QS  1152       /* packed qkv row stride */
#define KVSPLIT 2

typedef __nv_bfloat16 bf16;
typedef __nv_bfloat162 bf162;

// ---------------- scratch (device globals) ----------------------------------
static __device__ float g_gb1[B*D2];
static __device__ float g_gb2[B*D2];
static __device__ float g_gx[B*D];
static __device__ float g_A2[B*D];
static __device__ float g_C2[B*D];
static __device__ float g_gx2sq[B*D];
static __device__ int   g_invp[NP];
static __device__ float g_kv[KVSPLIT*B*NC*NH*HD*HD];
static __device__ float g_ks[KVSPLIT*B*NC*NH*HD];
static __device__ float g_bqkv[QS];
static __device__ float g_pgq[2*D];       // interleaved {g,b} for q LN
static __device__ float g_pgk[2*D];       // interleaved {g,b} for k LN
// bf16 activations
static __device__ bf16  g_imtok16[(size_t)T*D];
static __device__ bf16  g_wi16[(size_t)T*D];
static __device__ bf16  g_wif16[(size_t)T*D];
static __device__ bf16  g_qkv16[(size_t)T*QS];
static __device__ bf16  g_xg16[(size_t)T*D];
static __device__ bf16  g_att16[(size_t)T*D];
static __device__ bf16  g_x216[(size_t)T*D];
static __device__ bf16  g_h116[(size_t)T*D4];
// bf16 weights
static __device__ bf16  g_wqkv16[QS*D];
static __device__ bf16  g_wo16[D*D];
static __device__ bf16  g_c1w16[D4*D];
static __device__ bf16  g_c2w16[D*D4];

// ---------------- helpers ----------------------------------------------------
__device__ __forceinline__ uint32_t sptr(const void* p) {
    return (uint32_t)__cvta_generic_to_shared(p);
}
__device__ __forceinline__ void cp16(uint32_t s, const void* g) {
    asm volatile("cp.async.cg.shared.global [%0], [%1], 16;\n" :: "r"(s), "l"(g));
}
__device__ __forceinline__ void cp_commit() {
    asm volatile("cp.async.commit_group;\n");
}
template<int N>
__device__ __forceinline__ void cp_wait() {
    asm volatile("cp.async.wait_group %0;\n" :: "n"(N));
}
__device__ __forceinline__ void mma16816(float* c, const uint32_t* a, const uint32_t* b) {
    asm volatile(
        "mma.sync.aligned.m16n8k16.row.col.f32.bf16.bf16.f32 "
        "{%0,%1,%2,%3}, {%4,%5,%6,%7}, {%8,%9}, {%0,%1,%2,%3};\n"
        : "+f"(c[0]), "+f"(c[1]), "+f"(c[2]), "+f"(c[3])
        : "r"(a[0]), "r"(a[1]), "r"(a[2]), "r"(a[3]), "r"(b[0]), "r"(b[1]));
}
__device__ __forceinline__ void ldsm4(uint32_t* r, uint32_t a) {
    asm volatile("ldmatrix.sync.aligned.m8n8.x4.shared.b16 {%0,%1,%2,%3}, [%4];"
        : "=r"(r[0]), "=r"(r[1]), "=r"(r[2]), "=r"(r[3]) : "r"(a));
}

__device__ __forceinline__ float blockReduce384(float v, float* sdata) {
    int tid = threadIdx.x;
    sdata[tid] = v;
    if (tid < 128) sdata[384 + tid] = 0.f;
    __syncthreads();
    #pragma unroll
    for (int s = 256; s >= 1; s >>= 1) {
        if (tid < s) sdata[tid] += sdata[tid + s];
        __syncthreads();
    }
    float r = sdata[0];
    __syncthreads();
    return r;
}

// ---------------- launch 0: prep + film + per-(b,d) image L2 norm ------------
#define NWQKV (3*D*D)
#define NWO   (D*D)
#define NC1   (D4*D)
#define NC2   (D*D4)
#define NFILM (2*B*D2)
#define NPACK (2*D)
#define PREP_ELEMS (NWQKV + NWO + NC1 + NC2 + QS + B*D + NP + NPACK + NFILM)
#define PREP_BLOCKS ((PREP_ELEMS + 255) / 256)
__global__ void k_prep(const float* __restrict__ Wq, const float* __restrict__ Wk,
                       const float* __restrict__ Wv, const float* __restrict__ Wo,
                       const float* __restrict__ c1, const float* __restrict__ c2,
                       const float* __restrict__ bq, const float* __restrict__ bk,
                       const float* __restrict__ bv,
                       const int* __restrict__ perm,
                       const float* __restrict__ film,
                       const float* __restrict__ W1, const float* __restrict__ b1,
                       const float* __restrict__ W2, const float* __restrict__ b2,
                       const float* __restrict__ lnqg, const float* __restrict__ lnqb,
                       const float* __restrict__ lnkg, const float* __restrict__ lnkb,
                       const float* __restrict__ img,
                       bf16* __restrict__ wqkv, bf16* __restrict__ wo,
                       bf16* __restrict__ c1o, bf16* __restrict__ c2o,
                       float* __restrict__ bqkv, float* __restrict__ gx2sq,
                       int* __restrict__ invp,
                       float* __restrict__ gb1, float* __restrict__ gb2,
                       float* __restrict__ pgq, float* __restrict__ pgk,
                       float* __restrict__ gx) {
    __shared__ float sdata[256];
    if (blockIdx.x >= PREP_BLOCKS) {
        int bd = blockIdx.x - PREP_BLOCKS;
        const float* p = img + (size_t)bd * NP;
        float s = 0.f;
        for (int i = threadIdx.x; i < NP; i += 256) { float v = p[i]; s += v * v; }
        sdata[threadIdx.x] = s; __syncthreads();
        for (int st = 128; st >= 1; st >>= 1) {
            if (threadIdx.x < st) sdata[threadIdx.x] += sdata[threadIdx.x + st];
            __syncthreads();
        }
        if (threadIdx.x == 0) gx[bd] = sqrtf(sdata[0]);
        return;
    }
    int i = blockIdx.x * blockDim.x + threadIdx.x;
    if (i < NWQKV) {
        int seg = i / (D*D), r = i % (D*D);
        const float* W = (seg == 0) ? Wq : (seg == 1) ? Wk : Wv;
        wqkv[i] = __float2bfloat16(W[r]);
        return;
    }
    i -= NWQKV;
    if (i < NWO) { wo[i] = __float2bfloat16(Wo[i]); return; }
    i -= NWO;
    if (i < NC1) { c1o[i] = __float2bfloat16(c1[i]); return; }
    i -= NC1;
    if (i < NC2) { c2o[i] = __float2bfloat16(c2[i]); return; }
    i -= NC2;
    if (i < QS) {
        bqkv[i] = (i < D) ? bq[i] : (i < 2*D) ? bk[i - D] : bv[i - 2*D];
        return;
    }
    i -= QS;
    if (i < B*D) { gx2sq[i] = 0.f; return; }
    i -= B*D;
    if (i < NP) { invp[perm[i]] = i; return; }
    i -= NP;
    if (i < NPACK) {
        int tbl = i / D, d = i % D;
        if (tbl == 0) { pgq[2*d] = lnqg[d]; pgq[2*d+1] = lnqb[d]; }
        else          { pgk[2*d] = lnkg[d]; pgk[2*d+1] = lnkb[d]; }
        return;
    }
    i -= NPACK;
    if (i < NFILM) {
        int which = i / (B * D2);
        int r = i % (B * D2);
        int b = r / D2, j = r % D2;
        const float* W = which ? W2 : W1;
        const float* bb = which ? b2 : b1;
        const float* f = film + b * FD;
        const float* w = W + (size_t)j * FD;
        float s = 0.f;
        #pragma unroll 8
        for (int q = 0; q < FD; q++) s += f[q] * w[q];
        s += bb[j];
        if (which) gb2[r] = s; else gb1[r] = s;
    }
}

// gmean+coef for GRN2 (input gx2sq needs sqrt)
__global__ void k_gmean_coef(const float* __restrict__ gxsq,
                             const float* __restrict__ gg, const float* __restrict__ gb_,
                             const float* __restrict__ gbmat,
                             float* __restrict__ A, float* __restrict__ C) {
    __shared__ float sdata[512];
    int b = blockIdx.x, d = threadIdx.x;
    float gv = sqrtf(gxsq[b * D + d]);
    float s = blockReduce384(gv, sdata);
    float gm = s / (float)D;
    float nx = gv / (gm + 1e-6f);
    float gamma = gbmat[b * D2 + d];
    float beta  = gbmat[b * D2 + D + d];
    A[b * D + d] = ((1.f + gg[d]) * nx + 1.f) * (1.f + gamma);
    C[b * D + d] = gb_[d] * (1.f + gamma) + beta;
}

// ---------------- launch 1: transpose-gather w/ inline adaLN1 + local gmean --
__global__ void __launch_bounds__(256) k_gather_t(
        const float* __restrict__ img, const int* __restrict__ invp,
        const float* __restrict__ gx,
        const float* __restrict__ gg, const float* __restrict__ gb_,
        const float* __restrict__ gb1,
        bf16* __restrict__ imtok, bf16* __restrict__ xg) {
    __shared__ float tile[64][65];
    __shared__ float sA[64], sC[64];
    __shared__ float sred[256];
    __shared__ int sinv[64];
    int p0 = blockIdx.x * 64, d0 = blockIdx.y * 64, b = blockIdx.z;
    int tid = threadIdx.x;
    float s = 0.f;
    for (int t = tid; t < D; t += 256) s += gx[b * D + t];
    sred[tid] = s; __syncthreads();
    for (int st = 128; st >= 1; st >>= 1) {
        if (tid < st) sred[tid] += sred[tid + st];
        __syncthreads();
    }
    float gmv = sred[0] * (1.f / (float)D);

    if (tid < 64) sinv[tid] = invp[p0 + tid];
    else if (tid >= 64 && tid < 128) {
        int dl = tid - 64, d = d0 + dl;
        float nx = gx[b * D + d] / (gmv + 1e-6f);
        float gamma = gb1[b * D2 + d];
        float beta  = gb1[b * D2 + D + d];
        sA[dl] = ((1.f + gg[d]) * nx + 1.f) * (1.f + gamma);
        sC[dl] = gb_[d] * (1.f + gamma) + beta;
    }
    #pragma unroll
    for (int l = 0; l < 4; l++) {
        int j = tid + l * 256;
        int i = j >> 4, q = (j & 15) * 4;
        float4 v = *(const float4*)(img + ((size_t)(b * D + d0 + i)) * NP + p0 + q);
        tile[i][q + 0] = v.x; tile[i][q + 1] = v.y;
        tile[i][q + 2] = v.z; tile[i][q + 3] = v.w;
    }
    __syncthreads();
    #pragma unroll
    for (int l = 0; l < 4; l++) {
        int j = tid + l * 256;
        int jp = j >> 4, i4 = (j & 15) * 4;
        int t = sinv[jp];
        size_t o = ((size_t)(b * NP + t)) * D + d0 + i4;
        float vv[4], xv[4];
        #pragma unroll
        for (int r = 0; r < 4; r++) {
            vv[r] = tile[i4 + r][jp];
            xv[r] = sA[i4 + r] * vv[r] + sC[i4 + r];
        }
        *(bf162*)&imtok[o] = __floats2bfloat162_rn(vv[0], vv[1]);
        *(bf162*)&imtok[o + 2] = __floats2bfloat162_rn(vv[2], vv[3]);
        *(bf162*)&xg[o] = __floats2bfloat162_rn(xv[0], xv[1]);
        *(bf162*)&xg[o + 2] = __floats2bfloat162_rn(xv[2], xv[3]);
    }
}

// ---------------- bf16 tensor-core GEMM (BK=64, 3-stage, XOR swizzle) --------
#define STG 3
#define STAGE_B 16384
#define GEMM_SMEM (STG * 2 * STAGE_B)
template<bool SILU, bool RES, bool GX2>
__global__ void __launch_bounds__(256, 2) gemm_mma(
        const bf16* __restrict__ A, const bf16* __restrict__ W,
        const float* __restrict__ bias, const bf16* __restrict__ res,
        const float* __restrict__ scale, bf16* __restrict__ C,
        float* __restrict__ gx2sq, int M, int N, int K) {
    extern __shared__ char smem[];
    uint32_t sbA = sptr(smem);
    uint32_t sbW = sbA + STG * STAGE_B;
    int tid = threadIdx.x;
    int m0 = blockIdx.y * 128, n0 = blockIdx.x * 128;
    int lane = tid & 31, warp = tid >> 5;
    int g = lane >> 2, tg = lane & 3;
    int wm = warp >> 2, wn = warp & 3;
    int lane8 = lane & 7, laneg = lane >> 3;

    uint32_t aByte[4], aMask[4];
    #pragma unroll
    for (int im = 0; im < 4; im++) {
        int row = wm * 64 + im * 16 + lane8 + (laneg & 1) * 8;
        aByte[im] = (uint32_t)row * 128;
        aMask[im] = (uint32_t)(row & 7);
    }
    uint32_t bByte[2], bMask[2];
    #pragma unroll
    for (int p = 0; p < 2; p++) {
        int row = wn * 32 + p * 16 + lane8 + (laneg >> 1) * 8;
        bByte[p] = (uint32_t)row * 128;
        bMask[p] = (uint32_t)(row & 7);
    }
    uint32_t cA = (uint32_t)(laneg >> 1);
    uint32_t cB = (uint32_t)(laneg & 1);

    float acc[4][4][4];
    #pragma unroll
    for (int i = 0; i < 4; i++)
        #pragma unroll
        for (int j = 0; j < 4; j++)
            #pragma unroll
            for (int p = 0; p < 4; p++) acc[i][j][p] = 0.f;

    int nt = K / 64;
    auto issue = [&](int t) {
        if (t < nt) {
            int s = t % STG;
            int k0 = t * 64;
            uint32_t ab = sbA + s * STAGE_B;
            uint32_t wb = sbW + s * STAGE_B;
            #pragma unroll
            for (int l = 0; l < 4; l++) {
                int j = tid + l * 256;
                uint32_t row = (uint32_t)(j >> 3), q8 = (uint32_t)(j & 7);
                uint32_t sw = (q8 ^ (row & 7)) << 4;
                cp16(ab + row * 128 + sw, A + (size_t)(m0 + (int)row) * K + k0 + (int)q8 * 8);
                cp16(wb + row * 128 + sw, W + (size_t)(n0 + (int)row) * K + k0 + (int)q8 * 8);
            }
        }
        cp_commit();
    };

    issue(0);
    issue(1);
    for (int t = 0; t < nt; t++) {
        issue(t + 2);
        cp_wait<2>();
        __syncthreads();
        int s = t % STG;
        uint32_t aBase = sbA + s * STAGE_B;
        uint32_t wBase = sbW + s * STAGE_B;
        #pragma unroll
        for (int kk = 0; kk < 64; kk += 16) {
            uint32_t kc = (uint32_t)(kk >> 3);
            uint32_t af[4][4], bf[2][4];
            #pragma unroll
            for (int im = 0; im < 4; im++)
                ldsm4(af[im], aBase + aByte[im] + (((kc + cA) ^ aMask[im]) << 4));
            #pragma unroll
            for (int p = 0; p < 2; p++)
                ldsm4(bf[p], wBase + bByte[p] + (((kc + cB) ^ bMask[p]) << 4));
            #pragma unroll
            for (int im = 0; im < 4; im++)
                #pragma unroll
                for (int in = 0; in < 4; in++)
                    mma16816(acc[im][in], af[im], &bf[in >> 1][(in & 1) * 2]);
        }
        __syncthreads();
    }

    // epilogue
    float sums[4][2];
    if (GX2) {
        #pragma unroll
        for (int in = 0; in < 4; in++) { sums[in][0] = 0.f; sums[in][1] = 0.f; }
    }
    #pragma unroll
    for (int im = 0; im < 4; im++) {
        int r0 = m0 + wm * 64 + im * 16 + g;
        #pragma unroll
        for (int in = 0; in < 4; in++) {
            int c = n0 + wn * 32 + in * 8 + tg * 2;
            float b0 = bias[c], b1 = bias[c + 1];
            float v00 = acc[im][in][0] + b0, v01 = acc[im][in][1] + b1;
            float v10 = acc[im][in][2] + b0, v11 = acc[im][in][3] + b1;
            if (SILU) {
                v00 = __fdividef(v00, 1.f + __expf(-v00));
                v01 = __fdividef(v01, 1.f + __expf(-v01));
                v10 = __fdividef(v10, 1.f + __expf(-v10));
                v11 = __fdividef(v11, 1.f + __expf(-v11));
            }
            if (RES) {
                float s0 = scale[c], s1 = scale[c + 1];
                bf162 ra = *(const bf162*)&res[(size_t)r0 * N + c];
                bf162 rb = *(const bf162*)&res[(size_t)(r0 + 8) * N + c];
                v00 = __bfloat162float(ra.x) + v00 * s0;
                v01 = __bfloat162float(ra.y) + v01 * s1;
                v10 = __bfloat162float(rb.x) + v10 * s0;
                v11 = __bfloat162float(rb.y) + v11 * s1;
            }
            if (GX2) {
                sums[in][0] += v00 * v00 + v10 * v10;
                sums[in][1] += v01 * v01 + v11 * v11;
            }
            *(bf162*)&C[(size_t)r0 * N + c] = __floats2bfloat162_rn(v00, v01);
            *(bf162*)&C[(size_t)(r0 + 8) * N + c] = __floats2bfloat162_rn(v10, v11);
        }
    }
    if (GX2) {
        #pragma unroll
        for (int off = 4; off <= 16; off <<= 1) {
            #pragma unroll
            for (int in = 0; in < 4; in++) {
                sums[in][0] += __shfl_xor_sync(0xffffffff, sums[in][0], off);
                sums[in][1] += __shfl_xor_sync(0xffffffff, sums[in][1], off);
            }
        }
        if (lane < 4) {
            int b = m0 >> 12;
            #pragma unroll
            for (int in = 0; in < 4; in++) {
                int c = n0 + wn * 32 + in * 8 + tg * 2;
                atomicAdd(&gx2sq[b * D + c], sums[in][0]);
                atomicAdd(&gx2sq[b * D + c + 1], sums[in][1]);
            }
        }
    }
}

// per-token LayerNorm over D then elu+1; packed {g,b} float4 table; y: 0=q, 1=k
__global__ void __launch_bounds__(256) k_lnelu(bf16* __restrict__ X,
        const float* __restrict__ pgq, const float* __restrict__ pgk) {
    int warp = threadIdx.x >> 5, lane = threadIdx.x & 31;
    int t = blockIdx.x * 8 + warp;
    int seg = blockIdx.y;
    const float4* pg4 = (const float4*)(seg ? pgk : pgq);
    size_t base = (size_t)t * QS + seg * D;
    float2 v[6];
    float s = 0.f, s2 = 0.f;
    #pragma unroll
    for (int j = 0; j < 6; j++) {
        bf162 h = *(const bf162*)&X[base + j * 64 + lane * 2];
        v[j].x = __bfloat162float(h.x);
        v[j].y = __bfloat162float(h.y);
        s += v[j].x + v[j].y;
        s2 += v[j].x * v[j].x + v[j].y * v[j].y;
    }
    #pragma unroll
    for (int o = 16; o >= 1; o >>= 1) {
        s  += __shfl_xor_sync(0xffffffff, s, o);
        s2 += __shfl_xor_sync(0xffffffff, s2, o);
    }
    float mean = s / (float)D;
    float var = s2 / (float)D - mean * mean;
    float rstd = rsqrtf(var + 1e-5f);
    #pragma unroll
    for (int j = 0; j < 6; j++) {
        int d = j * 64 + lane * 2;
        float4 gb = pg4[d >> 1];          // {g[d], b[d], g[d+1], b[d+1]}
        float y0 = (v[j].x - mean) * rstd * gb.x + gb.y;
        float y1 = (v[j].y - mean) * rstd * gb.z + gb.w;
        y0 = (y0 > 0.f) ? (y0 + 1.f) : __expf(y0);
        y1 = (y1 > 0.f) ? (y1 + 1.f) : __expf(y1);
        *(bf162*)&X[base + d] = __floats2bfloat162_rn(y0, y1);
    }
}

// kv partial: kvp[sp][bh][d*48+e] = sum over 512 tokens of k[t,d]*v[t,e]
__global__ void __launch_bounds__(288) k_attn_kv(const bf16* __restrict__ qkv,
                                                 float* __restrict__ kvp,
                                                 float* __restrict__ ksp) {
    int bh = blockIdx.x, sp = blockIdx.y;
    int h = bh & (NH - 1), bc = bh >> 3;
    int tid = threadIdx.x;
    int d = tid % 48, eg = tid / 48;
    __shared__ float sk[16][48];
    __shared__ float sv[16][48];
    float acc[8];
    #pragma unroll
    for (int p = 0; p < 8; p++) acc[p] = 0.f;
    float ks = 0.f;

    for (int c = 0; c < (GS / KVSPLIT) / 16; c++) {
        int tt0 = bc * GS + sp * (GS / KVSPLIT) + c * 16;
        #pragma unroll
        for (int r = 0; r < 3; r++) {
            int ti = eg + r * 6;
            if (ti < 16) {
                size_t row = (size_t)(tt0 + ti) * QS + h * HD + d;
                sk[ti][d] = __bfloat162float(qkv[row + D]);
                sv[ti][d] = __bfloat162float(qkv[row + 2 * D]);
            }
        }
        __syncthreads();
        #pragma unroll
        for (int ti = 0; ti < 16; ti++) {
            float kval = sk[ti][d];
            const float* vp = &sv[ti][eg * 8];
            float4 v0 = *(const float4*)vp;
            float4 v1 = *(const float4*)(vp + 4);
            acc[0] += kval * v0.x; acc[1] += kval * v0.y;
            acc[2] += kval * v0.z; acc[3] += kval * v0.w;
            acc[4] += kval * v1.x; acc[5] += kval * v1.y;
            acc[6] += kval * v1.z; acc[7] += kval * v1.w;
            if (tid < 48) ks += kval;
        }
        __syncthreads();
    }
    float* out = kvp + ((size_t)(sp * (B*NC*NH) + bh)) * HD * HD + d * HD + eg * 8;
    *(float4*)out = make_float4(acc[0], acc[1], acc[2], acc[3]);
    *(float4*)(out + 4) = make_float4(acc[4], acc[5], acc[6], acc[7]);
    if (tid < 48) ksp[(sp * (B*NC*NH) + bh) * HD + tid] = ks;
}

// apply: out[t,h,e] = (q.kv[:,e]) / (q.ksum + 1e-8); 384 threads
__global__ void __launch_bounds__(384) k_attn_apply(const bf16* __restrict__ qkv,
                                                    const float* __restrict__ kvp,
                                                    const float* __restrict__ ksp,
                                                    bf16* __restrict__ out) {
    int bh = blockIdx.x, tile = blockIdx.y;
    int h = bh & (NH - 1), bc = bh >> 3;
    int tid = threadIdx.x;
    __shared__ float skv[48 * 48];
    __shared__ float sks[48];
    __shared__ float sq[64][49];

    const float* kv0 = kvp + (size_t)bh * HD * HD;
    const float* kv1 = kvp + (size_t)(B*NC*NH + bh) * HD * HD;
    for (int i = tid; i < HD * HD; i += 384) skv[i] = kv0[i] + kv1[i];
    if (tid < 48) sks[tid] = ksp[bh * HD + tid] + ksp[(B*NC*NH + bh) * HD + tid];

    int t0 = bc * GS + tile * 64;
    int dp = tid % 24, rowi = tid / 24;     // 24 pair-lanes x 16 rows
    #pragma unroll
    for (int r = 0; r < 4; r++) {
        int lt = rowi + r * 16;
        bf162 h2 = *(const bf162*)&qkv[(size_t)(t0 + lt) * QS + h * HD + dp * 2];
        sq[lt][dp * 2] = __bfloat162float(h2.x);
        sq[lt][dp * 2 + 1] = __bfloat162float(h2.y);
    }
    __syncthreads();

    int g = tid % 6, lt = tid / 6;
    float acc[8];
    #pragma unroll
    for (int p = 0; p < 8; p++) acc[p] = 0.f;
    float den = 0.f;
    #pragma unroll 8
    for (int dl = 0; dl < 48; dl++) {
        float qq = sq[lt][dl];
        const float* kp = &skv[dl * 48 + g * 8];
        float4 a = *(const float4*)kp;
        float4 b = *(const float4*)(kp + 4);
        acc[0] += qq * a.x; acc[1] += qq * a.y;
        acc[2] += qq * a.z; acc[3] += qq * a.w;
        acc[4] += qq * b.x; acc[5] += qq * b.y;
        acc[6] += qq * b.z; acc[7] += qq * b.w;
        den += qq * sks[dl];
    }
    float rden = __fdividef(1.f, den + 1e-8f);
    bf16* op = out + (size_t)(t0 + lt) * D + h * HD + g * 8;
    *(bf162*)(op + 0) = __floats2bfloat162_rn(acc[0] * rden, acc[1] * rden);
    *(bf162*)(op + 2) = __floats2bfloat162_rn(acc[2] * rden, acc[3] * rden);
    *(bf162*)(op + 4) = __floats2bfloat162_rn(acc[4] * rden, acc[5] * rden);
    *(bf162*)(op + 6) = __floats2bfloat162_rn(acc[6] * rden, acc[7] * rden);
}

// x2 = A2[b,d]*wi + C2[b,d]; 4 elems/thread
__global__ void k_x2(const bf16* __restrict__ wi, const float* __restrict__ A,
                     const float* __restrict__ C, bf16* __restrict__ x2) {
    size_t e = ((size_t)blockIdx.x * 256 + threadIdx.x) * 4;
    int t = (int)(e / D), d = (int)(e % D);
    int b = t >> 12;
    bf162 w01 = *(const bf162*)&wi[e];
    bf162 w23 = *(const bf162*)&wi[e + 2];
    const float* Ab = A + b * D + d;
    const float* Cb = C + b * D + d;
    float r0 = Ab[0] * __bfloat162float(w01.x) + Cb[0];
    float r1 = Ab[1] * __bfloat162float(w01.y) + Cb[1];
    float r2 = Ab[2] * __bfloat162float(w23.x) + Cb[2];
    float r3 = Ab[3] * __bfloat162float(w23.y) + Cb[3];
    bf162 o01 = __floats2bfloat162_rn(r0, r1);
    bf162 o23 = __floats2bfloat162_rn(r2, r3);
    uint2 u; u.x = *(uint32_t*)&o01; u.y = *(uint32_t*)&o23;
    *(uint2*)&x2[e] = u;
}

// out[b,d,pix] = image[b,d,pix] + wif[token(pix), d] * final_scalar[d]
__global__ void __launch_bounds__(256) k_final_t(
        const float* __restrict__ img, const bf16* __restrict__ wif,
        const int* __restrict__ invp, const float* __restrict__ fs,
        float* __restrict__ out) {
    __shared__ float tile[64][65];
    __shared__ int sinv[64];
    int p0 = blockIdx.x * 64, d0 = blockIdx.y * 64, b = blockIdx.z;
    int tid = threadIdx.x;
    if (tid < 64) sinv[tid] = invp[p0 + tid];
    __syncthreads();
    #pragma unroll
    for (int l = 0; l < 4; l++) {
        int j = tid + l * 256;
        int jp = j >> 4, i4 = (j & 15) * 4;
        int t = sinv[jp];
        const bf16* src = wif + ((size_t)(b * NP + t)) * D + d0 + i4;
        bf162 v01 = *(const bf162*)src;
        bf162 v23 = *(const bf162*)(src + 2);
        tile[i4 + 0][jp] = __bfloat162float(v01.x);
        tile[i4 + 1][jp] = __bfloat162float(v01.y);
        tile[i4 + 2][jp] = __bfloat162float(v23.x);
        tile[i4 + 3][jp] = __bfloat162float(v23.y);
    }
    __syncthreads();
    #pragma unroll
    for (int l = 0; l < 4; l++) {
        int j = tid + l * 256;
        int i = j >> 4, q = (j & 15) * 4;
        size_t o = ((size_t)(b * D + d0 + i)) * NP + p0 + q;
        float4 im4 = *(const float4*)(img + o);
        float f = fs[d0 + i];
        float4 r;
        r.x = im4.x + tile[i][q + 0] * f;
        r.y = im4.y + tile[i][q + 1] * f;
        r.z = im4.z + tile[i][q + 2] * f;
        r.w = im4.w + tile[i][q + 3] * f;
        *(float4*)(out + o) = r;
    }
}

// ---------------- driver ----------------------------------------------------
extern "C" void kernel_launch(void* const* d_in, const int* in_sizes, int n_in,
                              void* d_out, int out_size) {
    const float* image  = (const float*)d_in[0];
    const float* film   = (const float*)d_in[1];
    const int*   perm   = (const int*)d_in[2];
    const float* Wq = (const float*)d_in[3];  const float* bq = (const float*)d_in[4];
    const float* Wk = (const float*)d_in[5];  const float* bk = (const float*)d_in[6];
    const float* Wv = (const float*)d_in[7];  const float* bv = (const float*)d_in[8];
    const float* Wo = (const float*)d_in[9];  const float* bo = (const float*)d_in[10];
    const float* lnq_g = (const float*)d_in[11]; const float* lnq_b = (const float*)d_in[12];
    const float* lnk_g = (const float*)d_in[13]; const float* lnk_b = (const float*)d_in[14];
    const float* ada1_W = (const float*)d_in[15]; const float* ada1_b = (const float*)d_in[16];
    const float* grn1_g = (const float*)d_in[17]; const float* grn1_b = (const float*)d_in[18];
    const float* ada2_W = (const float*)d_in[19]; const float* ada2_b = (const float*)d_in[20];
    const float* grn2_g = (const float*)d_in[21]; const float* grn2_b = (const float*)d_in[22];
    const float* conv1_W = (const float*)d_in[23]; const float* conv1_b = (const float*)d_in[24];
    const float* conv2_W = (const float*)d_in[25]; const float* conv2_b = (const float*)d_in[26];
    const float* cs  = (const float*)d_in[27];
    const float* ffs = (const float*)d_in[28];
    const float* fs  = (const float*)d_in[29];
    float* out = (float*)d_out;

    float *p_gb1, *p_gb2, *p_gx, *p_A2, *p_C2, *p_gx2sq;
    int* p_invp;
    float *p_kv, *p_ks, *p_bqkv, *p_pgq, *p_pgk;
    bf16 *p_imtok16, *p_wi16, *p_wif16;
    bf16 *p_qkv16, *p_xg16, *p_att16, *p_x216, *p_h116;
    bf16 *p_wqkv16, *p_wo16, *p_c1w16, *p_c2w16;
    cudaGetSymbolAddress((void**)&p_gb1, g_gb1);
    cudaGetSymbolAddress((void**)&p_gb2, g_gb2);
    cudaGetSymbolAddress((void**)&p_gx, g_gx);
    cudaGetSymbolAddress((void**)&p_A2, g_A2);
    cudaGetSymbolAddress((void**)&p_C2, g_C2);
    cudaGetSymbolAddress((void**)&p_gx2sq, g_gx2sq);
    cudaGetSymbolAddress((void**)&p_invp, g_invp);
    cudaGetSymbolAddress((void**)&p_kv, g_kv);
    cudaGetSymbolAddress((void**)&p_ks, g_ks);
    cudaGetSymbolAddress((void**)&p_bqkv, g_bqkv);
    cudaGetSymbolAddress((void**)&p_pgq, g_pgq);
    cudaGetSymbolAddress((void**)&p_pgk, g_pgk);
    cudaGetSymbolAddress((void**)&p_imtok16, g_imtok16);
    cudaGetSymbolAddress((void**)&p_wi16, g_wi16);
    cudaGetSymbolAddress((void**)&p_wif16, g_wif16);
    cudaGetSymbolAddress((void**)&p_qkv16, g_qkv16);
    cudaGetSymbolAddress((void**)&p_xg16, g_xg16);
    cudaGetSymbolAddress((void**)&p_att16, g_att16);
    cudaGetSymbolAddress((void**)&p_x216, g_x216);
    cudaGetSymbolAddress((void**)&p_h116, g_h116);
    cudaGetSymbolAddress((void**)&p_wqkv16, g_wqkv16);
    cudaGetSymbolAddress((void**)&p_wo16, g_wo16);
    cudaGetSymbolAddress((void**)&p_c1w16, g_c1w16);
    cudaGetSymbolAddress((void**)&p_c2w16, g_c2w16);

    cudaFuncSetAttribute((const void*)gemm_mma<false,false,false>,
                         cudaFuncAttributeMaxDynamicSharedMemorySize, GEMM_SMEM);
    cudaFuncSetAttribute((const void*)gemm_mma<false,true,true>,
                         cudaFuncAttributeMaxDynamicSharedMemorySize, GEMM_SMEM);
    cudaFuncSetAttribute((const void*)gemm_mma<true,false,false>,
                         cudaFuncAttributeMaxDynamicSharedMemorySize, GEMM_SMEM);
    cudaFuncSetAttribute((const void*)gemm_mma<false,true,false>,
                         cudaFuncAttributeMaxDynamicSharedMemorySize, GEMM_SMEM);

    // launch 0: all prep + film + gx
    k_prep<<<PREP_BLOCKS + B * D, 256>>>(Wq, Wk, Wv, Wo, conv1_W, conv2_W,
        bq, bk, bv, perm, film, ada1_W, ada1_b, ada2_W, ada2_b,
        lnq_g, lnq_b, lnk_g, lnk_b, image,
        p_wqkv16, p_wo16, p_c1w16, p_c2w16,
        p_bqkv, p_gx2sq, p_invp, p_gb1, p_gb2, p_pgq, p_pgk, p_gx);
    // launch 1: gather with inline adaLN1 coefficients + local gmean
    k_gather_t<<<dim3(NP/64, D/64, B), 256>>>(image, p_invp, p_gx,
        grn1_g, grn1_b, p_gb1, p_imtok16, p_xg16);
    // launch 2: packed QKV GEMM
    gemm_mma<false,false,false><<<dim3(QS/128, T/128), 256, GEMM_SMEM>>>(
        p_xg16, p_wqkv16, p_bqkv, nullptr, nullptr, p_qkv16, nullptr, T, QS, D);

    k_lnelu<<<dim3(T/8, 2), 256>>>(p_qkv16, p_pgq, p_pgk);

    k_attn_kv<<<dim3(B * NC * NH, KVSPLIT), 288>>>(p_qkv16, p_kv, p_ks);
    k_attn_apply<<<dim3(B * NC * NH, 16), 384>>>(p_qkv16, p_kv, p_ks, p_att16);

    // wi = imtok + (attn@Wo^T + bo) * cs ; also gx2sq += wi^2
    gemm_mma<false,true,true><<<dim3(3, T/128), 256, GEMM_SMEM>>>(
        p_att16, p_wo16, bo, p_imtok16, cs, p_wi16, p_gx2sq, T, D, D);

    k_gmean_coef<<<B, 384>>>(p_gx2sq, grn2_g, grn2_b, p_gb2, p_A2, p_C2);
    k_x2<<<(int)(((size_t)T*D) / 1024), 256>>>(p_wi16, p_A2, p_C2, p_x216);

    // h1 = silu(x2 @ conv1^T + b1)
    gemm_mma<true,false,false><<<dim3(12, T/128), 256, GEMM_SMEM>>>(
        p_x216, p_c1w16, conv1_b, nullptr, nullptr, p_h116, nullptr, T, D4, D);
    // wif = wi + (h1 @ conv2^T + b2) * ffs
    gemm_mma<false,true,false><<<dim3(3, T/128), 256, GEMM_SMEM>>>(
        p_h116, p_c2w16, conv2_b, p_wi16, ffs, p_wif16, nullptr, T, D, D4);

    k_final_t<<<dim3(NP/64, D/64, B), 256>>>(image, p_wif16, p_invp, fs, out);
}

// round 16
// speedup vs baseline: 1.3474x; 1.0032x over previous
#include <cuda_runtime.h>
#include <cuda_bf16.h>
#include <math.h>
#include <stdint.h>

#define B   8
#define D   384
#define FD  256
#define NP  4096
#define NH  8
#define NC  4
#define HD  48
#define GS  1024
#define T   (B*NP)     /* 32768 tokens */
#define D4  1536
#define D2  768
#define QS  1152       /* packed qkv row stride */
#define KVSPLIT 2

typedef __nv_bfloat16 bf16;
typedef __nv_bfloat162 bf162;

// ---------------- scratch (device globals) ----------------------------------
static __device__ float g_gb1[B*D2];
static __device__ float g_gb2[B*D2];
static __device__ float g_gx[B*D];
static __device__ float g_A2[B*D];
static __device__ float g_C2[B*D];
static __device__ float g_gx2sq[B*D];
static __device__ int   g_invp[NP];
static __device__ float g_kv[KVSPLIT*B*NC*NH*HD*HD];
static __device__ float g_ks[KVSPLIT*B*NC*NH*HD];
static __device__ float g_bqkv[QS];
static __device__ float g_pgq[2*D];
static __device__ float g_pgk[2*D];
// bf16 activations
static __device__ bf16  g_imtok16[(size_t)T*D];
static __device__ bf16  g_wi16[(size_t)T*D];
static __device__ bf16  g_wif16[(size_t)T*D];
static __device__ bf16  g_qkv16[(size_t)T*QS];
static __device__ bf16  g_xg16[(size_t)T*D];
static __device__ bf16  g_att16[(size_t)T*D];
static __device__ bf16  g_x216[(size_t)T*D];
static __device__ bf16  g_h116[(size_t)T*D4];
// bf16 weights
static __device__ bf16  g_wqkv16[QS*D];
static __device__ bf16  g_wo16[D*D];
static __device__ bf16  g_c1w16[D4*D];
static __device__ bf16  g_c2w16[D*D4];

// ---------------- helpers ----------------------------------------------------
__device__ __forceinline__ uint32_t sptr(const void* p) {
    return (uint32_t)__cvta_generic_to_shared(p);
}
__device__ __forceinline__ void cp16(uint32_t s, const void* g) {
    asm volatile("cp.async.cg.shared.global [%0], [%1], 16;\n" :: "r"(s), "l"(g));
}
__device__ __forceinline__ void cp_commit() {
    asm volatile("cp.async.commit_group;\n");
}
template<int N>
__device__ __forceinline__ void cp_wait() {
    asm volatile("cp.async.wait_group %0;\n" :: "n"(N));
}
__device__ __forceinline__ void mma16816(float* c, const uint32_t* a, const uint32_t* b) {
    asm volatile(
        "mma.sync.aligned.m16n8k16.row.col.f32.bf16.bf16.f32 "
        "{%0,%1,%2,%3}, {%4,%5,%6,%7}, {%8,%9}, {%0,%1,%2,%3};\n"
        : "+f"(c[0]), "+f"(c[1]), "+f"(c[2]), "+f"(c[3])
        : "r"(a[0]), "r"(a[1]), "r"(a[2]), "r"(a[3]), "r"(b[0]), "r"(b[1]));
}
__device__ __forceinline__ void ldsm4(uint32_t* r, uint32_t a) {
    asm volatile("ldmatrix.sync.aligned.m8n8.x4.shared.b16 {%0,%1,%2,%3}, [%4];"
        : "=r"(r[0]), "=r"(r[1]), "=r"(r[2]), "=r"(r[3]) : "r"(a));
}

__device__ __forceinline__ float blockReduce384(float v, float* sdata) {
    int tid = threadIdx.x;
    sdata[tid] = v;
    if (tid < 128) sdata[384 + tid] = 0.f;
    __syncthreads();
    #pragma unroll
    for (int s = 256; s >= 1; s >>= 1) {
        if (tid < s) sdata[tid] += sdata[tid + s];
        __syncthreads();
    }
    float r = sdata[0];
    __syncthreads();
    return r;
}

// ---------------- launch 0: prep + film + per-(b,d) image L2 norm ------------
#define NWQKV (3*D*D)
#define NWO   (D*D)
#define NC1   (D4*D)
#define NC2   (D*D4)
#define NFILM (2*B*D2)
#define NPACK (2*D)
#define PREP_ELEMS (NWQKV + NWO + NC1 + NC2 + QS + B*D + NP + NPACK + NFILM)
#define PREP_BLOCKS ((PREP_ELEMS + 255) / 256)
__global__ void k_prep(const float* __restrict__ Wq, const float* __restrict__ Wk,
                       const float* __restrict__ Wv, const float* __restrict__ Wo,
                       const float* __restrict__ c1, const float* __restrict__ c2,
                       const float* __restrict__ bq, const float* __restrict__ bk,
                       const float* __restrict__ bv,
                       const int* __restrict__ perm,
                       const float* __restrict__ film,
                       const float* __restrict__ W1, const float* __restrict__ b1,
                       const float* __restrict__ W2, const float* __restrict__ b2,
                       const float* __restrict__ lnqg, const float* __restrict__ lnqb,
                       const float* __restrict__ lnkg, const float* __restrict__ lnkb,
                       const float* __restrict__ img,
                       bf16* __restrict__ wqkv, bf16* __restrict__ wo,
                       bf16* __restrict__ c1o, bf16* __restrict__ c2o,
                       float* __restrict__ bqkv, float* __restrict__ gx2sq,
                       int* __restrict__ invp,
                       float* __restrict__ gb1, float* __restrict__ gb2,
                       float* __restrict__ pgq, float* __restrict__ pgk,
                       float* __restrict__ gx) {
    __shared__ float sdata[256];
    if (blockIdx.x >= PREP_BLOCKS) {
        int bd = blockIdx.x - PREP_BLOCKS;
        const float* p = img + (size_t)bd * NP;
        float s = 0.f;
        for (int i = threadIdx.x; i < NP; i += 256) { float v = p[i]; s += v * v; }
        sdata[threadIdx.x] = s; __syncthreads();
        for (int st = 128; st >= 1; st >>= 1) {
            if (threadIdx.x < st) sdata[threadIdx.x] += sdata[threadIdx.x + st];
            __syncthreads();
        }
        if (threadIdx.x == 0) gx[bd] = sqrtf(sdata[0]);
        return;
    }
    int i = blockIdx.x * blockDim.x + threadIdx.x;
    if (i < NWQKV) {
        int seg = i / (D*D), r = i % (D*D);
        const float* W = (seg == 0) ? Wq : (seg == 1) ? Wk : Wv;
        wqkv[i] = __float2bfloat16(W[r]);
        return;
    }
    i -= NWQKV;
    if (i < NWO) { wo[i] = __float2bfloat16(Wo[i]); return; }
    i -= NWO;
    if (i < NC1) { c1o[i] = __float2bfloat16(c1[i]); return; }
    i -= NC1;
    if (i < NC2) { c2o[i] = __float2bfloat16(c2[i]); return; }
    i -= NC2;
    if (i < QS) {
        bqkv[i] = (i < D) ? bq[i] : (i < 2*D) ? bk[i - D] : bv[i - 2*D];
        return;
    }
    i -= QS;
    if (i < B*D) { gx2sq[i] = 0.f; return; }
    i -= B*D;
    if (i < NP) { invp[perm[i]] = i; return; }
    i -= NP;
    if (i < NPACK) {
        int tbl = i / D, d = i % D;
        if (tbl == 0) { pgq[2*d] = lnqg[d]; pgq[2*d+1] = lnqb[d]; }
        else          { pgk[2*d] = lnkg[d]; pgk[2*d+1] = lnkb[d]; }
        return;
    }
    i -= NPACK;
    if (i < NFILM) {
        int which = i / (B * D2);
        int r = i % (B * D2);
        int b = r / D2, j = r % D2;
        const float* W = which ? W2 : W1;
        const float* bb = which ? b2 : b1;
        const float* f = film + b * FD;
        const float* w = W + (size_t)j * FD;
        float s = 0.f;
        #pragma unroll 8
        for (int q = 0; q < FD; q++) s += f[q] * w[q];
        s += bb[j];
        if (which) gb2[r] = s; else gb1[r] = s;
    }
}

// gmean+coef for GRN2 (input gx2sq needs sqrt)
__global__ void k_gmean_coef(const float* __restrict__ gxsq,
                             const float* __restrict__ gg, const float* __restrict__ gb_,
                             const float* __restrict__ gbmat,
                             float* __restrict__ A, float* __restrict__ C) {
    __shared__ float sdata[512];
    int b = blockIdx.x, d = threadIdx.x;
    float gv = sqrtf(gxsq[b * D + d]);
    float s = blockReduce384(gv, sdata);
    float gm = s / (float)D;
    float nx = gv / (gm + 1e-6f);
    float gamma = gbmat[b * D2 + d];
    float beta  = gbmat[b * D2 + D + d];
    A[b * D + d] = ((1.f + gg[d]) * nx + 1.f) * (1.f + gamma);
    C[b * D + d] = gb_[d] * (1.f + gamma) + beta;
}

// ---------------- launch 1: transpose-gather w/ inline adaLN1 + local gmean --
__global__ void __launch_bounds__(256) k_gather_t(
        const float* __restrict__ img, const int* __restrict__ invp,
        const float* __restrict__ gx,
        const float* __restrict__ gg, const float* __restrict__ gb_,
        const float* __restrict__ gb1,
        bf16* __restrict__ imtok, bf16* __restrict__ xg) {
    __shared__ float tile[64][65];
    __shared__ float sA[64], sC[64];
    __shared__ float sred[256];
    __shared__ int sinv[64];
    int p0 = blockIdx.x * 64, d0 = blockIdx.y * 64, b = blockIdx.z;
    int tid = threadIdx.x;
    float s = 0.f;
    for (int t = tid; t < D; t += 256) s += gx[b * D + t];
    sred[tid] = s; __syncthreads();
    for (int st = 128; st >= 1; st >>= 1) {
        if (tid < st) sred[tid] += sred[tid + st];
        __syncthreads();
    }
    float gmv = sred[0] * (1.f / (float)D);

    if (tid < 64) sinv[tid] = invp[p0 + tid];
    else if (tid >= 64 && tid < 128) {
        int dl = tid - 64, d = d0 + dl;
        float nx = gx[b * D + d] / (gmv + 1e-6f);
        float gamma = gb1[b * D2 + d];
        float beta  = gb1[b * D2 + D + d];
        sA[dl] = ((1.f + gg[d]) * nx + 1.f) * (1.f + gamma);
        sC[dl] = gb_[d] * (1.f + gamma) + beta;
    }
    #pragma unroll
    for (int l = 0; l < 4; l++) {
        int j = tid + l * 256;
        int i = j >> 4, q = (j & 15) * 4;
        float4 v = *(const float4*)(img + ((size_t)(b * D + d0 + i)) * NP + p0 + q);
        tile[i][q + 0] = v.x; tile[i][q + 1] = v.y;
        tile[i][q + 2] = v.z; tile[i][q + 3] = v.w;
    }
    __syncthreads();
    #pragma unroll
    for (int l = 0; l < 4; l++) {
        int j = tid + l * 256;
        int jp = j >> 4, i4 = (j & 15) * 4;
        int t = sinv[jp];
        size_t o = ((size_t)(b * NP + t)) * D + d0 + i4;
        float vv[4], xv[4];
        #pragma unroll
        for (int r = 0; r < 4; r++) {
            vv[r] = tile[i4 + r][jp];
            xv[r] = sA[i4 + r] * vv[r] + sC[i4 + r];
        }
        *(bf162*)&imtok[o] = __floats2bfloat162_rn(vv[0], vv[1]);
        *(bf162*)&imtok[o + 2] = __floats2bfloat162_rn(vv[2], vv[3]);
        *(bf162*)&xg[o] = __floats2bfloat162_rn(xv[0], xv[1]);
        *(bf162*)&xg[o + 2] = __floats2bfloat162_rn(xv[2], xv[3]);
    }
}

// ---------------- bf16 tensor-core GEMM (BK=64, 3-stage, XOR swizzle) --------
// Epilogue staged through smem for coalesced res reads + output stores.
#define STG 3
#define STAGE_B 16384
#define GEMM_SMEM (STG * 2 * STAGE_B)
#define EPI_PITCH 132
template<bool SILU, bool RES, bool GX2>
__global__ void __launch_bounds__(256, 2) gemm_mma(
        const bf16* __restrict__ A, const bf16* __restrict__ W,
        const float* __restrict__ bias, const bf16* __restrict__ res,
        const float* __restrict__ scale, bf16* __restrict__ C,
        float* __restrict__ gx2sq, int M, int N, int K) {
    extern __shared__ char smem[];
    uint32_t sbA = sptr(smem);
    uint32_t sbW = sbA + STG * STAGE_B;
    int tid = threadIdx.x;
    int m0 = blockIdx.y * 128, n0 = blockIdx.x * 128;
    int lane = tid & 31, warp = tid >> 5;
    int g = lane >> 2, tg = lane & 3;
    int wm = warp >> 2, wn = warp & 3;
    int lane8 = lane & 7, laneg = lane >> 3;

    uint32_t aByte[4], aMask[4];
    #pragma unroll
    for (int im = 0; im < 4; im++) {
        int row = wm * 64 + im * 16 + lane8 + (laneg & 1) * 8;
        aByte[im] = (uint32_t)row * 128;
        aMask[im] = (uint32_t)(row & 7);
    }
    uint32_t bByte[2], bMask[2];
    #pragma unroll
    for (int p = 0; p < 2; p++) {
        int row = wn * 32 + p * 16 + lane8 + (laneg >> 1) * 8;
        bByte[p] = (uint32_t)row * 128;
        bMask[p] = (uint32_t)(row & 7);
    }
    uint32_t cA = (uint32_t)(laneg >> 1);
    uint32_t cB = (uint32_t)(laneg & 1);

    float acc[4][4][4];
    #pragma unroll
    for (int i = 0; i < 4; i++)
        #pragma unroll
        for (int j = 0; j < 4; j++)
            #pragma unroll
            for (int p = 0; p < 4; p++) acc[i][j][p] = 0.f;

    int nt = K / 64;
    auto issue = [&](int t) {
        if (t < nt) {
            int s = t % STG;
            int k0 = t * 64;
            uint32_t ab = sbA + s * STAGE_B;
            uint32_t wb = sbW + s * STAGE_B;
            #pragma unroll
            for (int l = 0; l < 4; l++) {
                int j = tid + l * 256;
                uint32_t row = (uint32_t)(j >> 3), q8 = (uint32_t)(j & 7);
                uint32_t sw = (q8 ^ (row & 7)) << 4;
                cp16(ab + row * 128 + sw, A + (size_t)(m0 + (int)row) * K + k0 + (int)q8 * 8);
                cp16(wb + row * 128 + sw, W + (size_t)(n0 + (int)row) * K + k0 + (int)q8 * 8);
            }
        }
        cp_commit();
    };

    issue(0);
    issue(1);
    for (int t = 0; t < nt; t++) {
        issue(t + 2);
        cp_wait<2>();
        __syncthreads();
        int s = t % STG;
        uint32_t aBase = sbA + s * STAGE_B;
        uint32_t wBase = sbW + s * STAGE_B;
        #pragma unroll
        for (int kk = 0; kk < 64; kk += 16) {
            uint32_t kc = (uint32_t)(kk >> 3);
            uint32_t af[4][4], bf[2][4];
            #pragma unroll
            for (int im = 0; im < 4; im++)
                ldsm4(af[im], aBase + aByte[im] + (((kc + cA) ^ aMask[im]) << 4));
            #pragma unroll
            for (int p = 0; p < 2; p++)
                ldsm4(bf[p], wBase + bByte[p] + (((kc + cB) ^ bMask[p]) << 4));
            #pragma unroll
            for (int im = 0; im < 4; im++)
                #pragma unroll
                for (int in = 0; in < 4; in++)
                    mma16816(acc[im][in], af[im], &bf[in >> 1][(in & 1) * 2]);
        }
        __syncthreads();
    }

    // ---- staged epilogue ----
    float* stage = (float*)smem;                     // [128][EPI_PITCH]
    float* colsum = (float*)(smem + 128 * EPI_PITCH * 4);
    // fragment phase: bias (+silu), write fp32 to stage
    #pragma unroll
    for (int im = 0; im < 4; im++) {
        int lr = wm * 64 + im * 16 + g;
        #pragma unroll
        for (int in = 0; in < 4; in++) {
            int lc = wn * 32 + in * 8 + tg * 2;
            float b0 = bias[n0 + lc], b1 = bias[n0 + lc + 1];
            float v00 = acc[im][in][0] + b0, v01 = acc[im][in][1] + b1;
            float v10 = acc[im][in][2] + b0, v11 = acc[im][in][3] + b1;
            if (SILU) {
                v00 = __fdividef(v00, 1.f + __expf(-v00));
                v01 = __fdividef(v01, 1.f + __expf(-v01));
                v10 = __fdividef(v10, 1.f + __expf(-v10));
                v11 = __fdividef(v11, 1.f + __expf(-v11));
            }
            stage[lr * EPI_PITCH + lc] = v00;
            stage[lr * EPI_PITCH + lc + 1] = v01;
            stage[(lr + 8) * EPI_PITCH + lc] = v10;
            stage[(lr + 8) * EPI_PITCH + lc + 1] = v11;
        }
    }
    if (GX2 && tid < 128) colsum[tid] = 0.f;
    __syncthreads();

    // store phase: coalesced res read + output store (16 thr per row)
    int cc = tid & 15, rbase = tid >> 4;
    int colg = cc * 8;
    float sc[8];
    if (RES) {
        #pragma unroll
        for (int i = 0; i < 8; i++) sc[i] = scale[n0 + colg + i];
    }
    float gacc[8];
    if (GX2) {
        #pragma unroll
        for (int i = 0; i < 8; i++) gacc[i] = 0.f;
    }
    #pragma unroll
    for (int j = 0; j < 8; j++) {
        int lr = rbase + j * 16;
        const float* sp = &stage[lr * EPI_PITCH + colg];
        float v[8];
        #pragma unroll
        for (int i = 0; i < 8; i++) v[i] = sp[i];
        if (RES) {
            const bf16* rp = res + (size_t)(m0 + lr) * N + n0 + colg;
            uint4 ru = *(const uint4*)rp;
            bf162 r0 = *(bf162*)&ru.x, r1 = *(bf162*)&ru.y;
            bf162 r2 = *(bf162*)&ru.z, r3 = *(bf162*)&ru.w;
            v[0] = __bfloat162float(r0.x) + v[0] * sc[0];
            v[1] = __bfloat162float(r0.y) + v[1] * sc[1];
            v[2] = __bfloat162float(r1.x) + v[2] * sc[2];
            v[3] = __bfloat162float(r1.y) + v[3] * sc[3];
            v[4] = __bfloat162float(r2.x) + v[4] * sc[4];
            v[5] = __bfloat162float(r2.y) + v[5] * sc[5];
            v[6] = __bfloat162float(r3.x) + v[6] * sc[6];
            v[7] = __bfloat162float(r3.y) + v[7] * sc[7];
        }
        if (GX2) {
            #pragma unroll
            for (int i = 0; i < 8; i++) gacc[i] += v[i] * v[i];
        }
        bf162 o0 = __floats2bfloat162_rn(v[0], v[1]);
        bf162 o1 = __floats2bfloat162_rn(v[2], v[3]);
        bf162 o2 = __floats2bfloat162_rn(v[4], v[5]);
        bf162 o3 = __floats2bfloat162_rn(v[6], v[7]);
        uint4 ou;
        ou.x = *(uint32_t*)&o0; ou.y = *(uint32_t*)&o1;
        ou.z = *(uint32_t*)&o2; ou.w = *(uint32_t*)&o3;
        *(uint4*)(C + (size_t)(m0 + lr) * N + n0 + colg) = ou;
    }
    if (GX2) {
        #pragma unroll
        for (int i = 0; i < 8; i++) atomicAdd(&colsum[colg + i], gacc[i]);
        __syncthreads();
        if (tid < 128) {
            int b = m0 >> 12;
            atomicAdd(&gx2sq[b * D + n0 + tid], colsum[tid]);
        }
    }
}

// per-token LayerNorm over D then elu+1; packed {g,b} float4 table; y: 0=q, 1=k
__global__ void __launch_bounds__(256) k_lnelu(bf16* __restrict__ X,
        const float* __restrict__ pgq, const float* __restrict__ pgk) {
    int warp = threadIdx.x >> 5, lane = threadIdx.x & 31;
    int t = blockIdx.x * 8 + warp;
    int seg = blockIdx.y;
    const float4* pg4 = (const float4*)(seg ? pgk : pgq);
    size_t base = (size_t)t * QS + seg * D;
    float2 v[6];
    float s = 0.f, s2 = 0.f;
    #pragma unroll
    for (int j = 0; j < 6; j++) {
        bf162 h = *(const bf162*)&X[base + j * 64 + lane * 2];
        v[j].x = __bfloat162float(h.x);
        v[j].y = __bfloat162float(h.y);
        s += v[j].x + v[j].y;
        s2 += v[j].x * v[j].x + v[j].y * v[j].y;
    }
    #pragma unroll
    for (int o = 16; o >= 1; o >>= 1) {
        s  += __shfl_xor_sync(0xffffffff, s, o);
        s2 += __shfl_xor_sync(0xffffffff, s2, o);
    }
    float mean = s / (float)D;
    float var = s2 / (float)D - mean * mean;
    float rstd = rsqrtf(var + 1e-5f);
    #pragma unroll
    for (int j = 0; j < 6; j++) {
        int d = j * 64 + lane * 2;
        float4 gb = pg4[d >> 1];
        float y0 = (v[j].x - mean) * rstd * gb.x + gb.y;
        float y1 = (v[j].y - mean) * rstd * gb.z + gb.w;
        y0 = (y0 > 0.f) ? (y0 + 1.f) : __expf(y0);
        y1 = (y1 > 0.f) ? (y1 + 1.f) : __expf(y1);
        *(bf162*)&X[base + d] = __floats2bfloat162_rn(y0, y1);
    }
}

// kv partial: kvp[sp][bh][d*48+e] = sum over 512 tokens of k[t,d]*v[t,e]
__global__ void __launch_bounds__(288) k_attn_kv(const bf16* __restrict__ qkv,
                                                 float* __restrict__ kvp,
                                                 float* __restrict__ ksp) {
    int bh = blockIdx.x, sp = blockIdx.y;
    int h = bh & (NH - 1), bc = bh >> 3;
    int tid = threadIdx.x;
    int d = tid % 48, eg = tid / 48;
    __shared__ float sk[16][48];
    __shared__ float sv[16][48];
    float acc[8];
    #pragma unroll
    for (int p = 0; p < 8; p++) acc[p] = 0.f;
    float ks = 0.f;

    for (int c = 0; c < (GS / KVSPLIT) / 16; c++) {
        int tt0 = bc * GS + sp * (GS / KVSPLIT) + c * 16;
        #pragma unroll
        for (int r = 0; r < 3; r++) {
            int ti = eg + r * 6;
            if (ti < 16) {
                size_t row = (size_t)(tt0 + ti) * QS + h * HD + d;
                sk[ti][d] = __bfloat162float(qkv[row + D]);
                sv[ti][d] = __bfloat162float(qkv[row + 2 * D]);
            }
        }
        __syncthreads();
        #pragma unroll
        for (int ti = 0; ti < 16; ti++) {
            float kval = sk[ti][d];
            const float* vp = &sv[ti][eg * 8];
            float4 v0 = *(const float4*)vp;
            float4 v1 = *(const float4*)(vp + 4);
            acc[0] += kval * v0.x; acc[1] += kval * v0.y;
            acc[2] += kval * v0.z; acc[3] += kval * v0.w;
            acc[4] += kval * v1.x; acc[5] += kval * v1.y;
            acc[6] += kval * v1.z; acc[7] += kval * v1.w;
            if (tid < 48) ks += kval;
        }
        __syncthreads();
    }
    float* out = kvp + ((size_t)(sp * (B*NC*NH) + bh)) * HD * HD + d * HD + eg * 8;
    *(float4*)out = make_float4(acc[0], acc[1], acc[2], acc[3]);
    *(float4*)(out + 4) = make_float4(acc[4], acc[5], acc[6], acc[7]);
    if (tid < 48) ksp[(sp * (B*NC*NH) + bh) * HD + tid] = ks;
}

// apply: out[t,h,e] = (q.kv[:,e]) / (q.ksum + 1e-8); 384 threads
__global__ void __launch_bounds__(384) k_attn_apply(const bf16* __restrict__ qkv,
                                                    const float* __restrict__ kvp,
                                                    const float* __restrict__ ksp,
                                                    bf16* __restrict__ out) {
    int bh = blockIdx.x, tile = blockIdx.y;
    int h = bh & (NH - 1), bc = bh >> 3;
    int tid = threadIdx.x;
    __shared__ float skv[48 * 48];
    __shared__ float sks[48];
    __shared__ float sq[64][49];

    const float* kv0 = kvp + (size_t)bh * HD * HD;
    const float* kv1 = kvp + (size_t)(B*NC*NH + bh) * HD * HD;
    for (int i = tid; i < HD * HD; i += 384) skv[i] = kv0[i] + kv1[i];
    if (tid < 48) sks[tid] = ksp[bh * HD + tid] + ksp[(B*NC*NH + bh) * HD + tid];

    int t0 = bc * GS + tile * 64;
    int dp = tid % 24, rowi = tid / 24;
    #pragma unroll
    for (int r = 0; r < 4; r++) {
        int lt = rowi + r * 16;
        bf162 h2 = *(const bf162*)&qkv[(size_t)(t0 + lt) * QS + h * HD + dp * 2];
        sq[lt][dp * 2] = __bfloat162float(h2.x);
        sq[lt][dp * 2 + 1] = __bfloat162float(h2.y);
    }
    __syncthreads();

    int g = tid % 6, lt = tid / 6;
    float acc[8];
    #pragma unroll
    for (int p = 0; p < 8; p++) acc[p] = 0.f;
    float den = 0.f;
    #pragma unroll 8
    for (int dl = 0; dl < 48; dl++) {
        float qq = sq[lt][dl];
        const float* kp = &skv[dl * 48 + g * 8];
        float4 a = *(const float4*)kp;
        float4 b = *(const float4*)(kp + 4);
        acc[0] += qq * a.x; acc[1] += qq * a.y;
        acc[2] += qq * a.z; acc[3] += qq * a.w;
        acc[4] += qq * b.x; acc[5] += qq * b.y;
        acc[6] += qq * b.z; acc[7] += qq * b.w;
        den += qq * sks[dl];
    }
    float rden = __fdividef(1.f, den + 1e-8f);
    bf16* op = out + (size_t)(t0 + lt) * D + h * HD + g * 8;
    *(bf162*)(op + 0) = __floats2bfloat162_rn(acc[0] * rden, acc[1] * rden);
    *(bf162*)(op + 2) = __floats2bfloat162_rn(acc[2] * rden, acc[3] * rden);
    *(bf162*)(op + 4) = __floats2bfloat162_rn(acc[4] * rden, acc[5] * rden);
    *(bf162*)(op + 6) = __floats2bfloat162_rn(acc[6] * rden, acc[7] * rden);
}

// x2 = A2[b,d]*wi + C2[b,d]; 4 elems/thread
__global__ void k_x2(const bf16* __restrict__ wi, const float* __restrict__ A,
                     const float* __restrict__ C, bf16* __restrict__ x2) {
    size_t e = ((size_t)blockIdx.x * 256 + threadIdx.x) * 4;
    int t = (int)(e / D), d = (int)(e % D);
    int b = t >> 12;
    bf162 w01 = *(const bf162*)&wi[e];
    bf162 w23 = *(const bf162*)&wi[e + 2];
    const float* Ab = A + b * D + d;
    const float* Cb = C + b * D + d;
    float r0 = Ab[0] * __bfloat162float(w01.x) + Cb[0];
    float r1 = Ab[1] * __bfloat162float(w01.y) + Cb[1];
    float r2 = Ab[2] * __bfloat162float(w23.x) + Cb[2];
    float r3 = Ab[3] * __bfloat162float(w23.y) + Cb[3];
    bf162 o01 = __floats2bfloat162_rn(r0, r1);
    bf162 o23 = __floats2bfloat162_rn(r2, r3);
    uint2 u; u.x = *(uint32_t*)&o01; u.y = *(uint32_t*)&o23;
    *(uint2*)&x2[e] = u;
}

// out[b,d,pix] = image[b,d,pix] + wif[token(pix), d] * final_scalar[d]
__global__ void __launch_bounds__(256) k_final_t(
        const float* __restrict__ img, const bf16* __restrict__ wif,
        const int* __restrict__ invp, const float* __restrict__ fs,
        float* __restrict__ out) {
    __shared__ float tile[64][65];
    __shared__ int sinv[64];
    int p0 = blockIdx.x * 64, d0 = blockIdx.y * 64, b = blockIdx.z;
    int tid = threadIdx.x;
    if (tid < 64) sinv[tid] = invp[p0 + tid];
    __syncthreads();
    #pragma unroll
    for (int l = 0; l < 4; l++) {
        int j = tid + l * 256;
        int jp = j >> 4, i4 = (j & 15) * 4;
        int t = sinv[jp];
        const bf16* src = wif + ((size_t)(b * NP + t)) * D + d0 + i4;
        bf162 v01 = *(const bf162*)src;
        bf162 v23 = *(const bf162*)(src + 2);
        tile[i4 + 0][jp] = __bfloat162float(v01.x);
        tile[i4 + 1][jp] = __bfloat162float(v01.y);
        tile[i4 + 2][jp] = __bfloat162float(v23.x);
        tile[i4 + 3][jp] = __bfloat162float(v23.y);
    }
    __syncthreads();
    #pragma unroll
    for (int l = 0; l < 4; l++) {
        int j = tid + l * 256;
        int i = j >> 4, q = (j & 15) * 4;
        size_t o = ((size_t)(b * D + d0 + i)) * NP + p0 + q;
        float4 im4 = *(const float4*)(img + o);
        float f = fs[d0 + i];
        float4 r;
        r.x = im4.x + tile[i][q + 0] * f;
        r.y = im4.y + tile[i][q + 1] * f;
        r.z = im4.z + tile[i][q + 2] * f;
        r.w = im4.w + tile[i][q + 3] * f;
        *(float4*)(out + o) = r;
    }
}

// ---------------- driver ----------------------------------------------------
extern "C" void kernel_launch(void* const* d_in, const int* in_sizes, int n_in,
                              void* d_out, int out_size) {
    const float* image  = (const float*)d_in[0];
    const float* film   = (const float*)d_in[1];
    const int*   perm   = (const int*)d_in[2];
    const float* Wq = (const float*)d_in[3];  const float* bq = (const float*)d_in[4];
    const float* Wk = (const float*)d_in[5];  const float* bk = (const float*)d_in[6];
    const float* Wv = (const float*)d_in[7];  const float* bv = (const float*)d_in[8];
    const float* Wo = (const float*)d_in[9];  const float* bo = (const float*)d_in[10];
    const float* lnq_g = (const float*)d_in[11]; const float* lnq_b = (const float*)d_in[12];
    const float* lnk_g = (const float*)d_in[13]; const float* lnk_b = (const float*)d_in[14];
    const float* ada1_W = (const float*)d_in[15]; const float* ada1_b = (const float*)d_in[16];
    const float* grn1_g = (const float*)d_in[17]; const float* grn1_b = (const float*)d_in[18];
    const float* ada2_W = (const float*)d_in[19]; const float* ada2_b = (const float*)d_in[20];
    const float* grn2_g = (const float*)d_in[21]; const float* grn2_b = (const float*)d_in[22];
    const float* conv1_W = (const float*)d_in[23]; const float* conv1_b = (const float*)d_in[24];
    const float* conv2_W = (const float*)d_in[25]; const float* conv2_b = (const float*)d_in[26];
    const float* cs  = (const float*)d_in[27];
    const float* ffs = (const float*)d_in[28];
    const float* fs  = (const float*)d_in[29];
    float* out = (float*)d_out;

    float *p_gb1, *p_gb2, *p_gx, *p_A2, *p_C2, *p_gx2sq;
    int* p_invp;
    float *p_kv, *p_ks, *p_bqkv, *p_pgq, *p_pgk;
    bf16 *p_imtok16, *p_wi16, *p_wif16;
    bf16 *p_qkv16, *p_xg16, *p_att16, *p_x216, *p_h116;
    bf16 *p_wqkv16, *p_wo16, *p_c1w16, *p_c2w16;
    cudaGetSymbolAddress((void**)&p_gb1, g_gb1);
    cudaGetSymbolAddress((void**)&p_gb2, g_gb2);
    cudaGetSymbolAddress((void**)&p_gx, g_gx);
    cudaGetSymbolAddress((void**)&p_A2, g_A2);
    cudaGetSymbolAddress((void**)&p_C2, g_C2);
    cudaGetSymbolAddress((void**)&p_gx2sq, g_gx2sq);
    cudaGetSymbolAddress((void**)&p_invp, g_invp);
    cudaGetSymbolAddress((void**)&p_kv, g_kv);
    cudaGetSymbolAddress((void**)&p_ks, g_ks);
    cudaGetSymbolAddress((void**)&p_bqkv, g_bqkv);
    cudaGetSymbolAddress((void**)&p_pgq, g_pgq);
    cudaGetSymbolAddress((void**)&p_pgk, g_pgk);
    cudaGetSymbolAddress((void**)&p_imtok16, g_imtok16);
    cudaGetSymbolAddress((void**)&p_wi16, g_wi16);
    cudaGetSymbolAddress((void**)&p_wif16, g_wif16);
    cudaGetSymbolAddress((void**)&p_qkv16, g_qkv16);
    cudaGetSymbolAddress((void**)&p_xg16, g_xg16);
    cudaGetSymbolAddress((void**)&p_att16, g_att16);
    cudaGetSymbolAddress((void**)&p_x216, g_x216);
    cudaGetSymbolAddress((void**)&p_h116, g_h116);
    cudaGetSymbolAddress((void**)&p_wqkv16, g_wqkv16);
    cudaGetSymbolAddress((void**)&p_wo16, g_wo16);
    cudaGetSymbolAddress((void**)&p_c1w16, g_c1w16);
    cudaGetSymbolAddress((void**)&p_c2w16, g_c2w16);

    cudaFuncSetAttribute((const void*)gemm_mma<false,false,false>,
                         cudaFuncAttributeMaxDynamicSharedMemorySize, GEMM_SMEM);
    cudaFuncSetAttribute((const void*)gemm_mma<false,true,true>,
                         cudaFuncAttributeMaxDynamicSharedMemorySize, GEMM_SMEM);
    cudaFuncSetAttribute((const void*)gemm_mma<true,false,false>,
                         cudaFuncAttributeMaxDynamicSharedMemorySize, GEMM_SMEM);
    cudaFuncSetAttribute((const void*)gemm_mma<false,true,false>,
                         cudaFuncAttributeMaxDynamicSharedMemorySize, GEMM_SMEM);

    // launch 0: all prep + film + gx
    k_prep<<<PREP_BLOCKS + B * D, 256>>>(Wq, Wk, Wv, Wo, conv1_W, conv2_W,
        bq, bk, bv, perm, film, ada1_W, ada1_b, ada2_W, ada2_b,
        lnq_g, lnq_b, lnk_g, lnk_b, image,
        p_wqkv16, p_wo16, p_c1w16, p_c2w16,
        p_bqkv, p_gx2sq, p_invp, p_gb1, p_gb2, p_pgq, p_pgk, p_gx);
    // launch 1: gather with inline adaLN1 coefficients + local gmean
    k_gather_t<<<dim3(NP/64, D/64, B), 256>>>(image, p_invp, p_gx,
        grn1_g, grn1_b, p_gb1, p_imtok16, p_xg16);
    // launch 2: packed QKV GEMM
    gemm_mma<false,false,false><<<dim3(QS/128, T/128), 256, GEMM_SMEM>>>(
        p_xg16, p_wqkv16, p_bqkv, nullptr, nullptr, p_qkv16, nullptr, T, QS, D);

    k_lnelu<<<dim3(T/8, 2), 256>>>(p_qkv16, p_pgq, p_pgk);

    k_attn_kv<<<dim3(B * NC * NH, KVSPLIT), 288>>>(p_qkv16, p_kv, p_ks);
    k_attn_apply<<<dim3(B * NC * NH, 16), 384>>>(p_qkv16, p_kv, p_ks, p_att16);

    // wi = imtok + (attn@Wo^T + bo) * cs ; also gx2sq += wi^2
    gemm_mma<false,true,true><<<dim3(3, T/128), 256, GEMM_SMEM>>>(
        p_att16, p_wo16, bo, p_imtok16, cs, p_wi16, p_gx2sq, T, D, D);

    k_gmean_coef<<<B, 384>>>(p_gx2sq, grn2_g, grn2_b, p_gb2, p_A2, p_C2);
    k_x2<<<(int)(((size_t)T*D) / 1024), 256>>>(p_wi16, p_A2, p_C2, p_x216);

    // h1 = silu(x2 @ conv1^T + b1)
    gemm_mma<true,false,false><<<dim3(12, T/128), 256, GEMM_SMEM>>>(
        p_x216, p_c1w16, conv1_b, nullptr, nullptr, p_h116, nullptr, T, D4, D);
    // wif = wi + (h1 @ conv2^T + b2) * ffs
    gemm_mma<false,true,false><<<dim3(3, T/128), 256, GEMM_SMEM>>>(
        p_h116, p_c2w16, conv2_b, p_wi16, ffs, p_wif16, nullptr, T, D, D4);

    k_final_t<<<dim3(NP/64, D/64, B), 256>>>(image, p_wif16, p_invp, fs, out);
}

// round 17
// speedup vs baseline: 1.3504x; 1.0022x over previous
#include <cuda_runtime.h>
#include <cuda_bf16.h>
#include <math.h>
#include <stdint.h>

#define B   8
#define D   384
#define FD  256
#define NP  4096
#define NH  8
#define NC  4
#define HD  48
#define GS  1024
#define T   (B*NP)     /* 32768 tokens */
#define D4  1536
#define D2  768
#define QS  1152       /* packed qkv row stride */
#define KVSPLIT 2

typedef __nv_bfloat16 bf16;
typedef __nv_bfloat162 bf162;

// ---------------- scratch (device globals) ----------------------------------
static __device__ float g_gb1[B*D2];
static __device__ float g_gb2[B*D2];
static __device__ float g_gx[B*D];
static __device__ float g_A2[B*D];
static __device__ float g_C2[B*D];
static __device__ float g_gx2sq[B*D];
static __device__ int   g_invp[NP];
static __device__ float g_kv[KVSPLIT*B*NC*NH*HD*HD];
static __device__ float g_ks[KVSPLIT*B*NC*NH*HD];
static __device__ float g_bqkv[QS];
static __device__ float g_pgq[2*D];
static __device__ float g_pgk[2*D];
static __device__ float g_lnstat[4*T];    // per (seg,tok): {sum,sumsq} -> {rstd,-mean*rstd}
// bf16 activations
static __device__ bf16  g_imtok16[(size_t)T*D];
static __device__ bf16  g_wi16[(size_t)T*D];
static __device__ bf16  g_wif16[(size_t)T*D];
static __device__ bf16  g_qkv16[(size_t)T*QS];
static __device__ bf16  g_xg16[(size_t)T*D];
static __device__ bf16  g_att16[(size_t)T*D];
static __device__ bf16  g_x216[(size_t)T*D];
static __device__ bf16  g_h116[(size_t)T*D4];
// bf16 weights
static __device__ bf16  g_wqkv16[QS*D];
static __device__ bf16  g_wo16[D*D];
static __device__ bf16  g_c1w16[D4*D];
static __device__ bf16  g_c2w16[D*D4];

// ---------------- helpers ----------------------------------------------------
__device__ __forceinline__ uint32_t sptr(const void* p) {
    return (uint32_t)__cvta_generic_to_shared(p);
}
__device__ __forceinline__ void cp16(uint32_t s, const void* g) {
    asm volatile("cp.async.cg.shared.global [%0], [%1], 16;\n" :: "r"(s), "l"(g));
}
__device__ __forceinline__ void cp_commit() {
    asm volatile("cp.async.commit_group;\n");
}
template<int N>
__device__ __forceinline__ void cp_wait() {
    asm volatile("cp.async.wait_group %0;\n" :: "n"(N));
}
__device__ __forceinline__ void mma16816(float* c, const uint32_t* a, const uint32_t* b) {
    asm volatile(
        "mma.sync.aligned.m16n8k16.row.col.f32.bf16.bf16.f32 "
        "{%0,%1,%2,%3}, {%4,%5,%6,%7}, {%8,%9}, {%0,%1,%2,%3};\n"
        : "+f"(c[0]), "+f"(c[1]), "+f"(c[2]), "+f"(c[3])
        : "r"(a[0]), "r"(a[1]), "r"(a[2]), "r"(a[3]), "r"(b[0]), "r"(b[1]));
}
__device__ __forceinline__ void ldsm4(uint32_t* r, uint32_t a) {
    asm volatile("ldmatrix.sync.aligned.m8n8.x4.shared.b16 {%0,%1,%2,%3}, [%4];"
        : "=r"(r[0]), "=r"(r[1]), "=r"(r[2]), "=r"(r[3]) : "r"(a));
}

__device__ __forceinline__ float blockReduce384(float v, float* sdata) {
    int tid = threadIdx.x;
    sdata[tid] = v;
    if (tid < 128) sdata[384 + tid] = 0.f;
    __syncthreads();
    #pragma unroll
    for (int s = 256; s >= 1; s >>= 1) {
        if (tid < s) sdata[tid] += sdata[tid + s];
        __syncthreads();
    }
    float r = sdata[0];
    __syncthreads();
    return r;
}

// ---------------- launch 0: prep + film + per-(b,d) image L2 norm ------------
#define NWQKV (3*D*D)
#define NWO   (D*D)
#define NC1   (D4*D)
#define NC2   (D*D4)
#define NFILM (2*B*D2)
#define NPACK (2*D)
#define NSTAT (4*T)
#define PREP_ELEMS (NWQKV + NWO + NC1 + NC2 + QS + B*D + NP + NPACK + NSTAT + NFILM)
#define PREP_BLOCKS ((PREP_ELEMS + 255) / 256)
__global__ void k_prep(const float* __restrict__ Wq, const float* __restrict__ Wk,
                       const float* __restrict__ Wv, const float* __restrict__ Wo,
                       const float* __restrict__ c1, const float* __restrict__ c2,
                       const float* __restrict__ bq, const float* __restrict__ bk,
                       const float* __restrict__ bv,
                       const int* __restrict__ perm,
                       const float* __restrict__ film,
                       const float* __restrict__ W1, const float* __restrict__ b1,
                       const float* __restrict__ W2, const float* __restrict__ b2,
                       const float* __restrict__ lnqg, const float* __restrict__ lnqb,
                       const float* __restrict__ lnkg, const float* __restrict__ lnkb,
                       const float* __restrict__ img,
                       bf16* __restrict__ wqkv, bf16* __restrict__ wo,
                       bf16* __restrict__ c1o, bf16* __restrict__ c2o,
                       float* __restrict__ bqkv, float* __restrict__ gx2sq,
                       int* __restrict__ invp,
                       float* __restrict__ gb1, float* __restrict__ gb2,
                       float* __restrict__ pgq, float* __restrict__ pgk,
                       float* __restrict__ lnstat,
                       float* __restrict__ gx) {
    __shared__ float sdata[256];
    if (blockIdx.x >= PREP_BLOCKS) {
        int bd = blockIdx.x - PREP_BLOCKS;
        const float* p = img + (size_t)bd * NP;
        float s = 0.f;
        for (int i = threadIdx.x; i < NP; i += 256) { float v = p[i]; s += v * v; }
        sdata[threadIdx.x] = s; __syncthreads();
        for (int st = 128; st >= 1; st >>= 1) {
            if (threadIdx.x < st) sdata[threadIdx.x] += sdata[threadIdx.x + st];
            __syncthreads();
        }
        if (threadIdx.x == 0) gx[bd] = sqrtf(sdata[0]);
        return;
    }
    int i = blockIdx.x * blockDim.x + threadIdx.x;
    if (i < NWQKV) {
        int seg = i / (D*D), r = i % (D*D);
        const float* W = (seg == 0) ? Wq : (seg == 1) ? Wk : Wv;
        wqkv[i] = __float2bfloat16(W[r]);
        return;
    }
    i -= NWQKV;
    if (i < NWO) { wo[i] = __float2bfloat16(Wo[i]); return; }
    i -= NWO;
    if (i < NC1) { c1o[i] = __float2bfloat16(c1[i]); return; }
    i -= NC1;
    if (i < NC2) { c2o[i] = __float2bfloat16(c2[i]); return; }
    i -= NC2;
    if (i < QS) {
        bqkv[i] = (i < D) ? bq[i] : (i < 2*D) ? bk[i - D] : bv[i - 2*D];
        return;
    }
    i -= QS;
    if (i < B*D) { gx2sq[i] = 0.f; return; }
    i -= B*D;
    if (i < NP) { invp[perm[i]] = i; return; }
    i -= NP;
    if (i < NPACK) {
        int tbl = i / D, d = i % D;
        if (tbl == 0) { pgq[2*d] = lnqg[d]; pgq[2*d+1] = lnqb[d]; }
        else          { pgk[2*d] = lnkg[d]; pgk[2*d+1] = lnkb[d]; }
        return;
    }
    i -= NPACK;
    if (i < NSTAT) { lnstat[i] = 0.f; return; }
    i -= NSTAT;
    if (i < NFILM) {
        int which = i / (B * D2);
        int r = i % (B * D2);
        int b = r / D2, j = r % D2;
        const float* W = which ? W2 : W1;
        const float* bb = which ? b2 : b1;
        const float* f = film + b * FD;
        const float* w = W + (size_t)j * FD;
        float s = 0.f;
        #pragma unroll 8
        for (int q = 0; q < FD; q++) s += f[q] * w[q];
        s += bb[j];
        if (which) gb2[r] = s; else gb1[r] = s;
    }
}

// gmean+coef for GRN2 (input gx2sq needs sqrt)
__global__ void k_gmean_coef(const float* __restrict__ gxsq,
                             const float* __restrict__ gg, const float* __restrict__ gb_,
                             const float* __restrict__ gbmat,
                             float* __restrict__ A, float* __restrict__ C) {
    __shared__ float sdata[512];
    int b = blockIdx.x, d = threadIdx.x;
    float gv = sqrtf(gxsq[b * D + d]);
    float s = blockReduce384(gv, sdata);
    float gm = s / (float)D;
    float nx = gv / (gm + 1e-6f);
    float gamma = gbmat[b * D2 + d];
    float beta  = gbmat[b * D2 + D + d];
    A[b * D + d] = ((1.f + gg[d]) * nx + 1.f) * (1.f + gamma);
    C[b * D + d] = gb_[d] * (1.f + gamma) + beta;
}

// convert accumulated {sum, sumsq} -> {rstd, -mean*rstd} per (seg, token)
__global__ void k_stat(float* __restrict__ s) {
    int i = blockIdx.x * 256 + threadIdx.x;   // < 2T
    float s0 = s[2*i], s1 = s[2*i + 1];
    float mean = s0 * (1.f / (float)D);
    float var = s1 * (1.f / (float)D) - mean * mean;
    float rstd = rsqrtf(var + 1e-5f);
    s[2*i] = rstd;
    s[2*i + 1] = -mean * rstd;
}

// ---------------- launch 1: transpose-gather w/ inline adaLN1 + local gmean --
__global__ void __launch_bounds__(256) k_gather_t(
        const float* __restrict__ img, const int* __restrict__ invp,
        const float* __restrict__ gx,
        const float* __restrict__ gg, const float* __restrict__ gb_,
        const float* __restrict__ gb1,
        bf16* __restrict__ imtok, bf16* __restrict__ xg) {
    __shared__ float tile[64][65];
    __shared__ float sA[64], sC[64];
    __shared__ float sred[256];
    __shared__ int sinv[64];
    int p0 = blockIdx.x * 64, d0 = blockIdx.y * 64, b = blockIdx.z;
    int tid = threadIdx.x;
    float s = 0.f;
    for (int t = tid; t < D; t += 256) s += gx[b * D + t];
    sred[tid] = s; __syncthreads();
    for (int st = 128; st >= 1; st >>= 1) {
        if (tid < st) sred[tid] += sred[tid + st];
        __syncthreads();
    }
    float gmv = sred[0] * (1.f / (float)D);

    if (tid < 64) sinv[tid] = invp[p0 + tid];
    else if (tid >= 64 && tid < 128) {
        int dl = tid - 64, d = d0 + dl;
        float nx = gx[b * D + d] / (gmv + 1e-6f);
        float gamma = gb1[b * D2 + d];
        float beta  = gb1[b * D2 + D + d];
        sA[dl] = ((1.f + gg[d]) * nx + 1.f) * (1.f + gamma);
        sC[dl] = gb_[d] * (1.f + gamma) + beta;
    }
    #pragma unroll
    for (int l = 0; l < 4; l++) {
        int j = tid + l * 256;
        int i = j >> 4, q = (j & 15) * 4;
        float4 v = *(const float4*)(img + ((size_t)(b * D + d0 + i)) * NP + p0 + q);
        tile[i][q + 0] = v.x; tile[i][q + 1] = v.y;
        tile[i][q + 2] = v.z; tile[i][q + 3] = v.w;
    }
    __syncthreads();
    #pragma unroll
    for (int l = 0; l < 4; l++) {
        int j = tid + l * 256;
        int jp = j >> 4, i4 = (j & 15) * 4;
        int t = sinv[jp];
        size_t o = ((size_t)(b * NP + t)) * D + d0 + i4;
        float vv[4], xv[4];
        #pragma unroll
        for (int r = 0; r < 4; r++) {
            vv[r] = tile[i4 + r][jp];
            xv[r] = sA[i4 + r] * vv[r] + sC[i4 + r];
        }
        *(bf162*)&imtok[o] = __floats2bfloat162_rn(vv[0], vv[1]);
        *(bf162*)&imtok[o + 2] = __floats2bfloat162_rn(vv[2], vv[3]);
        *(bf162*)&xg[o] = __floats2bfloat162_rn(xv[0], xv[1]);
        *(bf162*)&xg[o + 2] = __floats2bfloat162_rn(xv[2], xv[3]);
    }
}

// ---------------- bf16 tensor-core GEMM (BK=64, 3-stage, XOR swizzle) --------
// Staged epilogue; optional per-token LN stat accumulation (QSTAT, q/k segs).
#define STG 3
#define STAGE_B 16384
#define GEMM_SMEM (STG * 2 * STAGE_B)
#define EPI_PITCH 132
template<bool SILU, bool RES, bool GX2, bool QSTAT>
__global__ void __launch_bounds__(256, 2) gemm_mma(
        const bf16* __restrict__ A, const bf16* __restrict__ W,
        const float* __restrict__ bias, const bf16* __restrict__ res,
        const float* __restrict__ scale, bf16* __restrict__ C,
        float* __restrict__ gx2sq, float* __restrict__ lnraw,
        int M, int N, int K) {
    extern __shared__ char smem[];
    uint32_t sbA = sptr(smem);
    uint32_t sbW = sbA + STG * STAGE_B;
    int tid = threadIdx.x;
    int m0 = blockIdx.y * 128, n0 = blockIdx.x * 128;
    int lane = tid & 31, warp = tid >> 5;
    int g = lane >> 2, tg = lane & 3;
    int wm = warp >> 2, wn = warp & 3;
    int lane8 = lane & 7, laneg = lane >> 3;

    uint32_t aByte[4], aMask[4];
    #pragma unroll
    for (int im = 0; im < 4; im++) {
        int row = wm * 64 + im * 16 + lane8 + (laneg & 1) * 8;
        aByte[im] = (uint32_t)row * 128;
        aMask[im] = (uint32_t)(row & 7);
    }
    uint32_t bByte[2], bMask[2];
    #pragma unroll
    for (int p = 0; p < 2; p++) {
        int row = wn * 32 + p * 16 + lane8 + (laneg >> 1) * 8;
        bByte[p] = (uint32_t)row * 128;
        bMask[p] = (uint32_t)(row & 7);
    }
    uint32_t cA = (uint32_t)(laneg >> 1);
    uint32_t cB = (uint32_t)(laneg & 1);

    float acc[4][4][4];
    #pragma unroll
    for (int i = 0; i < 4; i++)
        #pragma unroll
        for (int j = 0; j < 4; j++)
            #pragma unroll
            for (int p = 0; p < 4; p++) acc[i][j][p] = 0.f;

    int nt = K / 64;
    auto issue = [&](int t) {
        if (t < nt) {
            int s = t % STG;
            int k0 = t * 64;
            uint32_t ab = sbA + s * STAGE_B;
            uint32_t wb = sbW + s * STAGE_B;
            #pragma unroll
            for (int l = 0; l < 4; l++) {
                int j = tid + l * 256;
                uint32_t row = (uint32_t)(j >> 3), q8 = (uint32_t)(j & 7);
                uint32_t sw = (q8 ^ (row & 7)) << 4;
                cp16(ab + row * 128 + sw, A + (size_t)(m0 + (int)row) * K + k0 + (int)q8 * 8);
                cp16(wb + row * 128 + sw, W + (size_t)(n0 + (int)row) * K + k0 + (int)q8 * 8);
            }
        }
        cp_commit();
    };

    issue(0);
    issue(1);
    for (int t = 0; t < nt; t++) {
        issue(t + 2);
        cp_wait<2>();
        __syncthreads();
        int s = t % STG;
        uint32_t aBase = sbA + s * STAGE_B;
        uint32_t wBase = sbW + s * STAGE_B;
        #pragma unroll
        for (int kk = 0; kk < 64; kk += 16) {
            uint32_t kc = (uint32_t)(kk >> 3);
            uint32_t af[4][4], bf[2][4];
            #pragma unroll
            for (int im = 0; im < 4; im++)
                ldsm4(af[im], aBase + aByte[im] + (((kc + cA) ^ aMask[im]) << 4));
            #pragma unroll
            for (int p = 0; p < 2; p++)
                ldsm4(bf[p], wBase + bByte[p] + (((kc + cB) ^ bMask[p]) << 4));
            #pragma unroll
            for (int im = 0; im < 4; im++)
                #pragma unroll
                for (int in = 0; in < 4; in++)
                    mma16816(acc[im][in], af[im], &bf[in >> 1][(in & 1) * 2]);
        }
        __syncthreads();
    }

    // ---- staged epilogue ----
    float* stage = (float*)smem;                     // [128][EPI_PITCH]
    float* colsum = (float*)(smem + 128 * EPI_PITCH * 4);
    float* rsum = colsum + 128;                      // [128][16]
    float* rsq  = rsum + 128 * 16;                   // [128][16]
    #pragma unroll
    for (int im = 0; im < 4; im++) {
        int lr = wm * 64 + im * 16 + g;
        #pragma unroll
        for (int in = 0; in < 4; in++) {
            int lc = wn * 32 + in * 8 + tg * 2;
            float b0 = bias[n0 + lc], b1 = bias[n0 + lc + 1];
            float v00 = acc[im][in][0] + b0, v01 = acc[im][in][1] + b1;
            float v10 = acc[im][in][2] + b0, v11 = acc[im][in][3] + b1;
            if (SILU) {
                v00 = __fdividef(v00, 1.f + __expf(-v00));
                v01 = __fdividef(v01, 1.f + __expf(-v01));
                v10 = __fdividef(v10, 1.f + __expf(-v10));
                v11 = __fdividef(v11, 1.f + __expf(-v11));
            }
            stage[lr * EPI_PITCH + lc] = v00;
            stage[lr * EPI_PITCH + lc + 1] = v01;
            stage[(lr + 8) * EPI_PITCH + lc] = v10;
            stage[(lr + 8) * EPI_PITCH + lc + 1] = v11;
        }
    }
    if (GX2 && tid < 128) colsum[tid] = 0.f;
    __syncthreads();

    bool dostat = QSTAT && (n0 < 2 * D);
    int cc = tid & 15, rbase = tid >> 4;
    int colg = cc * 8;
    float sc[8];
    if (RES) {
        #pragma unroll
        for (int i = 0; i < 8; i++) sc[i] = scale[n0 + colg + i];
    }
    float gacc[8];
    if (GX2) {
        #pragma unroll
        for (int i = 0; i < 8; i++) gacc[i] = 0.f;
    }
    #pragma unroll
    for (int j = 0; j < 8; j++) {
        int lr = rbase + j * 16;
        const float* sp = &stage[lr * EPI_PITCH + colg];
        float v[8];
        #pragma unroll
        for (int i = 0; i < 8; i++) v[i] = sp[i];
        if (RES) {
            const bf16* rp = res + (size_t)(m0 + lr) * N + n0 + colg;
            uint4 ru = *(const uint4*)rp;
            bf162 r0 = *(bf162*)&ru.x, r1 = *(bf162*)&ru.y;
            bf162 r2 = *(bf162*)&ru.z, r3 = *(bf162*)&ru.w;
            v[0] = __bfloat162float(r0.x) + v[0] * sc[0];
            v[1] = __bfloat162float(r0.y) + v[1] * sc[1];
            v[2] = __bfloat162float(r1.x) + v[2] * sc[2];
            v[3] = __bfloat162float(r1.y) + v[3] * sc[3];
            v[4] = __bfloat162float(r2.x) + v[4] * sc[4];
            v[5] = __bfloat162float(r2.y) + v[5] * sc[5];
            v[6] = __bfloat162float(r3.x) + v[6] * sc[6];
            v[7] = __bfloat162float(r3.y) + v[7] * sc[7];
        }
        if (GX2) {
            #pragma unroll
            for (int i = 0; i < 8; i++) gacc[i] += v[i] * v[i];
        }
        if (dostat) {
            float ps = 0.f, pq = 0.f;
            #pragma unroll
            for (int i = 0; i < 8; i++) { ps += v[i]; pq += v[i] * v[i]; }
            rsum[lr * 16 + cc] = ps;
            rsq[lr * 16 + cc] = pq;
        }
        bf162 o0 = __floats2bfloat162_rn(v[0], v[1]);
        bf162 o1 = __floats2bfloat162_rn(v[2], v[3]);
        bf162 o2 = __floats2bfloat162_rn(v[4], v[5]);
        bf162 o3 = __floats2bfloat162_rn(v[6], v[7]);
        uint4 ou;
        ou.x = *(uint32_t*)&o0; ou.y = *(uint32_t*)&o1;
        ou.z = *(uint32_t*)&o2; ou.w = *(uint32_t*)&o3;
        *(uint4*)(C + (size_t)(m0 + lr) * N + n0 + colg) = ou;
    }
    if (dostat) {
        __syncthreads();
        if (tid < 128) {
            int seg = n0 / D;
            float s = 0.f, q = 0.f;
            #pragma unroll
            for (int i = 0; i < 16; i++) { s += rsum[tid * 16 + i]; q += rsq[tid * 16 + i]; }
            atomicAdd(&lnraw[(size_t)(seg * T + m0 + tid) * 2], s);
            atomicAdd(&lnraw[(size_t)(seg * T + m0 + tid) * 2 + 1], q);
        }
    }
    if (GX2) {
        #pragma unroll
        for (int i = 0; i < 8; i++) atomicAdd(&colsum[colg + i], gacc[i]);
        __syncthreads();
        if (tid < 128) {
            int b = m0 >> 12;
            atomicAdd(&gx2sq[b * D + n0 + tid], colsum[tid]);
        }
    }
}

// kv partial: LN+elu applied to k inline; kvp[sp][bh][d*48+e] = sum k'v
__global__ void __launch_bounds__(288) k_attn_kv(const bf16* __restrict__ qkv,
                                                 const float* __restrict__ lnstat,
                                                 const float* __restrict__ pgk,
                                                 float* __restrict__ kvp,
                                                 float* __restrict__ ksp) {
    int bh = blockIdx.x, sp = blockIdx.y;
    int h = bh & (NH - 1), bc = bh >> 3;
    int tid = threadIdx.x;
    int d = tid % 48, eg = tid / 48;
    __shared__ float sk[16][48];
    __shared__ float sv[16][48];
    __shared__ float sgk[48], sbk[48];
    if (tid < 48) {
        sgk[tid] = pgk[2 * (h * HD + tid)];
        sbk[tid] = pgk[2 * (h * HD + tid) + 1];
    }
    float acc[8];
    #pragma unroll
    for (int p = 0; p < 8; p++) acc[p] = 0.f;
    float ks = 0.f;
    __syncthreads();

    for (int c = 0; c < (GS / KVSPLIT) / 16; c++) {
        int tt0 = bc * GS + sp * (GS / KVSPLIT) + c * 16;
        #pragma unroll
        for (int r = 0; r < 3; r++) {
            int ti = eg + r * 6;
            if (ti < 16) {
                size_t row = (size_t)(tt0 + ti) * QS + h * HD + d;
                float kraw = __bfloat162float(qkv[row + D]);
                float2 st = *(const float2*)&lnstat[(size_t)(T + tt0 + ti) * 2];
                float y = fmaf(kraw, st.x, st.y) * sgk[d] + sbk[d];
                sk[ti][d] = (y > 0.f) ? (y + 1.f) : __expf(y);
                sv[ti][d] = __bfloat162float(qkv[row + 2 * D]);
            }
        }
        __syncthreads();
        #pragma unroll
        for (int ti = 0; ti < 16; ti++) {
            float kval = sk[ti][d];
            const float* vp = &sv[ti][eg * 8];
            float4 v0 = *(const float4*)vp;
            float4 v1 = *(const float4*)(vp + 4);
            acc[0] += kval * v0.x; acc[1] += kval * v0.y;
            acc[2] += kval * v0.z; acc[3] += kval * v0.w;
            acc[4] += kval * v1.x; acc[5] += kval * v1.y;
            acc[6] += kval * v1.z; acc[7] += kval * v1.w;
            if (tid < 48) ks += kval;
        }
        __syncthreads();
    }
    float* out = kvp + ((size_t)(sp * (B*NC*NH) + bh)) * HD * HD + d * HD + eg * 8;
    *(float4*)out = make_float4(acc[0], acc[1], acc[2], acc[3]);
    *(float4*)(out + 4) = make_float4(acc[4], acc[5], acc[6], acc[7]);
    if (tid < 48) ksp[(sp * (B*NC*NH) + bh) * HD + tid] = ks;
}

// apply: LN+elu applied to q inline; out = (q'.kv) / (q'.ksum + 1e-8)
__global__ void __launch_bounds__(384) k_attn_apply(const bf16* __restrict__ qkv,
                                                    const float* __restrict__ lnstat,
                                                    const float* __restrict__ pgq,
                                                    const float* __restrict__ kvp,
                                                    const float* __restrict__ ksp,
                                                    bf16* __restrict__ out) {
    int bh = blockIdx.x, tile = blockIdx.y;
    int h = bh & (NH - 1), bc = bh >> 3;
    int tid = threadIdx.x;
    __shared__ float skv[48 * 48];
    __shared__ float sks[48];
    __shared__ float sq[64][49];

    const float* kv0 = kvp + (size_t)bh * HD * HD;
    const float* kv1 = kvp + (size_t)(B*NC*NH + bh) * HD * HD;
    for (int i = tid; i < HD * HD; i += 384) skv[i] = kv0[i] + kv1[i];
    if (tid < 48) sks[tid] = ksp[bh * HD + tid] + ksp[(B*NC*NH + bh) * HD + tid];

    int t0 = bc * GS + tile * 64;
    int dp = tid % 24, rowi = tid / 24;
    float4 gb = *(const float4*)&pgq[2 * (h * HD + dp * 2)];
    #pragma unroll
    for (int r = 0; r < 4; r++) {
        int lt = rowi + r * 16;
        float2 st = *(const float2*)&lnstat[(size_t)(t0 + lt) * 2];
        bf162 h2 = *(const bf162*)&qkv[(size_t)(t0 + lt) * QS + h * HD + dp * 2];
        float y0 = fmaf(__bfloat162float(h2.x), st.x, st.y) * gb.x + gb.y;
        float y1 = fmaf(__bfloat162float(h2.y), st.x, st.y) * gb.z + gb.w;
        sq[lt][dp * 2] = (y0 > 0.f) ? (y0 + 1.f) : __expf(y0);
        sq[lt][dp * 2 + 1] = (y1 > 0.f) ? (y1 + 1.f) : __expf(y1);
    }
    __syncthreads();

    int g = tid % 6, lt = tid / 6;
    float acc[8];
    #pragma unroll
    for (int p = 0; p < 8; p++) acc[p] = 0.f;
    float den = 0.f;
    #pragma unroll 8
    for (int dl = 0; dl < 48; dl++) {
        float qq = sq[lt][dl];
        const float* kp = &skv[dl * 48 + g * 8];
        float4 a = *(const float4*)kp;
        float4 b = *(const float4*)(kp + 4);
        acc[0] += qq * a.x; acc[1] += qq * a.y;
        acc[2] += qq * a.z; acc[3] += qq * a.w;
        acc[4] += qq * b.x; acc[5] += qq * b.y;
        acc[6] += qq * b.z; acc[7] += qq * b.w;
        den += qq * sks[dl];
    }
    float rden = __fdividef(1.f, den + 1e-8f);
    bf16* op = out + (size_t)(t0 + lt) * D + h * HD + g * 8;
    *(bf162*)(op + 0) = __floats2bfloat162_rn(acc[0] * rden, acc[1] * rden);
    *(bf162*)(op + 2) = __floats2bfloat162_rn(acc[2] * rden, acc[3] * rden);
    *(bf162*)(op + 4) = __floats2bfloat162_rn(acc[4] * rden, acc[5] * rden);
    *(bf162*)(op + 6) = __floats2bfloat162_rn(acc[6] * rden, acc[7] * rden);
}

// x2 = A2[b,d]*wi + C2[b,d]; 4 elems/thread
__global__ void k_x2(const bf16* __restrict__ wi, const float* __restrict__ A,
                     const float* __restrict__ C, bf16* __restrict__ x2) {
    size_t e = ((size_t)blockIdx.x * 256 + threadIdx.x) * 4;
    int t = (int)(e / D), d = (int)(e % D);
    int b = t >> 12;
    bf162 w01 = *(const bf162*)&wi[e];
    bf162 w23 = *(const bf162*)&wi[e + 2];
    const float* Ab = A + b * D + d;
    const float* Cb = C + b * D + d;
    float r0 = Ab[0] * __bfloat162float(w01.x) + Cb[0];
    float r1 = Ab[1] * __bfloat162float(w01.y) + Cb[1];
    float r2 = Ab[2] * __bfloat162float(w23.x) + Cb[2];
    float r3 = Ab[3] * __bfloat162float(w23.y) + Cb[3];
    bf162 o01 = __floats2bfloat162_rn(r0, r1);
    bf162 o23 = __floats2bfloat162_rn(r2, r3);
    uint2 u; u.x = *(uint32_t*)&o01; u.y = *(uint32_t*)&o23;
    *(uint2*)&x2[e] = u;
}

// out[b,d,pix] = image[b,d,pix] + wif[token(pix), d] * final_scalar[d]
__global__ void __launch_bounds__(256) k_final_t(
        const float* __restrict__ img, const bf16* __restrict__ wif,
        const int* __restrict__ invp, const float* __restrict__ fs,
        float* __restrict__ out) {
    __shared__ float tile[64][65];
    __shared__ int sinv[64];
    int p0 = blockIdx.x * 64, d0 = blockIdx.y * 64, b = blockIdx.z;
    int tid = threadIdx.x;
    if (tid < 64) sinv[tid] = invp[p0 + tid];
    __syncthreads();
    #pragma unroll
    for (int l = 0; l < 4; l++) {
        int j = tid + l * 256;
        int jp = j >> 4, i4 = (j & 15) * 4;
        int t = sinv[jp];
        const bf16* src = wif + ((size_t)(b * NP + t)) * D + d0 + i4;
        bf162 v01 = *(const bf162*)src;
        bf162 v23 = *(const bf162*)(src + 2);
        tile[i4 + 0][jp] = __bfloat162float(v01.x);
        tile[i4 + 1][jp] = __bfloat162float(v01.y);
        tile[i4 + 2][jp] = __bfloat162float(v23.x);
        tile[i4 + 3][jp] = __bfloat162float(v23.y);
    }
    __syncthreads();
    #pragma unroll
    for (int l = 0; l < 4; l++) {
        int j = tid + l * 256;
        int i = j >> 4, q = (j & 15) * 4;
        size_t o = ((size_t)(b * D + d0 + i)) * NP + p0 + q;
        float4 im4 = *(const float4*)(img + o);
        float f = fs[d0 + i];
        float4 r;
        r.x = im4.x + tile[i][q + 0] * f;
        r.y = im4.y + tile[i][q + 1] * f;
        r.z = im4.z + tile[i][q + 2] * f;
        r.w = im4.w + tile[i][q + 3] * f;
        *(float4*)(out + o) = r;
    }
}

// ---------------- driver ----------------------------------------------------
extern "C" void kernel_launch(void* const* d_in, const int* in_sizes, int n_in,
                              void* d_out, int out_size) {
    const float* image  = (const float*)d_in[0];
    const float* film   = (const float*)d_in[1];
    const int*   perm   = (const int*)d_in[2];
    const float* Wq = (const float*)d_in[3];  const float* bq = (const float*)d_in[4];
    const float* Wk = (const float*)d_in[5];  const float* bk = (const float*)d_in[6];
    const float* Wv = (const float*)d_in[7];  const float* bv = (const float*)d_in[8];
    const float* Wo = (const float*)d_in[9];  const float* bo = (const float*)d_in[10];
    const float* lnq_g = (const float*)d_in[11]; const float* lnq_b = (const float*)d_in[12];
    const float* lnk_g = (const float*)d_in[13]; const float* lnk_b = (const float*)d_in[14];
    const float* ada1_W = (const float*)d_in[15]; const float* ada1_b = (const float*)d_in[16];
    const float* grn1_g = (const float*)d_in[17]; const float* grn1_b = (const float*)d_in[18];
    const float* ada2_W = (const float*)d_in[19]; const float* ada2_b = (const float*)d_in[20];
    const float* grn2_g = (const float*)d_in[21]; const float* grn2_b = (const float*)d_in[22];
    const float* conv1_W = (const float*)d_in[23]; const float* conv1_b = (const float*)d_in[24];
    const float* conv2_W = (const float*)d_in[25]; const float* conv2_b = (const float*)d_in[26];
    const float* cs  = (const float*)d_in[27];
    const float* ffs = (const float*)d_in[28];
    const float* fs  = (const float*)d_in[29];
    float* out = (float*)d_out;

    float *p_gb1, *p_gb2, *p_gx, *p_A2, *p_C2, *p_gx2sq;
    int* p_invp;
    float *p_kv, *p_ks, *p_bqkv, *p_pgq, *p_pgk, *p_lnstat;
    bf16 *p_imtok16, *p_wi16, *p_wif16;
    bf16 *p_qkv16, *p_xg16, *p_att16, *p_x216, *p_h116;
    bf16 *p_wqkv16, *p_wo16, *p_c1w16, *p_c2w16;
    cudaGetSymbolAddress((void**)&p_gb1, g_gb1);
    cudaGetSymbolAddress((void**)&p_gb2, g_gb2);
    cudaGetSymbolAddress((void**)&p_gx, g_gx);
    cudaGetSymbolAddress((void**)&p_A2, g_A2);
    cudaGetSymbolAddress((void**)&p_C2, g_C2);
    cudaGetSymbolAddress((void**)&p_gx2sq, g_gx2sq);
    cudaGetSymbolAddress((void**)&p_invp, g_invp);
    cudaGetSymbolAddress((void**)&p_kv, g_kv);
    cudaGetSymbolAddress((void**)&p_ks, g_ks);
    cudaGetSymbolAddress((void**)&p_bqkv, g_bqkv);
    cudaGetSymbolAddress((void**)&p_pgq, g_pgq);
    cudaGetSymbolAddress((void**)&p_pgk, g_pgk);
    cudaGetSymbolAddress((void**)&p_lnstat, g_lnstat);
    cudaGetSymbolAddress((void**)&p_imtok16, g_imtok16);
    cudaGetSymbolAddress((void**)&p_wi16, g_wi16);
    cudaGetSymbolAddress((void**)&p_wif16, g_wif16);
    cudaGetSymbolAddress((void**)&p_qkv16, g_qkv16);
    cudaGetSymbolAddress((void**)&p_xg16, g_xg16);
    cudaGetSymbolAddress((void**)&p_att16, g_att16);
    cudaGetSymbolAddress((void**)&p_x216, g_x216);
    cudaGetSymbolAddress((void**)&p_h116, g_h116);
    cudaGetSymbolAddress((void**)&p_wqkv16, g_wqkv16);
    cudaGetSymbolAddress((void**)&p_wo16, g_wo16);
    cudaGetSymbolAddress((void**)&p_c1w16, g_c1w16);
    cudaGetSymbolAddress((void**)&p_c2w16, g_c2w16);

    cudaFuncSetAttribute((const void*)gemm_mma<false,false,false,true>,
                         cudaFuncAttributeMaxDynamicSharedMemorySize, GEMM_SMEM);
    cudaFuncSetAttribute((const void*)gemm_mma<false,true,true,false>,
                         cudaFuncAttributeMaxDynamicSharedMemorySize, GEMM_SMEM);
    cudaFuncSetAttribute((const void*)gemm_mma<true,false,false,false>,
                         cudaFuncAttributeMaxDynamicSharedMemorySize, GEMM_SMEM);
    cudaFuncSetAttribute((const void*)gemm_mma<false,true,false,false>,
                         cudaFuncAttributeMaxDynamicSharedMemorySize, GEMM_SMEM);

    // launch 0: all prep + film + gx (+ lnstat zero)
    k_prep<<<PREP_BLOCKS + B * D, 256>>>(Wq, Wk, Wv, Wo, conv1_W, conv2_W,
        bq, bk, bv, perm, film, ada1_W, ada1_b, ada2_W, ada2_b,
        lnq_g, lnq_b, lnk_g, lnk_b, image,
        p_wqkv16, p_wo16, p_c1w16, p_c2w16,
        p_bqkv, p_gx2sq, p_invp, p_gb1, p_gb2, p_pgq, p_pgk, p_lnstat, p_gx);
    // launch 1: gather with inline adaLN1 coefficients + local gmean
    k_gather_t<<<dim3(NP/64, D/64, B), 256>>>(image, p_invp, p_gx,
        grn1_g, grn1_b, p_gb1, p_imtok16, p_xg16);
    // launch 2: packed QKV GEMM, accumulates LN stats for q/k segments
    gemm_mma<false,false,false,true><<<dim3(QS/128, T/128), 256, GEMM_SMEM>>>(
        p_xg16, p_wqkv16, p_bqkv, nullptr, nullptr, p_qkv16, nullptr, p_lnstat, T, QS, D);

    // convert stats
    k_stat<<<2 * T / 256, 256>>>(p_lnstat);

    k_attn_kv<<<dim3(B * NC * NH, KVSPLIT), 288>>>(p_qkv16, p_lnstat, p_pgk, p_kv, p_ks);
    k_attn_apply<<<dim3(B * NC * NH, 16), 384>>>(p_qkv16, p_lnstat, p_pgq, p_kv, p_ks, p_att16);

    // wi = imtok + (attn@Wo^T + bo) * cs ; also gx2sq += wi^2
    gemm_mma<false,true,true,false><<<dim3(3, T/128), 256, GEMM_SMEM>>>(
        p_att16, p_wo16, bo, p_imtok16, cs, p_wi16, p_gx2sq, nullptr, T, D, D);

    k_gmean_coef<<<B, 384>>>(p_gx2sq, grn2_g, grn2_b, p_gb2, p_A2, p_C2);
    k_x2<<<(int)(((size_t)T*D) / 1024), 256>>>(p_wi16, p_A2, p_C2, p_x216);

    // h1 = silu(x2 @ conv1^T + b1)
    gemm_mma<true,false,false,false><<<dim3(12, T/128), 256, GEMM_SMEM>>>(
        p_x216, p_c1w16, conv1_b, nullptr, nullptr, p_h116, nullptr, nullptr, T, D4, D);
    // wif = wi + (h1 @ conv2^T + b2) * ffs
    gemm_mma<false,true,false,false><<<dim3(3, T/128), 256, GEMM_SMEM>>>(
        p_h116, p_c2w16, conv2_b, p_wi16, ffs, p_wif16, nullptr, nullptr, T, D, D4);

    k_final_t<<<dim3(NP/64, D/64, B), 256>>>(image, p_wif16, p_invp, fs, out);
}